// round 7
// baseline (speedup 1.0000x reference)
#include <cuda_runtime.h>
#include <math.h>

// ---------------- dimensions ----------------
#define NB 8          // batch*groups
#define S  66
#define S2 4356       // 66*66
#define S3 287496     // 66^3
#define HH 33
#define H2 1089       // 33*33
#define H3 35937      // 33^3
#define D3 262144     // 64^3

// output packing offsets (x, helmholtz, vel, vel_phi, vel_vort)
#define OFF_X     0
#define OFF_HELM  16777216
#define OFF_VEL   25977088
#define OFF_VPHI  32268544
#define OFF_VVORT 38560000

#define WC1_PACK 7776          // 18*27*16
// ---------------- scratch (static device memory; no allocation APIs) ----------------
__device__ float g_f[3][NB*64*H3];     // encoder outputs: pm, pb, nm
__device__ float g_corr[NB*18*H3];     // correlation output (18 distinct channels)
__device__ float g_c1[NB*16*H3];       // conv1 raw out (phi 0-7, vort 8-15)
__device__ float g_u1[NB*16*S3];       // upsampled (post BN1+relu)
__device__ float g_c2[NB*16*S3];       // conv2 raw out
__device__ float g_ti[NB*D3*8];        // texture, interleaved [n][p][8]
__device__ float g_phi1[NB*D3*8];      // advect pass 1, interleaved
__device__ float g_comb[NB*D3*8];      // 1.5*tex - 0.5*phi2, interleaved
__device__ float g_pred[NB*D3*8];      // final advect result, interleaved
__device__ float g_gbuf[D3*64];        // FF hidden, interleaved [p][64]
__device__ float g_wc1[3*WC1_PACK];    // conv1 summed packs: [pack][(tap*18+ic)*16+oc]
__device__ float g_wp2[27*8*16];       // packed conv2 weights [(tap*8+icg)*16+oc]
__device__ float g_stat[64];           // mean1[16], istd1[16], mean2[16], istd2[16]
__device__ double g_part[16*32*2];     // partial reduction sums

// ---------------- weight packing ----------------
__global__ void pack_kernel(const float* __restrict__ pw1, const float* __restrict__ vw1,
                            const float* __restrict__ pw2, const float* __restrict__ vw2) {
    int i = blockIdx.x * blockDim.x + threadIdx.x;
    if (i < 3*WC1_PACK) {
        int pack = i / WC1_PACK; int r = i % WC1_PACK;
        int oc = r & 15; int t18 = r >> 4; int ic = t18 % 18; int tap = t18 / 18;
        int w = ic / 9, s = ic % 9;
        int c0 = w*27 + s, c1 = c0 + 9, c2 = c0 + 18;
        const float* src = (oc < 8) ? pw1 : vw1;
        int o = (oc < 8) ? oc : oc - 8;
        float W0 = src[(o*54 + c0)*27 + tap];
        float W1 = src[(o*54 + c1)*27 + tap];
        float W2 = src[(o*54 + c2)*27 + tap];
        float v = (pack == 0) ? (W0 + W1 + W2) : ((pack == 1) ? (W0 + W1) : (W1 + W2));
        g_wc1[i] = v;
    }
    if (i < 27*8*16) {
        int oc = i & 15; int icg = (i >> 4) % 8; int t = (i >> 4) / 8;
        g_wp2[i] = (oc < 8) ? pw2[(oc*8 + icg)*27 + t] : vw2[((oc-8)*8 + icg)*27 + t];
    }
}

// ---------------- texture transpose: channel-major -> interleaved [n][p][8] ----------------
__global__ void tpose_kernel(const float* __restrict__ tex) {
    int idx = blockIdx.x * blockDim.x + threadIdx.x;
    if (idx >= NB*D3) return;
    int p = idx % D3; int n = idx / D3;
    float4 lo, hi;
    lo.x = tex[(n*8+0)*D3 + p]; lo.y = tex[(n*8+1)*D3 + p];
    lo.z = tex[(n*8+2)*D3 + p]; lo.w = tex[(n*8+3)*D3 + p];
    hi.x = tex[(n*8+4)*D3 + p]; hi.y = tex[(n*8+5)*D3 + p];
    hi.z = tex[(n*8+6)*D3 + p]; hi.w = tex[(n*8+7)*D3 + p];
    float4* dst = reinterpret_cast<float4*>(g_ti + (size_t)idx*8);
    dst[0] = lo; dst[1] = hi;
}

// ---------------- encoder: conv3d stride 2, kernel 2, input = src*mul ----------------
__global__ void enc_kernel(const float* __restrict__ src, const float* __restrict__ mul,
                           const float* __restrict__ w, const float* __restrict__ b, int variant) {
    __shared__ float ws[4096];
    __shared__ float bs[64];
    for (int i = threadIdx.x; i < 4096; i += blockDim.x) ws[i] = w[i];
    if (threadIdx.x < 64) bs[threadIdx.x] = b[threadIdx.x];
    __syncthreads();

    int idx = blockIdx.x * blockDim.x + threadIdx.x;
    if (idx >= NB*H3) return;
    int p = idx % H3;
    int n = idx / H3;
    int z = p % HH, y = (p / HH) % HH, x = p / H2;
    int X = 2*x, Y = 2*y, Z = 2*z;

    float m[8];
#pragma unroll
    for (int t = 0; t < 8; t++) {
        int dx = t >> 2, dy = (t >> 1) & 1, dz = t & 1;
        m[t] = mul[((X+dx)*S + (Y+dy))*S + (Z+dz)];
    }

    float xin[64];
#pragma unroll
    for (int ic = 0; ic < 8; ic++) {
        int base = (n*8 + ic)*S3 + (X*S + Y)*S + Z;
#pragma unroll
        for (int t = 0; t < 8; t++) {
            int dx = t >> 2, dy = (t >> 1) & 1, dz = t & 1;
            xin[ic*8 + t] = src[base + (dx*S + dy)*S + dz] * m[t];
        }
    }

    float* outp = &g_f[variant][(n*64)*H3 + p];
    for (int oc = 0; oc < 64; oc++) {
        float acc = bs[oc];
        const float4* wv = reinterpret_cast<const float4*>(ws + (oc << 6));
#pragma unroll
        for (int q = 0; q < 16; q++) {
            float4 w4 = wv[q];
            acc += xin[q*4+0]*w4.x + xin[q*4+1]*w4.y + xin[q*4+2]*w4.z + xin[q*4+3]*w4.w;
        }
        outp[oc*H3] = acc;
    }
}

// ---------------- correlation: 18 distinct channels (masks folded into conv1 weights) ----------------
__global__ void corr_kernel() {
    int idx = blockIdx.x * blockDim.x + threadIdx.x;
    if (idx >= NB*H3) return;
    int p = idx % H3; int n = idx / H3;
    int y = (p / HH) % HH, x = p / H2;

    const float* A0 = &g_f[0][n*64*H3 + p];
    const float* A1 = &g_f[1][n*64*H3 + p];
    const float* B  = &g_f[2][n*64*H3 + p];

    int off[9]; bool ok[9];
    {
        int s = 0;
        for (int di = -1; di <= 1; di++)
            for (int dj = -1; dj <= 1; dj++) {
                ok[s] = (x+di >= 0 && x+di < HH && y+dj >= 0 && y+dj < HH);
                off[s] = (di*HH + dj)*HH;
                s++;
            }
    }
    float acc[18];
#pragma unroll
    for (int s = 0; s < 18; s++) acc[s] = 0.f;

    for (int c = 0; c < 64; c++) {
        float a0 = A0[c*H3];
        float a1 = A1[c*H3];
        const float* Bc = B + c*H3;
#pragma unroll
        for (int s = 0; s < 9; s++) {
            float bv = ok[s] ? Bc[off[s]] : 0.f;
            acc[s]   += a0 * bv;
            acc[9+s] += a1 * bv;
        }
    }
#pragma unroll
    for (int s = 0; s < 18; s++)
        g_corr[(n*18 + s)*H3 + p] = acc[s] * (1.f/64.f);
}

// ---------------- conv1: effective 18 -> 16, 3^3, pad 1, on 33^3, z-masked weight packs ----------------
__global__ void conv1_kernel() {
    extern __shared__ float ws[];
    for (int i = threadIdx.x; i < 3*WC1_PACK; i += blockDim.x) ws[i] = g_wc1[i];
    __syncthreads();

    int idx = blockIdx.x * blockDim.x + threadIdx.x;
    if (idx >= NB*H3) return;
    int p = idx % H3; int n = idx / H3;
    int z = p % HH, y = (p / HH) % HH, x = p / H2;

    float acc[16];
#pragma unroll
    for (int i = 0; i < 16; i++) acc[i] = 0.f;

    const float* cbase = g_corr + n*18*H3;
    for (int tap = 0; tap < 27; tap++) {
        int dx = tap/9 - 1, dy = (tap/3)%3 - 1, dz = tap%3 - 1;
        int xx = x+dx, yy = y+dy, zz = z+dz;
        if ((unsigned)xx >= (unsigned)HH || (unsigned)yy >= (unsigned)HH || (unsigned)zz >= (unsigned)HH) continue;
        int q = (xx*HH + yy)*HH + zz;
        int sel = (zz == 0) ? 1 : ((zz == HH-1) ? 2 : 0);
        const float* wt = ws + sel*WC1_PACK + tap*288;
#pragma unroll
        for (int ic = 0; ic < 18; ic++) {
            float v = cbase[ic*H3 + q];
            const float4* wv = reinterpret_cast<const float4*>(wt + (ic << 4));
            float4 w0 = wv[0], w1 = wv[1], w2 = wv[2], w3 = wv[3];
            acc[0]  += v*w0.x; acc[1]  += v*w0.y; acc[2]  += v*w0.z; acc[3]  += v*w0.w;
            acc[4]  += v*w1.x; acc[5]  += v*w1.y; acc[6]  += v*w1.z; acc[7]  += v*w1.w;
            acc[8]  += v*w2.x; acc[9]  += v*w2.y; acc[10] += v*w2.z; acc[11] += v*w2.w;
            acc[12] += v*w3.x; acc[13] += v*w3.y; acc[14] += v*w3.z; acc[15] += v*w3.w;
        }
    }
#pragma unroll
    for (int oc = 0; oc < 16; oc++) g_c1[(n*16 + oc)*H3 + p] = acc[oc];
}

// ---------------- BN stats (two-stage deterministic) ----------------
__global__ void bn_stats_partial(int phase) {
    const float* src = phase ? g_c2 : g_c1;
    int spatial = phase ? S3 : H3;
    int total = NB * spatial;
    int ch = blockIdx.x, sl = blockIdx.y;
    double s = 0.0, s2 = 0.0;
    for (int i = sl*blockDim.x + threadIdx.x; i < total; i += 32*blockDim.x) {
        int n = i / spatial, p = i % spatial;
        float v = src[(n*16 + ch)*spatial + p];
        s += v; s2 += (double)v * v;
    }
    __shared__ double sh[512], sh2[512];
    sh[threadIdx.x] = s; sh2[threadIdx.x] = s2;
    __syncthreads();
    for (int st = 256; st > 0; st >>= 1) {
        if (threadIdx.x < st) { sh[threadIdx.x] += sh[threadIdx.x+st]; sh2[threadIdx.x] += sh2[threadIdx.x+st]; }
        __syncthreads();
    }
    if (threadIdx.x == 0) {
        g_part[(ch*32 + sl)*2 + 0] = sh[0];
        g_part[(ch*32 + sl)*2 + 1] = sh2[0];
    }
}

__global__ void bn_stats_final(int phase) {
    int ch = blockIdx.x;
    if (threadIdx.x != 0) return;
    int spatial = phase ? S3 : H3;
    double total = (double)NB * spatial;
    double s = 0.0, s2 = 0.0;
    for (int i = 0; i < 32; i++) { s += g_part[(ch*32+i)*2]; s2 += g_part[(ch*32+i)*2+1]; }
    double mean = s / total;
    double var = s2 / total - mean*mean;
    g_stat[phase*32 + ch]      = (float)mean;
    g_stat[phase*32 + 16 + ch] = (float)(1.0 / sqrt(var + 1e-5));
}

// ---------------- BN1 + relu + trilinear upsample x2 (align_corners) ----------------
__device__ __forceinline__ float bnrelu(float v, float sc, float sh) { return fmaxf(v*sc + sh, 0.f); }

__global__ void upsample_kernel(const float* __restrict__ g1p, const float* __restrict__ b1p,
                                const float* __restrict__ g1v, const float* __restrict__ b1v) {
    int idx = blockIdx.x * blockDim.x + threadIdx.x;
    if (idx >= NB*16*S3) return;
    int p = idx % S3; int ch = (idx / S3) % 16; int n = idx / (16*S3);
    int Z = p % S, Y = (p / S) % S, X = p / S2;

    float mean = g_stat[ch], istd = g_stat[16 + ch];
    float gg = (ch < 8) ? g1p[ch] : g1v[ch-8];
    float bb = (ch < 8) ? b1p[ch] : b1v[ch-8];
    float sc = istd * gg, sh = bb - mean * sc;

    const float SC = 32.f / 65.f;
    float sx = X * SC; int x0 = (int)sx; float fx = sx - x0; int x1 = min(x0+1, 32);
    float sy = Y * SC; int y0 = (int)sy; float fy = sy - y0; int y1 = min(y0+1, 32);
    float sz = Z * SC; int z0 = (int)sz; float fz = sz - z0; int z1 = min(z0+1, 32);

    const float* base = g_c1 + (n*16 + ch)*H3;
#define RD(xi,yi,zi) bnrelu(base[((xi)*HH+(yi))*HH+(zi)], sc, sh)
    float v =
      ((RD(x0,y0,z0)*(1-fx) + RD(x1,y0,z0)*fx)*(1-fy) + (RD(x0,y1,z0)*(1-fx) + RD(x1,y1,z0)*fx)*fy)*(1-fz)
    + ((RD(x0,y0,z1)*(1-fx) + RD(x1,y0,z1)*fx)*(1-fy) + (RD(x0,y1,z1)*(1-fx) + RD(x1,y1,z1)*fx)*fy)*fz;
#undef RD
    g_u1[idx] = v;
}

// ---------------- conv2: grouped 2x(8->8), 3^3, pad 1, on 66^3, z-vectorized x2 ----------------
__global__ void conv2_kernel() {
    __shared__ float ws[27*8*16];
    for (int i = threadIdx.x; i < 27*8*16; i += blockDim.x) ws[i] = g_wp2[i];
    __syncthreads();

    int idx = blockIdx.x * blockDim.x + threadIdx.x;
    if (idx >= NB*S*S*33) return;
    int zt = idx % 33;
    int y  = (idx / 33) % S;
    int x  = (idx / (33*S)) % S;
    int n  = idx / (33*S*S);
    int z0 = 2*zt;

    float acc[2][16];
#pragma unroll
    for (int pp = 0; pp < 2; pp++)
#pragma unroll
        for (int i = 0; i < 16; i++) acc[pp][i] = 0.f;

    const float* ubase = g_u1 + n*16*S3;
    bool zlo = (zt == 0);
    bool zhi = (zt == 32);

#pragma unroll
    for (int dx = -1; dx <= 1; dx++) {
        int xx = x + dx;
        if ((unsigned)xx >= (unsigned)S) continue;
#pragma unroll
        for (int dy = -1; dy <= 1; dy++) {
            int yy = y + dy;
            if ((unsigned)yy >= (unsigned)S) continue;
            int tap0 = ((dx+1)*3 + (dy+1))*3;
            const float* col = ubase + (xx*S + yy)*S + z0;
#pragma unroll
            for (int icg = 0; icg < 8; icg++) {
                const float* cp = col + icg*S3;
                const float* cv = col + (8+icg)*S3;
                float inp[4], inv[4];
                inp[0] = zlo ? 0.f : cp[-1];  inv[0] = zlo ? 0.f : cv[-1];
                inp[1] = cp[0];               inv[1] = cv[0];
                inp[2] = cp[1];               inv[2] = cv[1];
                inp[3] = zhi ? 0.f : cp[2];   inv[3] = zhi ? 0.f : cv[2];
#pragma unroll
                for (int dz = 0; dz < 3; dz++) {
                    const float4* wv = reinterpret_cast<const float4*>(ws + (((tap0+dz)*8 + icg) << 4));
                    float4 w0 = wv[0], w1 = wv[1], w2 = wv[2], w3 = wv[3];
#pragma unroll
                    for (int pp = 0; pp < 2; pp++) {
                        float vp = inp[pp+dz];
                        float vv = inv[pp+dz];
                        acc[pp][0]  += vp*w0.x; acc[pp][1]  += vp*w0.y; acc[pp][2]  += vp*w0.z; acc[pp][3]  += vp*w0.w;
                        acc[pp][4]  += vp*w1.x; acc[pp][5]  += vp*w1.y; acc[pp][6]  += vp*w1.z; acc[pp][7]  += vp*w1.w;
                        acc[pp][8]  += vv*w2.x; acc[pp][9]  += vv*w2.y; acc[pp][10] += vv*w2.z; acc[pp][11] += vv*w2.w;
                        acc[pp][12] += vv*w3.x; acc[pp][13] += vv*w3.y; acc[pp][14] += vv*w3.z; acc[pp][15] += vv*w3.w;
                    }
                }
            }
        }
    }
    int ob = (x*S + y)*S + z0;
#pragma unroll
    for (int oc = 0; oc < 16; oc++) {
        float2 v; v.x = acc[0][oc]; v.y = acc[1][oc];
        *reinterpret_cast<float2*>(&g_c2[(n*16 + oc)*S3 + ob]) = v;
    }
}

// ---------------- BN2 + relu + 1x1 heads -> helmholtz (into d_out) ----------------
__global__ void helm_kernel(const float* __restrict__ g2p, const float* __restrict__ b2p,
                            const float* __restrict__ g2v, const float* __restrict__ b2v,
                            const float* __restrict__ pow_, const float* __restrict__ pob,
                            const float* __restrict__ vow,  const float* __restrict__ vob,
                            const float* __restrict__ phiw, const float* __restrict__ vortw,
                            float* __restrict__ out) {
    int idx = blockIdx.x * blockDim.x + threadIdx.x;
    if (idx >= NB*S3) return;
    int p = idx % S3; int n = idx / S3;

    float y[16];
#pragma unroll
    for (int c = 0; c < 16; c++) {
        float mean = g_stat[32 + c], istd = g_stat[48 + c];
        float gg = (c < 8) ? g2p[c] : g2v[c-8];
        float bb = (c < 8) ? b2p[c] : b2v[c-8];
        float v = (g_c2[(n*16 + c)*S3 + p] - mean) * istd * gg + bb;
        y[c] = fmaxf(v, 0.f);
    }
    float ph = pob[0];
#pragma unroll
    for (int c = 0; c < 8; c++) ph += y[c] * pow_[c];
    ph *= phiw[0];
    out[OFF_HELM + (n*4)*S3 + p] = ph;
    float vscale = vortw[0] * 66.f;
#pragma unroll
    for (int r = 0; r < 3; r++) {
        float v = vob[r];
#pragma unroll
        for (int c = 0; c < 8; c++) v += y[8+c] * vow[r*8 + c];
        out[OFF_HELM + (n*4 + 1 + r)*S3 + p] = v * vscale;
    }
}

// ---------------- velocity stencils (into d_out) ----------------
__device__ __forceinline__ float HV(const float* hm, int ch, int x, int y, int z) {
    return hm[ch*S3 + (x*S + y)*S + z];
}

__global__ void vel_kernel(float* __restrict__ out) {
    int idx = blockIdx.x * blockDim.x + threadIdx.x;
    if (idx >= NB*D3) return;
    int p = idx % D3; int n = idx / D3;
    int k = p & 63, j = (p >> 6) & 63, i = p >> 12;
    const float* hm = out + OFF_HELM + n*4*S3;

    float vp0 = 0.5f * (HV(hm,0, 1+i, 1+j, k+2) - HV(hm,0, 1+i, 1+j, k));
    float vp1 = 0.5f * (HV(hm,0, 1+i, j+2, 1+k) - HV(hm,0, 1+i, j,   1+k));
    float vp2 = 0.5f * (HV(hm,0, i+2, 1+j, 1+k) - HV(hm,0, i,   1+j, 1+k));

    float ua = (HV(hm,2, 2+i,1+j,k+1) - HV(hm,2, 1+i,1+j,k+1)) - (HV(hm,1, 1+i,2+j,k+1) - HV(hm,1, 1+i,1+j,k+1));
    float ub = (HV(hm,2, 2+i,1+j,k  ) - HV(hm,2, 1+i,1+j,k  )) - (HV(hm,1, 1+i,2+j,k  ) - HV(hm,1, 1+i,1+j,k  ));
    float vv0 = 0.5f * (ua + ub);
    float va = (HV(hm,1, 1+i,j+1,k+2) - HV(hm,1, 1+i,j+1,k+1)) - (HV(hm,3, i+2,j+1,k+1) - HV(hm,3, i+1,j+1,k+1));
    float vb = (HV(hm,1, 1+i,j,  k+2) - HV(hm,1, 1+i,j,  k+1)) - (HV(hm,3, i+2,j,  k+1) - HV(hm,3, i+1,j,  k+1));
    float vv1 = 0.5f * (va + vb);
    float wa = (HV(hm,3, i+1,j+2,k+1) - HV(hm,3, i+1,j+1,k+1)) - (HV(hm,2, i+1,j+1,k+2) - HV(hm,2, i+1,j+1,k+1));
    float wb = (HV(hm,3, i,  j+2,k+1) - HV(hm,3, i,  j+1,k+1)) - (HV(hm,2, i,  j+1,k+2) - HV(hm,2, i,  j+1,k+1));
    float vv2 = 0.5f * (wa + wb);

    int b = n*3*D3 + p;
    out[OFF_VPHI  + b        ] = vp0;
    out[OFF_VPHI  + b + D3   ] = vp1;
    out[OFF_VPHI  + b + 2*D3 ] = vp2;
    out[OFF_VVORT + b        ] = vv0;
    out[OFF_VVORT + b + D3   ] = vv1;
    out[OFF_VVORT + b + 2*D3 ] = vv2;
    out[OFF_VEL   + b        ] = vp0 + vv0;
    out[OFF_VEL   + b + D3   ] = vp1 + vv1;
    out[OFF_VEL   + b + 2*D3 ] = vp2 + vv2;
}

// ---------------- BFECC advect passes (interleaved layout) ----------------
// mode 0: dst=g_phi1, src=g_ti,   sgn=+1
// mode 1: dst=g_comb, src=g_phi1, sgn=-1, combine: 1.5*tex - 0.5*sample
// mode 2: dst=g_pred, src=g_comb, sgn=+1
__global__ void advect_kernel(const float* __restrict__ vel, float sgn, int mode) {
    int idx = blockIdx.x * blockDim.x + threadIdx.x;
    if (idx >= NB*D3) return;
    int p = idx % D3; int n = idx / D3;
    int k = p & 63, j = (p >> 6) & 63, i = p >> 12;

    float v0 = vel[(n*3    )*D3 + p];
    float v1 = vel[(n*3 + 1)*D3 + p];
    float v2 = vel[(n*3 + 2)*D3 + p];
    float px = (float)i - sgn*v2;
    float py = (float)j - sgn*v1;
    float pz = (float)k - sgn*v0;
    px = fminf(fmaxf(px, 0.f), 63.f);
    py = fminf(fmaxf(py, 0.f), 63.f);
    pz = fminf(fmaxf(pz, 0.f), 63.f);
    int x0 = (int)px; float fx = px - x0; int x1 = min(x0+1, 63);
    int y0 = (int)py; float fy = py - y0; int y1 = min(y0+1, 63);
    int z0 = (int)pz; float fz = pz - z0; int z1 = min(z0+1, 63);

    float wt[8];
    wt[0] = (1-fx)*(1-fy)*(1-fz); wt[1] = (1-fx)*(1-fy)*fz;
    wt[2] = (1-fx)*fy*(1-fz);     wt[3] = (1-fx)*fy*fz;
    wt[4] = fx*(1-fy)*(1-fz);     wt[5] = fx*(1-fy)*fz;
    wt[6] = fx*fy*(1-fz);         wt[7] = fx*fy*fz;

    int q[8];
    q[0] = (x0*64 + y0)*64 + z0; q[1] = (x0*64 + y0)*64 + z1;
    q[2] = (x0*64 + y1)*64 + z0; q[3] = (x0*64 + y1)*64 + z1;
    q[4] = (x1*64 + y0)*64 + z0; q[5] = (x1*64 + y0)*64 + z1;
    q[6] = (x1*64 + y1)*64 + z0; q[7] = (x1*64 + y1)*64 + z1;

    const float* src = (mode == 0) ? g_ti : ((mode == 1) ? g_phi1 : g_comb);
    float* dst = (mode == 0) ? g_phi1 : ((mode == 1) ? g_comb : g_pred);
    const float* sb = src + (size_t)n*D3*8;

    float acc[8];
#pragma unroll
    for (int c = 0; c < 8; c++) acc[c] = 0.f;

#pragma unroll
    for (int t = 0; t < 8; t++) {
        const float4* s4 = reinterpret_cast<const float4*>(sb + (size_t)q[t]*8);
        float4 lo = s4[0], hi = s4[1];
        float w = wt[t];
        acc[0] += w*lo.x; acc[1] += w*lo.y; acc[2] += w*lo.z; acc[3] += w*lo.w;
        acc[4] += w*hi.x; acc[5] += w*hi.y; acc[6] += w*hi.z; acc[7] += w*hi.w;
    }

    if (mode == 1) {
        const float4* t4 = reinterpret_cast<const float4*>(g_ti + (size_t)idx*8);
        float4 lo = t4[0], hi = t4[1];
        acc[0] = 1.5f*lo.x - 0.5f*acc[0]; acc[1] = 1.5f*lo.y - 0.5f*acc[1];
        acc[2] = 1.5f*lo.z - 0.5f*acc[2]; acc[3] = 1.5f*lo.w - 0.5f*acc[3];
        acc[4] = 1.5f*hi.x - 0.5f*acc[4]; acc[5] = 1.5f*hi.y - 0.5f*acc[5];
        acc[6] = 1.5f*hi.z - 0.5f*acc[6]; acc[7] = 1.5f*hi.w - 0.5f*acc[7];
    }

    float4* d4 = reinterpret_cast<float4*>(dst + (size_t)idx*8);
    float4 lo, hi;
    lo.x = acc[0]; lo.y = acc[1]; lo.z = acc[2]; lo.w = acc[3];
    hi.x = acc[4]; hi.y = acc[5]; hi.z = acc[6]; hi.w = acc[7];
    d4[0] = lo; d4[1] = hi;
}

// ---------------- LN + FF stage 1 (LN, @W1+b1, exact GELU) ----------------
__global__ void f1_kernel(const float* __restrict__ lng, const float* __restrict__ lnb,
                          const float* __restrict__ w1, const float* __restrict__ b1) {
    __shared__ float W[4096], Bv[64], G[64], Bt[64];
    for (int i = threadIdx.x; i < 4096; i += blockDim.x) W[i] = w1[i];
    if (threadIdx.x < 64) { Bv[threadIdx.x] = b1[threadIdx.x]; G[threadIdx.x] = lng[threadIdx.x]; Bt[threadIdx.x] = lnb[threadIdx.x]; }
    __syncthreads();

    int p = blockIdx.x * blockDim.x + threadIdx.x;
    if (p >= D3) return;
    float h[64]; float s = 0.f, s2 = 0.f;
#pragma unroll
    for (int n = 0; n < 8; n++) {
        const float4* p4 = reinterpret_cast<const float4*>(g_pred + ((size_t)n*D3 + p)*8);
        float4 lo = p4[0], hi = p4[1];
        h[n*8+0] = lo.x; h[n*8+1] = lo.y; h[n*8+2] = lo.z; h[n*8+3] = lo.w;
        h[n*8+4] = hi.x; h[n*8+5] = hi.y; h[n*8+6] = hi.z; h[n*8+7] = hi.w;
    }
#pragma unroll
    for (int c = 0; c < 64; c++) { s += h[c]; s2 += h[c]*h[c]; }
    float mean = s * (1.f/64.f);
    float var  = s2 * (1.f/64.f) - mean*mean;
    float is = rsqrtf(var + 1e-5f);
#pragma unroll
    for (int c = 0; c < 64; c++) h[c] = (h[c] - mean) * is * G[c] + Bt[c];

    float* gb = g_gbuf + (size_t)p*64;
    for (int jj = 0; jj < 64; jj += 4) {
        float a0 = Bv[jj], a1 = Bv[jj+1], a2 = Bv[jj+2], a3 = Bv[jj+3];
#pragma unroll
        for (int ii = 0; ii < 64; ii++) {
            float hv = h[ii];
            const float* wr = W + ii*64 + jj;
            a0 += hv * wr[0]; a1 += hv * wr[1]; a2 += hv * wr[2]; a3 += hv * wr[3];
        }
        float4 g;
        g.x = 0.5f * a0 * (1.f + erff(a0 * 0.70710678118f));
        g.y = 0.5f * a1 * (1.f + erff(a1 * 0.70710678118f));
        g.z = 0.5f * a2 * (1.f + erff(a2 * 0.70710678118f));
        g.w = 0.5f * a3 * (1.f + erff(a3 * 0.70710678118f));
        *reinterpret_cast<float4*>(gb + jj) = g;
    }
}

// ---------------- FF stage 2 (@W2+b2, residual -> d_out x) ----------------
__global__ void f2_kernel(const float* __restrict__ w2, const float* __restrict__ b2,
                          float* __restrict__ out) {
    __shared__ float W[4096], Bv[64];
    for (int i = threadIdx.x; i < 4096; i += blockDim.x) W[i] = w2[i];
    if (threadIdx.x < 64) Bv[threadIdx.x] = b2[threadIdx.x];
    __syncthreads();

    int p = blockIdx.x * blockDim.x + threadIdx.x;
    if (p >= D3) return;
    float g[64];
    const float* gb = g_gbuf + (size_t)p*64;
#pragma unroll
    for (int c = 0; c < 64; c += 4) {
        float4 v = *reinterpret_cast<const float4*>(gb + c);
        g[c] = v.x; g[c+1] = v.y; g[c+2] = v.z; g[c+3] = v.w;
    }
    float r[64];
#pragma unroll
    for (int n = 0; n < 8; n++) {
        const float4* p4 = reinterpret_cast<const float4*>(g_pred + ((size_t)n*D3 + p)*8);
        float4 lo = p4[0], hi = p4[1];
        r[n*8+0] = lo.x; r[n*8+1] = lo.y; r[n*8+2] = lo.z; r[n*8+3] = lo.w;
        r[n*8+4] = hi.x; r[n*8+5] = hi.y; r[n*8+6] = hi.z; r[n*8+7] = hi.w;
    }
    for (int jj = 0; jj < 64; jj++) {
        float a = Bv[jj];
#pragma unroll
        for (int ii = 0; ii < 64; ii++) a += g[ii] * W[ii*64 + jj];
        out[OFF_X + (size_t)jj*D3 + p] = r[jj] + a;
    }
}

// ---------------- host launch ----------------
extern "C" void kernel_launch(void* const* d_in, const int* in_sizes, int n_in,
                              void* d_out, int out_size) {
    const float* prev      = (const float*)d_in[0];
    const float* nxt       = (const float*)d_in[1];
    const float* texture   = (const float*)d_in[2];
    const float* mask      = (const float*)d_in[3];
    const float* boundary  = (const float*)d_in[4];
    const float* enc_w     = (const float*)d_in[5];
    const float* enc_b     = (const float*)d_in[6];
    const float* phi_c1_w  = (const float*)d_in[7];
    const float* phi_bn1_g = (const float*)d_in[8];
    const float* phi_bn1_b = (const float*)d_in[9];
    const float* phi_c2_w  = (const float*)d_in[10];
    const float* phi_bn2_g = (const float*)d_in[11];
    const float* phi_bn2_b = (const float*)d_in[12];
    const float* phi_out_w = (const float*)d_in[13];
    const float* phi_out_b = (const float*)d_in[14];
    const float* vort_c1_w = (const float*)d_in[15];
    const float* vort_bn1_g= (const float*)d_in[16];
    const float* vort_bn1_b= (const float*)d_in[17];
    const float* vort_c2_w = (const float*)d_in[18];
    const float* vort_bn2_g= (const float*)d_in[19];
    const float* vort_bn2_b= (const float*)d_in[20];
    const float* vort_out_w= (const float*)d_in[21];
    const float* vort_out_b= (const float*)d_in[22];
    const float* phi_weight= (const float*)d_in[23];
    const float* vort_weight=(const float*)d_in[24];
    const float* ln_g      = (const float*)d_in[25];
    const float* ln_b      = (const float*)d_in[26];
    const float* ff_w1     = (const float*)d_in[27];
    const float* ff_b1     = (const float*)d_in[28];
    const float* ff_w2     = (const float*)d_in[29];
    const float* ff_b2     = (const float*)d_in[30];
    float* out = (float*)d_out;

    pack_kernel<<<(3*WC1_PACK + 255)/256, 256>>>(phi_c1_w, vort_c1_w, phi_c2_w, vort_c2_w);
    tpose_kernel<<<(NB*D3 + 255)/256, 256>>>(texture);

    int encBlocks = (NB*H3 + 255)/256;
    enc_kernel<<<encBlocks, 256>>>(prev, mask,     enc_w, enc_b, 0);
    enc_kernel<<<encBlocks, 256>>>(prev, boundary, enc_w, enc_b, 1);
    enc_kernel<<<encBlocks, 256>>>(nxt,  mask,     enc_w, enc_b, 2);

    corr_kernel<<<(NB*H3 + 255)/256, 256>>>();

    cudaFuncSetAttribute(conv1_kernel, cudaFuncAttributeMaxDynamicSharedMemorySize, 3*WC1_PACK*4);
    conv1_kernel<<<(NB*H3 + 255)/256, 256, 3*WC1_PACK*4>>>();

    bn_stats_partial<<<dim3(16, 32), 512>>>(0);
    bn_stats_final<<<16, 32>>>(0);

    int upN = NB*16*S3;
    upsample_kernel<<<(upN + 255)/256, 256>>>(phi_bn1_g, phi_bn1_b, vort_bn1_g, vort_bn1_b);

    conv2_kernel<<<(NB*S*S*33 + 255)/256, 256>>>();

    bn_stats_partial<<<dim3(16, 32), 512>>>(1);
    bn_stats_final<<<16, 32>>>(1);

    helm_kernel<<<(NB*S3 + 255)/256, 256>>>(phi_bn2_g, phi_bn2_b, vort_bn2_g, vort_bn2_b,
                                            phi_out_w, phi_out_b, vort_out_w, vort_out_b,
                                            phi_weight, vort_weight, out);

    vel_kernel<<<(NB*D3 + 255)/256, 256>>>(out);

    const float* vel = out + OFF_VEL;
    advect_kernel<<<(NB*D3 + 255)/256, 256>>>(vel,  1.f, 0);
    advect_kernel<<<(NB*D3 + 255)/256, 256>>>(vel, -1.f, 1);
    advect_kernel<<<(NB*D3 + 255)/256, 256>>>(vel,  1.f, 2);

    f1_kernel<<<(D3 + 127)/128, 128>>>(ln_g, ln_b, ff_w1, ff_b1);
    f2_kernel<<<(D3 + 127)/128, 128>>>(ff_w2, ff_b2, out);
}

// round 8
// speedup vs baseline: 1.0404x; 1.0404x over previous
#include <cuda_runtime.h>
#include <math.h>

// ---------------- dimensions ----------------
#define NB 8          // batch*groups
#define S  66
#define S2 4356       // 66*66
#define S3 287496     // 66^3
#define HH 33
#define H2 1089       // 33*33
#define H3 35937      // 33^3
#define D3 262144     // 64^3

// output packing offsets (x, helmholtz, vel, vel_phi, vel_vort)
#define OFF_X     0
#define OFF_HELM  16777216
#define OFF_VEL   25977088
#define OFF_VPHI  32268544
#define OFF_VVORT 38560000

#define WC1_PACK 7776          // 18*27*16
// ---------------- scratch (static device memory; no allocation APIs) ----------------
__device__ float g_f[3][NB*64*H3];     // encoder outputs: pm, pb, nm
__device__ float g_corr[NB*18*H3];     // correlation output (18 distinct channels)
__device__ float g_c1[NB*16*H3];       // conv1 raw out (phi 0-7, vort 8-15)
__device__ float g_u1[NB*16*S3];       // upsampled (post BN1+relu)
__device__ float g_c2[NB*16*S3];       // conv2 raw out
__device__ float g_phi1[64*D3];        // advect pass 1
__device__ float g_comb[64*D3];        // 1.5*tex - 0.5*phi2
__device__ float g_pred[64*D3];        // final advect result
__device__ float g_gbuf[64*D3];        // FF hidden
__device__ float g_wc1[3*WC1_PACK];    // conv1 summed packs: [pack][(tap*18+ic)*16+oc]
__device__ float g_wp2[27*8*16];       // packed conv2 weights [(tap*8+icg)*16+oc]
__device__ float g_stat[64];           // mean1[16], istd1[16], mean2[16], istd2[16]
__device__ double g_part[16*32*2];     // partial reduction sums

// ---------------- packed f32x2 helpers (sm_103a FFMA2 via PTX) ----------------
__device__ __forceinline__ unsigned long long pk2(float a, float b) {
    unsigned long long r;
    asm("mov.b64 %0, {%1, %2};" : "=l"(r) : "f"(a), "f"(b));
    return r;
}
__device__ __forceinline__ void fma2(unsigned long long& d, unsigned long long a, unsigned long long b) {
    asm("fma.rn.f32x2 %0, %1, %2, %0;" : "+l"(d) : "l"(a), "l"(b));
}
__device__ __forceinline__ void upk2(unsigned long long v, float& lo, float& hi) {
    asm("mov.b64 {%0, %1}, %2;" : "=f"(lo), "=f"(hi) : "l"(v));
}

// ---------------- weight packing ----------------
__global__ void pack_kernel(const float* __restrict__ pw1, const float* __restrict__ vw1,
                            const float* __restrict__ pw2, const float* __restrict__ vw2) {
    int i = blockIdx.x * blockDim.x + threadIdx.x;
    if (i < 3*WC1_PACK) {
        int pack = i / WC1_PACK; int r = i % WC1_PACK;
        int oc = r & 15; int t18 = r >> 4; int ic = t18 % 18; int tap = t18 / 18;
        int w = ic / 9, s = ic % 9;
        int c0 = w*27 + s, c1 = c0 + 9, c2 = c0 + 18;
        const float* src = (oc < 8) ? pw1 : vw1;
        int o = (oc < 8) ? oc : oc - 8;
        float W0 = src[(o*54 + c0)*27 + tap];
        float W1 = src[(o*54 + c1)*27 + tap];
        float W2 = src[(o*54 + c2)*27 + tap];
        float v = (pack == 0) ? (W0 + W1 + W2) : ((pack == 1) ? (W0 + W1) : (W1 + W2));
        g_wc1[i] = v;
    }
    if (i < 27*8*16) {
        int oc = i & 15; int icg = (i >> 4) % 8; int t = (i >> 4) / 8;
        g_wp2[i] = (oc < 8) ? pw2[(oc*8 + icg)*27 + t] : vw2[((oc-8)*8 + icg)*27 + t];
    }
}

// ---------------- encoder: conv3d stride 2, kernel 2, input = src*mul ----------------
__global__ void enc_kernel(const float* __restrict__ src, const float* __restrict__ mul,
                           const float* __restrict__ w, const float* __restrict__ b, int variant) {
    __shared__ float ws[4096];
    __shared__ float bs[64];
    for (int i = threadIdx.x; i < 4096; i += blockDim.x) ws[i] = w[i];
    if (threadIdx.x < 64) bs[threadIdx.x] = b[threadIdx.x];
    __syncthreads();

    int idx = blockIdx.x * blockDim.x + threadIdx.x;
    if (idx >= NB*H3) return;
    int p = idx % H3;
    int n = idx / H3;
    int z = p % HH, y = (p / HH) % HH, x = p / H2;
    int X = 2*x, Y = 2*y, Z = 2*z;

    float m[8];
#pragma unroll
    for (int t = 0; t < 8; t++) {
        int dx = t >> 2, dy = (t >> 1) & 1, dz = t & 1;
        m[t] = mul[((X+dx)*S + (Y+dy))*S + (Z+dz)];
    }

    float xin[64];
#pragma unroll
    for (int ic = 0; ic < 8; ic++) {
        int base = (n*8 + ic)*S3 + (X*S + Y)*S + Z;
#pragma unroll
        for (int t = 0; t < 8; t++) {
            int dx = t >> 2, dy = (t >> 1) & 1, dz = t & 1;
            xin[ic*8 + t] = src[base + (dx*S + dy)*S + dz] * m[t];
        }
    }

    float* outp = &g_f[variant][(n*64)*H3 + p];
    for (int oc = 0; oc < 64; oc++) {
        float acc = bs[oc];
        const float4* wv = reinterpret_cast<const float4*>(ws + (oc << 6));
#pragma unroll
        for (int q = 0; q < 16; q++) {
            float4 w4 = wv[q];
            acc += xin[q*4+0]*w4.x + xin[q*4+1]*w4.y + xin[q*4+2]*w4.z + xin[q*4+3]*w4.w;
        }
        outp[oc*H3] = acc;
    }
}

// ---------------- correlation: 18 distinct channels (masks folded into conv1 weights) ----------------
__global__ void corr_kernel() {
    int idx = blockIdx.x * blockDim.x + threadIdx.x;
    if (idx >= NB*H3) return;
    int p = idx % H3; int n = idx / H3;
    int y = (p / HH) % HH, x = p / H2;

    const float* A0 = &g_f[0][n*64*H3 + p];
    const float* A1 = &g_f[1][n*64*H3 + p];
    const float* B  = &g_f[2][n*64*H3 + p];

    int off[9]; bool ok[9];
    {
        int s = 0;
        for (int di = -1; di <= 1; di++)
            for (int dj = -1; dj <= 1; dj++) {
                ok[s] = (x+di >= 0 && x+di < HH && y+dj >= 0 && y+dj < HH);
                off[s] = (di*HH + dj)*HH;
                s++;
            }
    }
    float acc[18];
#pragma unroll
    for (int s = 0; s < 18; s++) acc[s] = 0.f;

    for (int c = 0; c < 64; c++) {
        float a0 = A0[c*H3];
        float a1 = A1[c*H3];
        const float* Bc = B + c*H3;
#pragma unroll
        for (int s = 0; s < 9; s++) {
            float bv = ok[s] ? Bc[off[s]] : 0.f;
            acc[s]   += a0 * bv;
            acc[9+s] += a1 * bv;
        }
    }
#pragma unroll
    for (int s = 0; s < 18; s++)
        g_corr[(n*18 + s)*H3 + p] = acc[s] * (1.f/64.f);
}

// ---------------- conv1: effective 18 -> 16, 3^3, pad 1, on 33^3, f32x2 packed ----------------
__global__ void conv1_kernel() {
    extern __shared__ float ws[];
    for (int i = threadIdx.x; i < 3*WC1_PACK; i += blockDim.x) ws[i] = g_wc1[i];
    __syncthreads();

    int idx = blockIdx.x * blockDim.x + threadIdx.x;
    if (idx >= NB*H3) return;
    int p = idx % H3; int n = idx / H3;
    int z = p % HH, y = (p / HH) % HH, x = p / H2;

    unsigned long long acc2[8];
#pragma unroll
    for (int i = 0; i < 8; i++) acc2[i] = 0ULL;

    const float* cbase = g_corr + n*18*H3;
    for (int tap = 0; tap < 27; tap++) {
        int dx = tap/9 - 1, dy = (tap/3)%3 - 1, dz = tap%3 - 1;
        int xx = x+dx, yy = y+dy, zz = z+dz;
        if ((unsigned)xx >= (unsigned)HH || (unsigned)yy >= (unsigned)HH || (unsigned)zz >= (unsigned)HH) continue;
        int q = (xx*HH + yy)*HH + zz;
        int sel = (zz == 0) ? 1 : ((zz == HH-1) ? 2 : 0);
        const float* wt = ws + sel*WC1_PACK + tap*288;
#pragma unroll
        for (int ic = 0; ic < 18; ic++) {
            float v = cbase[ic*H3 + q];
            unsigned long long v2 = pk2(v, v);
            const unsigned long long* wp = reinterpret_cast<const unsigned long long*>(wt + (ic << 4));
            fma2(acc2[0], v2, wp[0]); fma2(acc2[1], v2, wp[1]);
            fma2(acc2[2], v2, wp[2]); fma2(acc2[3], v2, wp[3]);
            fma2(acc2[4], v2, wp[4]); fma2(acc2[5], v2, wp[5]);
            fma2(acc2[6], v2, wp[6]); fma2(acc2[7], v2, wp[7]);
        }
    }
#pragma unroll
    for (int j = 0; j < 8; j++) {
        float lo, hi;
        upk2(acc2[j], lo, hi);
        g_c1[(n*16 + 2*j    )*H3 + p] = lo;
        g_c1[(n*16 + 2*j + 1)*H3 + p] = hi;
    }
}

// ---------------- BN stats (two-stage deterministic) ----------------
__global__ void bn_stats_partial(int phase) {
    const float* src = phase ? g_c2 : g_c1;
    int spatial = phase ? S3 : H3;
    int total = NB * spatial;
    int ch = blockIdx.x, sl = blockIdx.y;
    double s = 0.0, s2 = 0.0;
    for (int i = sl*blockDim.x + threadIdx.x; i < total; i += 32*blockDim.x) {
        int n = i / spatial, p = i % spatial;
        float v = src[(n*16 + ch)*spatial + p];
        s += v; s2 += (double)v * v;
    }
    __shared__ double sh[512], sh2[512];
    sh[threadIdx.x] = s; sh2[threadIdx.x] = s2;
    __syncthreads();
    for (int st = 256; st > 0; st >>= 1) {
        if (threadIdx.x < st) { sh[threadIdx.x] += sh[threadIdx.x+st]; sh2[threadIdx.x] += sh2[threadIdx.x+st]; }
        __syncthreads();
    }
    if (threadIdx.x == 0) {
        g_part[(ch*32 + sl)*2 + 0] = sh[0];
        g_part[(ch*32 + sl)*2 + 1] = sh2[0];
    }
}

__global__ void bn_stats_final(int phase) {
    int ch = blockIdx.x;
    if (threadIdx.x != 0) return;
    int spatial = phase ? S3 : H3;
    double total = (double)NB * spatial;
    double s = 0.0, s2 = 0.0;
    for (int i = 0; i < 32; i++) { s += g_part[(ch*32+i)*2]; s2 += g_part[(ch*32+i)*2+1]; }
    double mean = s / total;
    double var = s2 / total - mean*mean;
    g_stat[phase*32 + ch]      = (float)mean;
    g_stat[phase*32 + 16 + ch] = (float)(1.0 / sqrt(var + 1e-5));
}

// ---------------- BN1 + relu + trilinear upsample x2 (align_corners) ----------------
__device__ __forceinline__ float bnrelu(float v, float sc, float sh) { return fmaxf(v*sc + sh, 0.f); }

__global__ void upsample_kernel(const float* __restrict__ g1p, const float* __restrict__ b1p,
                                const float* __restrict__ g1v, const float* __restrict__ b1v) {
    int idx = blockIdx.x * blockDim.x + threadIdx.x;
    if (idx >= NB*16*S3) return;
    int p = idx % S3; int ch = (idx / S3) % 16; int n = idx / (16*S3);
    int Z = p % S, Y = (p / S) % S, X = p / S2;

    float mean = g_stat[ch], istd = g_stat[16 + ch];
    float gg = (ch < 8) ? g1p[ch] : g1v[ch-8];
    float bb = (ch < 8) ? b1p[ch] : b1v[ch-8];
    float sc = istd * gg, sh = bb - mean * sc;

    const float SC = 32.f / 65.f;
    float sx = X * SC; int x0 = (int)sx; float fx = sx - x0; int x1 = min(x0+1, 32);
    float sy = Y * SC; int y0 = (int)sy; float fy = sy - y0; int y1 = min(y0+1, 32);
    float sz = Z * SC; int z0 = (int)sz; float fz = sz - z0; int z1 = min(z0+1, 32);

    const float* base = g_c1 + (n*16 + ch)*H3;
#define RD(xi,yi,zi) bnrelu(base[((xi)*HH+(yi))*HH+(zi)], sc, sh)
    float v =
      ((RD(x0,y0,z0)*(1-fx) + RD(x1,y0,z0)*fx)*(1-fy) + (RD(x0,y1,z0)*(1-fx) + RD(x1,y1,z0)*fx)*fy)*(1-fz)
    + ((RD(x0,y0,z1)*(1-fx) + RD(x1,y0,z1)*fx)*(1-fy) + (RD(x0,y1,z1)*(1-fx) + RD(x1,y1,z1)*fx)*fy)*fz;
#undef RD
    g_u1[idx] = v;
}

// ---------------- conv2: grouped 2x(8->8), 3^3, pad 1, on 66^3, z-vec x2, f32x2 packed ----------------
__global__ void conv2_kernel() {
    __shared__ float ws[27*8*16];
    for (int i = threadIdx.x; i < 27*8*16; i += blockDim.x) ws[i] = g_wp2[i];
    __syncthreads();

    int idx = blockIdx.x * blockDim.x + threadIdx.x;
    if (idx >= NB*S*S*33) return;
    int zt = idx % 33;
    int y  = (idx / 33) % S;
    int x  = (idx / (33*S)) % S;
    int n  = idx / (33*S*S);
    int z0 = 2*zt;

    unsigned long long acc2[2][8];
#pragma unroll
    for (int pp = 0; pp < 2; pp++)
#pragma unroll
        for (int i = 0; i < 8; i++) acc2[pp][i] = 0ULL;

    const float* ubase = g_u1 + n*16*S3;
    bool zlo = (zt == 0);
    bool zhi = (zt == 32);

#pragma unroll
    for (int dx = -1; dx <= 1; dx++) {
        int xx = x + dx;
        if ((unsigned)xx >= (unsigned)S) continue;
#pragma unroll
        for (int dy = -1; dy <= 1; dy++) {
            int yy = y + dy;
            if ((unsigned)yy >= (unsigned)S) continue;
            int tap0 = ((dx+1)*3 + (dy+1))*3;
            const float* col = ubase + (xx*S + yy)*S + z0;
#pragma unroll
            for (int icg = 0; icg < 8; icg++) {
                const float* cp = col + icg*S3;
                const float* cv = col + (8+icg)*S3;
                float inp[4], inv[4];
                inp[0] = zlo ? 0.f : cp[-1];  inv[0] = zlo ? 0.f : cv[-1];
                inp[1] = cp[0];               inv[1] = cv[0];
                inp[2] = cp[1];               inv[2] = cv[1];
                inp[3] = zhi ? 0.f : cp[2];   inv[3] = zhi ? 0.f : cv[2];
                unsigned long long ip2[4], iv2[4];
#pragma unroll
                for (int t = 0; t < 4; t++) { ip2[t] = pk2(inp[t], inp[t]); iv2[t] = pk2(inv[t], inv[t]); }
#pragma unroll
                for (int dz = 0; dz < 3; dz++) {
                    const unsigned long long* wp =
                        reinterpret_cast<const unsigned long long*>(ws + (((tap0+dz)*8 + icg) << 4));
                    unsigned long long w0 = wp[0], w1 = wp[1], w2 = wp[2], w3 = wp[3];
                    unsigned long long w4 = wp[4], w5 = wp[5], w6 = wp[6], w7 = wp[7];
#pragma unroll
                    for (int pp = 0; pp < 2; pp++) {
                        unsigned long long vp = ip2[pp+dz];
                        unsigned long long vv = iv2[pp+dz];
                        fma2(acc2[pp][0], vp, w0); fma2(acc2[pp][1], vp, w1);
                        fma2(acc2[pp][2], vp, w2); fma2(acc2[pp][3], vp, w3);
                        fma2(acc2[pp][4], vv, w4); fma2(acc2[pp][5], vv, w5);
                        fma2(acc2[pp][6], vv, w6); fma2(acc2[pp][7], vv, w7);
                    }
                }
            }
        }
    }
    int ob = (x*S + y)*S + z0;
#pragma unroll
    for (int j = 0; j < 8; j++) {
        float lo0, hi0, lo1, hi1;
        upk2(acc2[0][j], lo0, hi0);
        upk2(acc2[1][j], lo1, hi1);
        float2 ve, vo;
        ve.x = lo0; ve.y = lo1;
        vo.x = hi0; vo.y = hi1;
        *reinterpret_cast<float2*>(&g_c2[(n*16 + 2*j    )*S3 + ob]) = ve;
        *reinterpret_cast<float2*>(&g_c2[(n*16 + 2*j + 1)*S3 + ob]) = vo;
    }
}

// ---------------- BN2 + relu + 1x1 heads -> helmholtz (into d_out) ----------------
__global__ void helm_kernel(const float* __restrict__ g2p, const float* __restrict__ b2p,
                            const float* __restrict__ g2v, const float* __restrict__ b2v,
                            const float* __restrict__ pow_, const float* __restrict__ pob,
                            const float* __restrict__ vow,  const float* __restrict__ vob,
                            const float* __restrict__ phiw, const float* __restrict__ vortw,
                            float* __restrict__ out) {
    int idx = blockIdx.x * blockDim.x + threadIdx.x;
    if (idx >= NB*S3) return;
    int p = idx % S3; int n = idx / S3;

    float y[16];
#pragma unroll
    for (int c = 0; c < 16; c++) {
        float mean = g_stat[32 + c], istd = g_stat[48 + c];
        float gg = (c < 8) ? g2p[c] : g2v[c-8];
        float bb = (c < 8) ? b2p[c] : b2v[c-8];
        float v = (g_c2[(n*16 + c)*S3 + p] - mean) * istd * gg + bb;
        y[c] = fmaxf(v, 0.f);
    }
    float ph = pob[0];
#pragma unroll
    for (int c = 0; c < 8; c++) ph += y[c] * pow_[c];
    ph *= phiw[0];
    out[OFF_HELM + (n*4)*S3 + p] = ph;
    float vscale = vortw[0] * 66.f;
#pragma unroll
    for (int r = 0; r < 3; r++) {
        float v = vob[r];
#pragma unroll
        for (int c = 0; c < 8; c++) v += y[8+c] * vow[r*8 + c];
        out[OFF_HELM + (n*4 + 1 + r)*S3 + p] = v * vscale;
    }
}

// ---------------- velocity stencils (into d_out) ----------------
__device__ __forceinline__ float HV(const float* hm, int ch, int x, int y, int z) {
    return hm[ch*S3 + (x*S + y)*S + z];
}

__global__ void vel_kernel(float* __restrict__ out) {
    int idx = blockIdx.x * blockDim.x + threadIdx.x;
    if (idx >= NB*D3) return;
    int p = idx % D3; int n = idx / D3;
    int k = p & 63, j = (p >> 6) & 63, i = p >> 12;
    const float* hm = out + OFF_HELM + n*4*S3;

    float vp0 = 0.5f * (HV(hm,0, 1+i, 1+j, k+2) - HV(hm,0, 1+i, 1+j, k));
    float vp1 = 0.5f * (HV(hm,0, 1+i, j+2, 1+k) - HV(hm,0, 1+i, j,   1+k));
    float vp2 = 0.5f * (HV(hm,0, i+2, 1+j, 1+k) - HV(hm,0, i,   1+j, 1+k));

    float ua = (HV(hm,2, 2+i,1+j,k+1) - HV(hm,2, 1+i,1+j,k+1)) - (HV(hm,1, 1+i,2+j,k+1) - HV(hm,1, 1+i,1+j,k+1));
    float ub = (HV(hm,2, 2+i,1+j,k  ) - HV(hm,2, 1+i,1+j,k  )) - (HV(hm,1, 1+i,2+j,k  ) - HV(hm,1, 1+i,1+j,k  ));
    float vv0 = 0.5f * (ua + ub);
    float va = (HV(hm,1, 1+i,j+1,k+2) - HV(hm,1, 1+i,j+1,k+1)) - (HV(hm,3, i+2,j+1,k+1) - HV(hm,3, i+1,j+1,k+1));
    float vb = (HV(hm,1, 1+i,j,  k+2) - HV(hm,1, 1+i,j,  k+1)) - (HV(hm,3, i+2,j,  k+1) - HV(hm,3, i+1,j,  k+1));
    float vv1 = 0.5f * (va + vb);
    float wa = (HV(hm,3, i+1,j+2,k+1) - HV(hm,3, i+1,j+1,k+1)) - (HV(hm,2, i+1,j+1,k+2) - HV(hm,2, i+1,j+1,k+1));
    float wb = (HV(hm,3, i,  j+2,k+1) - HV(hm,3, i,  j+1,k+1)) - (HV(hm,2, i,  j+1,k+2) - HV(hm,2, i,  j+1,k+1));
    float vv2 = 0.5f * (wa + wb);

    int b = n*3*D3 + p;
    out[OFF_VPHI  + b        ] = vp0;
    out[OFF_VPHI  + b + D3   ] = vp1;
    out[OFF_VPHI  + b + 2*D3 ] = vp2;
    out[OFF_VVORT + b        ] = vv0;
    out[OFF_VVORT + b + D3   ] = vv1;
    out[OFF_VVORT + b + 2*D3 ] = vv2;
    out[OFF_VEL   + b        ] = vp0 + vv0;
    out[OFF_VEL   + b + D3   ] = vp1 + vv1;
    out[OFF_VEL   + b + 2*D3 ] = vp2 + vv2;
}

// ---------------- BFECC advect passes ----------------
__global__ void advect_kernel(const float* __restrict__ ext_src, const float* __restrict__ tex,
                              const float* __restrict__ vel, float sgn, int mode) {
    int idx = blockIdx.x * blockDim.x + threadIdx.x;
    if (idx >= NB*D3) return;
    int p = idx % D3; int n = idx / D3;
    int k = p & 63, j = (p >> 6) & 63, i = p >> 12;

    float v0 = vel[(n*3    )*D3 + p];
    float v1 = vel[(n*3 + 1)*D3 + p];
    float v2 = vel[(n*3 + 2)*D3 + p];
    float px = (float)i - sgn*v2;
    float py = (float)j - sgn*v1;
    float pz = (float)k - sgn*v0;
    px = fminf(fmaxf(px, 0.f), 63.f);
    py = fminf(fmaxf(py, 0.f), 63.f);
    pz = fminf(fmaxf(pz, 0.f), 63.f);
    int x0 = (int)px; float fx = px - x0; int x1 = min(x0+1, 63);
    int y0 = (int)py; float fy = py - y0; int y1 = min(y0+1, 63);
    int z0 = (int)pz; float fz = pz - z0; int z1 = min(z0+1, 63);

    float w000 = (1-fx)*(1-fy)*(1-fz), w001 = (1-fx)*(1-fy)*fz;
    float w010 = (1-fx)*fy*(1-fz),     w011 = (1-fx)*fy*fz;
    float w100 = fx*(1-fy)*(1-fz),     w101 = fx*(1-fy)*fz;
    float w110 = fx*fy*(1-fz),         w111 = fx*fy*fz;

    int b00 = (x0*64 + y0)*64, b01 = (x0*64 + y1)*64;
    int b10 = (x1*64 + y0)*64, b11 = (x1*64 + y1)*64;

    const float* src = (mode == 0) ? ext_src : ((mode == 1) ? g_phi1 : g_comb);
    float* dst = (mode == 0) ? g_phi1 : ((mode == 1) ? g_comb : g_pred);

#pragma unroll
    for (int c = 0; c < 8; c++) {
        const float* s = src + (n*8 + c)*D3;
        float v = w000*s[b00+z0] + w001*s[b00+z1] + w010*s[b01+z0] + w011*s[b01+z1]
                + w100*s[b10+z0] + w101*s[b10+z1] + w110*s[b11+z0] + w111*s[b11+z1];
        if (mode == 1) v = 1.5f * tex[(n*8 + c)*D3 + p] - 0.5f * v;
        dst[(n*8 + c)*D3 + p] = v;
    }
}

// ---------------- LN + FF stage 1 (LN, @W1+b1, exact GELU) ----------------
__global__ void f1_kernel(const float* __restrict__ lng, const float* __restrict__ lnb,
                          const float* __restrict__ w1, const float* __restrict__ b1) {
    __shared__ float W[4096], Bv[64], G[64], Bt[64];
    for (int i = threadIdx.x; i < 4096; i += blockDim.x) W[i] = w1[i];
    if (threadIdx.x < 64) { Bv[threadIdx.x] = b1[threadIdx.x]; G[threadIdx.x] = lng[threadIdx.x]; Bt[threadIdx.x] = lnb[threadIdx.x]; }
    __syncthreads();

    int p = blockIdx.x * blockDim.x + threadIdx.x;
    if (p >= D3) return;
    float h[64]; float s = 0.f, s2 = 0.f;
#pragma unroll
    for (int c = 0; c < 64; c++) { float v = g_pred[c*D3 + p]; h[c] = v; s += v; s2 += v*v; }
    float mean = s * (1.f/64.f);
    float var  = s2 * (1.f/64.f) - mean*mean;
    float is = rsqrtf(var + 1e-5f);
#pragma unroll
    for (int c = 0; c < 64; c++) h[c] = (h[c] - mean) * is * G[c] + Bt[c];

    for (int jj = 0; jj < 64; jj++) {
        float a = Bv[jj];
#pragma unroll
        for (int ii = 0; ii < 64; ii++) a += h[ii] * W[ii*64 + jj];
        float g = 0.5f * a * (1.f + erff(a * 0.70710678118f));
        g_gbuf[jj*D3 + p] = g;
    }
}

// ---------------- FF stage 2 (@W2+b2, residual -> d_out x) ----------------
__global__ void f2_kernel(const float* __restrict__ w2, const float* __restrict__ b2,
                          float* __restrict__ out) {
    __shared__ float W[4096], Bv[64];
    for (int i = threadIdx.x; i < 4096; i += blockDim.x) W[i] = w2[i];
    if (threadIdx.x < 64) Bv[threadIdx.x] = b2[threadIdx.x];
    __syncthreads();

    int p = blockIdx.x * blockDim.x + threadIdx.x;
    if (p >= D3) return;
    float g[64];
#pragma unroll
    for (int c = 0; c < 64; c++) g[c] = g_gbuf[c*D3 + p];
    for (int jj = 0; jj < 64; jj++) {
        float a = Bv[jj];
#pragma unroll
        for (int ii = 0; ii < 64; ii++) a += g[ii] * W[ii*64 + jj];
        out[OFF_X + jj*D3 + p] = g_pred[jj*D3 + p] + a;
    }
}

// ---------------- host launch ----------------
extern "C" void kernel_launch(void* const* d_in, const int* in_sizes, int n_in,
                              void* d_out, int out_size) {
    const float* prev      = (const float*)d_in[0];
    const float* nxt       = (const float*)d_in[1];
    const float* texture   = (const float*)d_in[2];
    const float* mask      = (const float*)d_in[3];
    const float* boundary  = (const float*)d_in[4];
    const float* enc_w     = (const float*)d_in[5];
    const float* enc_b     = (const float*)d_in[6];
    const float* phi_c1_w  = (const float*)d_in[7];
    const float* phi_bn1_g = (const float*)d_in[8];
    const float* phi_bn1_b = (const float*)d_in[9];
    const float* phi_c2_w  = (const float*)d_in[10];
    const float* phi_bn2_g = (const float*)d_in[11];
    const float* phi_bn2_b = (const float*)d_in[12];
    const float* phi_out_w = (const float*)d_in[13];
    const float* phi_out_b = (const float*)d_in[14];
    const float* vort_c1_w = (const float*)d_in[15];
    const float* vort_bn1_g= (const float*)d_in[16];
    const float* vort_bn1_b= (const float*)d_in[17];
    const float* vort_c2_w = (const float*)d_in[18];
    const float* vort_bn2_g= (const float*)d_in[19];
    const float* vort_bn2_b= (const float*)d_in[20];
    const float* vort_out_w= (const float*)d_in[21];
    const float* vort_out_b= (const float*)d_in[22];
    const float* phi_weight= (const float*)d_in[23];
    const float* vort_weight=(const float*)d_in[24];
    const float* ln_g      = (const float*)d_in[25];
    const float* ln_b      = (const float*)d_in[26];
    const float* ff_w1     = (const float*)d_in[27];
    const float* ff_b1     = (const float*)d_in[28];
    const float* ff_w2     = (const float*)d_in[29];
    const float* ff_b2     = (const float*)d_in[30];
    float* out = (float*)d_out;

    pack_kernel<<<(3*WC1_PACK + 255)/256, 256>>>(phi_c1_w, vort_c1_w, phi_c2_w, vort_c2_w);

    int encBlocks = (NB*H3 + 255)/256;
    enc_kernel<<<encBlocks, 256>>>(prev, mask,     enc_w, enc_b, 0);
    enc_kernel<<<encBlocks, 256>>>(prev, boundary, enc_w, enc_b, 1);
    enc_kernel<<<encBlocks, 256>>>(nxt,  mask,     enc_w, enc_b, 2);

    corr_kernel<<<(NB*H3 + 255)/256, 256>>>();

    cudaFuncSetAttribute(conv1_kernel, cudaFuncAttributeMaxDynamicSharedMemorySize, 3*WC1_PACK*4);
    conv1_kernel<<<(NB*H3 + 255)/256, 256, 3*WC1_PACK*4>>>();

    bn_stats_partial<<<dim3(16, 32), 512>>>(0);
    bn_stats_final<<<16, 32>>>(0);

    int upN = NB*16*S3;
    upsample_kernel<<<(upN + 255)/256, 256>>>(phi_bn1_g, phi_bn1_b, vort_bn1_g, vort_bn1_b);

    conv2_kernel<<<(NB*S*S*33 + 255)/256, 256>>>();

    bn_stats_partial<<<dim3(16, 32), 512>>>(1);
    bn_stats_final<<<16, 32>>>(1);

    helm_kernel<<<(NB*S3 + 255)/256, 256>>>(phi_bn2_g, phi_bn2_b, vort_bn2_g, vort_bn2_b,
                                            phi_out_w, phi_out_b, vort_out_w, vort_out_b,
                                            phi_weight, vort_weight, out);

    vel_kernel<<<(NB*D3 + 255)/256, 256>>>(out);

    const float* vel = out + OFF_VEL;
    advect_kernel<<<(NB*D3 + 255)/256, 256>>>(texture, texture, vel,  1.f, 0);
    advect_kernel<<<(NB*D3 + 255)/256, 256>>>(texture, texture, vel, -1.f, 1);
    advect_kernel<<<(NB*D3 + 255)/256, 256>>>(texture, texture, vel,  1.f, 2);

    f1_kernel<<<(D3 + 127)/128, 128>>>(ln_g, ln_b, ff_w1, ff_b1);
    f2_kernel<<<(D3 + 127)/128, 128>>>(ff_w2, ff_b2, out);
}

// round 9
// speedup vs baseline: 1.0959x; 1.0534x over previous
#include <cuda_runtime.h>
#include <math.h>

// ---------------- dimensions ----------------
#define NB 8          // batch*groups
#define S  66
#define S2 4356       // 66*66
#define S3 287496     // 66^3
#define HH 33
#define H2 1089       // 33*33
#define H3 35937      // 33^3
#define D3 262144     // 64^3

// output packing offsets (x, helmholtz, vel, vel_phi, vel_vort)
#define OFF_X     0
#define OFF_HELM  16777216
#define OFF_VEL   25977088
#define OFF_VPHI  32268544
#define OFF_VVORT 38560000

#define WC1_PACK 7776          // 18*27*16
// ---------------- scratch (static device memory; no allocation APIs) ----------------
__device__ float g_f[3][NB*64*H3];     // encoder outputs: pm, pb, nm
__device__ float g_corr[NB*18*H3];     // correlation output (18 distinct channels)
__device__ float g_c1[NB*16*H3];       // conv1 raw out (phi 0-7, vort 8-15)
__device__ float g_u1[NB*16*S3];       // upsampled (post BN1+relu)
__device__ float g_c2[NB*16*S3];       // conv2 raw out
__device__ float g_phi1[64*D3];        // advect pass 1
__device__ float g_comb[64*D3];        // 1.5*tex - 0.5*phi2
__device__ float g_pred[64*D3];        // final advect result
__device__ float g_gbuf[64*D3];        // FF hidden
__device__ float g_wc1[3*WC1_PACK];    // conv1 summed packs: [pack][(tap*18+ic)*16+oc]
__device__ float g_wp2[27*8*16];       // packed conv2 weights [(tap*8+icg)*16+oc]
__device__ float g_stat[64];           // mean1[16], istd1[16], mean2[16], istd2[16]
__device__ double g_part[16*32*2];     // partial reduction sums

// ---------------- packed f32x2 helpers (sm_103a FFMA2 via PTX) ----------------
__device__ __forceinline__ unsigned long long pk2(float a, float b) {
    unsigned long long r;
    asm("mov.b64 %0, {%1, %2};" : "=l"(r) : "f"(a), "f"(b));
    return r;
}
__device__ __forceinline__ void fma2(unsigned long long& d, unsigned long long a, unsigned long long b) {
    asm("fma.rn.f32x2 %0, %1, %2, %0;" : "+l"(d) : "l"(a), "l"(b));
}
__device__ __forceinline__ void upk2(unsigned long long v, float& lo, float& hi) {
    asm("mov.b64 {%0, %1}, %2;" : "=f"(lo), "=f"(hi) : "l"(v));
}

// ---------------- weight packing ----------------
__global__ void pack_kernel(const float* __restrict__ pw1, const float* __restrict__ vw1,
                            const float* __restrict__ pw2, const float* __restrict__ vw2) {
    int i = blockIdx.x * blockDim.x + threadIdx.x;
    if (i < 3*WC1_PACK) {
        int pack = i / WC1_PACK; int r = i % WC1_PACK;
        int oc = r & 15; int t18 = r >> 4; int ic = t18 % 18; int tap = t18 / 18;
        int w = ic / 9, s = ic % 9;
        int c0 = w*27 + s, c1 = c0 + 9, c2 = c0 + 18;
        const float* src = (oc < 8) ? pw1 : vw1;
        int o = (oc < 8) ? oc : oc - 8;
        float W0 = src[(o*54 + c0)*27 + tap];
        float W1 = src[(o*54 + c1)*27 + tap];
        float W2 = src[(o*54 + c2)*27 + tap];
        float v = (pack == 0) ? (W0 + W1 + W2) : ((pack == 1) ? (W0 + W1) : (W1 + W2));
        g_wc1[i] = v;
    }
    if (i < 27*8*16) {
        int oc = i & 15; int icg = (i >> 4) % 8; int t = (i >> 4) / 8;
        g_wp2[i] = (oc < 8) ? pw2[(oc*8 + icg)*27 + t] : vw2[((oc-8)*8 + icg)*27 + t];
    }
}

// ---------------- encoder: conv3d stride 2, kernel 2, input = src*mul, ic-pair f32x2 ----------------
__global__ void enc_kernel(const float* __restrict__ src, const float* __restrict__ mul,
                           const float* __restrict__ w, const float* __restrict__ b, int variant) {
    __shared__ __align__(16) float ws[4096];
    __shared__ float bs[64];
    for (int i = threadIdx.x; i < 4096; i += blockDim.x) ws[i] = w[i];
    if (threadIdx.x < 64) bs[threadIdx.x] = b[threadIdx.x];
    __syncthreads();

    int idx = blockIdx.x * blockDim.x + threadIdx.x;
    if (idx >= NB*H3) return;
    int p = idx % H3;
    int n = idx / H3;
    int z = p % HH, y = (p / HH) % HH, x = p / H2;
    int X = 2*x, Y = 2*y, Z = 2*z;

    float m[8];
#pragma unroll
    for (int t = 0; t < 8; t++) {
        int dx = t >> 2, dy = (t >> 1) & 1, dz = t & 1;
        m[t] = mul[((X+dx)*S + (Y+dy))*S + (Z+dz)];
    }

    // packed input taps: pairs of consecutive flattened index (ic*8 + t)
    unsigned long long xp[32];
#pragma unroll
    for (int ic = 0; ic < 8; ic++) {
        int base = (n*8 + ic)*S3 + (X*S + Y)*S + Z;
#pragma unroll
        for (int th = 0; th < 4; th++) {           // pairs (2*th, 2*th+1)
            int t0 = 2*th, t1 = 2*th + 1;
            int dx0 = t0 >> 2, dy0 = (t0 >> 1) & 1, dz0 = t0 & 1;
            int dx1 = t1 >> 2, dy1 = (t1 >> 1) & 1, dz1 = t1 & 1;
            float v0 = src[base + (dx0*S + dy0)*S + dz0] * m[t0];
            float v1 = src[base + (dx1*S + dy1)*S + dz1] * m[t1];
            xp[ic*4 + th] = pk2(v0, v1);
        }
    }

    float* outp = &g_f[variant][(n*64)*H3 + p];
    for (int oc = 0; oc < 64; oc++) {
        const unsigned long long* wu = reinterpret_cast<const unsigned long long*>(ws + (oc << 6));
        unsigned long long a0 = 0ULL, a1 = 0ULL;
#pragma unroll
        for (int q = 0; q < 32; q += 2) {
            fma2(a0, xp[q],   wu[q]);
            fma2(a1, xp[q+1], wu[q+1]);
        }
        float l0, h0, l1, h1;
        upk2(a0, l0, h0); upk2(a1, l1, h1);
        outp[oc*H3] = bs[oc] + ((l0 + h0) + (l1 + h1));
    }
}

// ---------------- correlation: 18 distinct channels, s-pair f32x2 ----------------
__global__ void corr_kernel() {
    int idx = blockIdx.x * blockDim.x + threadIdx.x;
    if (idx >= NB*H3) return;
    int p = idx % H3; int n = idx / H3;
    int y = (p / HH) % HH, x = p / H2;

    const float* A0 = &g_f[0][n*64*H3 + p];
    const float* A1 = &g_f[1][n*64*H3 + p];
    const float* B  = &g_f[2][n*64*H3 + p];

    int off[9]; bool ok[9];
    {
        int s = 0;
        for (int di = -1; di <= 1; di++)
            for (int dj = -1; dj <= 1; dj++) {
                ok[s] = (x+di >= 0 && x+di < HH && y+dj >= 0 && y+dj < HH);
                off[s] = (di*HH + dj)*HH;
                s++;
            }
    }
    unsigned long long acc2[9];
#pragma unroll
    for (int s = 0; s < 9; s++) acc2[s] = 0ULL;

    for (int c = 0; c < 64; c++) {
        unsigned long long a2 = pk2(A0[c*H3], A1[c*H3]);
        const float* Bc = B + c*H3;
#pragma unroll
        for (int s = 0; s < 9; s++) {
            float bv = ok[s] ? Bc[off[s]] : 0.f;
            fma2(acc2[s], pk2(bv, bv), a2);
        }
    }
#pragma unroll
    for (int s = 0; s < 9; s++) {
        float a, bqq;
        upk2(acc2[s], a, bqq);
        g_corr[(n*18 + s    )*H3 + p] = a   * (1.f/64.f);
        g_corr[(n*18 + 9 + s)*H3 + p] = bqq * (1.f/64.f);
    }
}

// ---------------- conv1: effective 18 -> 16, 3^3, pad 1, on 33^3, f32x2 packed ----------------
__global__ void conv1_kernel() {
    extern __shared__ float ws[];
    for (int i = threadIdx.x; i < 3*WC1_PACK; i += blockDim.x) ws[i] = g_wc1[i];
    __syncthreads();

    int idx = blockIdx.x * blockDim.x + threadIdx.x;
    if (idx >= NB*H3) return;
    int p = idx % H3; int n = idx / H3;
    int z = p % HH, y = (p / HH) % HH, x = p / H2;

    unsigned long long acc2[8];
#pragma unroll
    for (int i = 0; i < 8; i++) acc2[i] = 0ULL;

    const float* cbase = g_corr + n*18*H3;
    for (int tap = 0; tap < 27; tap++) {
        int dx = tap/9 - 1, dy = (tap/3)%3 - 1, dz = tap%3 - 1;
        int xx = x+dx, yy = y+dy, zz = z+dz;
        if ((unsigned)xx >= (unsigned)HH || (unsigned)yy >= (unsigned)HH || (unsigned)zz >= (unsigned)HH) continue;
        int q = (xx*HH + yy)*HH + zz;
        int sel = (zz == 0) ? 1 : ((zz == HH-1) ? 2 : 0);
        const float* wt = ws + sel*WC1_PACK + tap*288;
#pragma unroll
        for (int ic = 0; ic < 18; ic++) {
            float v = cbase[ic*H3 + q];
            unsigned long long v2 = pk2(v, v);
            const unsigned long long* wp = reinterpret_cast<const unsigned long long*>(wt + (ic << 4));
            fma2(acc2[0], v2, wp[0]); fma2(acc2[1], v2, wp[1]);
            fma2(acc2[2], v2, wp[2]); fma2(acc2[3], v2, wp[3]);
            fma2(acc2[4], v2, wp[4]); fma2(acc2[5], v2, wp[5]);
            fma2(acc2[6], v2, wp[6]); fma2(acc2[7], v2, wp[7]);
        }
    }
#pragma unroll
    for (int j = 0; j < 8; j++) {
        float lo, hi;
        upk2(acc2[j], lo, hi);
        g_c1[(n*16 + 2*j    )*H3 + p] = lo;
        g_c1[(n*16 + 2*j + 1)*H3 + p] = hi;
    }
}

// ---------------- BN stats (two-stage deterministic) ----------------
__global__ void bn_stats_partial(int phase) {
    const float* src = phase ? g_c2 : g_c1;
    int spatial = phase ? S3 : H3;
    int total = NB * spatial;
    int ch = blockIdx.x, sl = blockIdx.y;
    double s = 0.0, s2 = 0.0;
    for (int i = sl*blockDim.x + threadIdx.x; i < total; i += 32*blockDim.x) {
        int n = i / spatial, p = i % spatial;
        float v = src[(n*16 + ch)*spatial + p];
        s += v; s2 += (double)v * v;
    }
    __shared__ double sh[512], sh2[512];
    sh[threadIdx.x] = s; sh2[threadIdx.x] = s2;
    __syncthreads();
    for (int st = 256; st > 0; st >>= 1) {
        if (threadIdx.x < st) { sh[threadIdx.x] += sh[threadIdx.x+st]; sh2[threadIdx.x] += sh2[threadIdx.x+st]; }
        __syncthreads();
    }
    if (threadIdx.x == 0) {
        g_part[(ch*32 + sl)*2 + 0] = sh[0];
        g_part[(ch*32 + sl)*2 + 1] = sh2[0];
    }
}

__global__ void bn_stats_final(int phase) {
    int ch = blockIdx.x;
    if (threadIdx.x != 0) return;
    int spatial = phase ? S3 : H3;
    double total = (double)NB * spatial;
    double s = 0.0, s2 = 0.0;
    for (int i = 0; i < 32; i++) { s += g_part[(ch*32+i)*2]; s2 += g_part[(ch*32+i)*2+1]; }
    double mean = s / total;
    double var = s2 / total - mean*mean;
    g_stat[phase*32 + ch]      = (float)mean;
    g_stat[phase*32 + 16 + ch] = (float)(1.0 / sqrt(var + 1e-5));
}

// ---------------- BN1 + relu + trilinear upsample x2 (align_corners) ----------------
__device__ __forceinline__ float bnrelu(float v, float sc, float sh) { return fmaxf(v*sc + sh, 0.f); }

__global__ void upsample_kernel(const float* __restrict__ g1p, const float* __restrict__ b1p,
                                const float* __restrict__ g1v, const float* __restrict__ b1v) {
    int idx = blockIdx.x * blockDim.x + threadIdx.x;
    if (idx >= NB*16*S3) return;
    int p = idx % S3; int ch = (idx / S3) % 16; int n = idx / (16*S3);
    int Z = p % S, Y = (p / S) % S, X = p / S2;

    float mean = g_stat[ch], istd = g_stat[16 + ch];
    float gg = (ch < 8) ? g1p[ch] : g1v[ch-8];
    float bb = (ch < 8) ? b1p[ch] : b1v[ch-8];
    float sc = istd * gg, sh = bb - mean * sc;

    const float SC = 32.f / 65.f;
    float sx = X * SC; int x0 = (int)sx; float fx = sx - x0; int x1 = min(x0+1, 32);
    float sy = Y * SC; int y0 = (int)sy; float fy = sy - y0; int y1 = min(y0+1, 32);
    float sz = Z * SC; int z0 = (int)sz; float fz = sz - z0; int z1 = min(z0+1, 32);

    const float* base = g_c1 + (n*16 + ch)*H3;
#define RD(xi,yi,zi) bnrelu(base[((xi)*HH+(yi))*HH+(zi)], sc, sh)
    float v =
      ((RD(x0,y0,z0)*(1-fx) + RD(x1,y0,z0)*fx)*(1-fy) + (RD(x0,y1,z0)*(1-fx) + RD(x1,y1,z0)*fx)*fy)*(1-fz)
    + ((RD(x0,y0,z1)*(1-fx) + RD(x1,y0,z1)*fx)*(1-fy) + (RD(x0,y1,z1)*(1-fx) + RD(x1,y1,z1)*fx)*fy)*fz;
#undef RD
    g_u1[idx] = v;
}

// ---------------- conv2: grouped 2x(8->8), 3^3, pad 1, on 66^3, z-vec x3, f32x2 packed ----------------
__global__ void conv2_kernel() {
    __shared__ __align__(16) float ws[27*8*16];
    for (int i = threadIdx.x; i < 27*8*16; i += blockDim.x) ws[i] = g_wp2[i];
    __syncthreads();

    int idx = blockIdx.x * blockDim.x + threadIdx.x;
    if (idx >= NB*S*S*22) return;
    int zt = idx % 22;
    int y  = (idx / 22) % S;
    int x  = (idx / (22*S)) % S;
    int n  = idx / (22*S*S);
    int z0 = 3*zt;

    unsigned long long acc2[3][8];
#pragma unroll
    for (int pp = 0; pp < 3; pp++)
#pragma unroll
        for (int i = 0; i < 8; i++) acc2[pp][i] = 0ULL;

    const float* ubase = g_u1 + n*16*S3;
    bool zlo = (zt == 0);    // window idx 0 (z0-1) invalid
    bool zhi = (zt == 21);   // window idx 4 (z0+3 == 66) invalid

#pragma unroll
    for (int dx = -1; dx <= 1; dx++) {
        int xx = x + dx;
        if ((unsigned)xx >= (unsigned)S) continue;
#pragma unroll
        for (int dy = -1; dy <= 1; dy++) {
            int yy = y + dy;
            if ((unsigned)yy >= (unsigned)S) continue;
            int tap0 = ((dx+1)*3 + (dy+1))*3;
            const float* col = ubase + (xx*S + yy)*S + z0;
#pragma unroll
            for (int icg = 0; icg < 8; icg++) {
                const float* cp = col + icg*S3;
                const float* cv = col + (8+icg)*S3;
                float inp[5], inv[5];
                inp[0] = zlo ? 0.f : cp[-1];  inv[0] = zlo ? 0.f : cv[-1];
                inp[1] = cp[0];               inv[1] = cv[0];
                inp[2] = cp[1];               inv[2] = cv[1];
                inp[3] = cp[2];               inv[3] = cv[2];
                inp[4] = zhi ? 0.f : cp[3];   inv[4] = zhi ? 0.f : cv[3];
                unsigned long long ip2[5], iv2[5];
#pragma unroll
                for (int t = 0; t < 5; t++) { ip2[t] = pk2(inp[t], inp[t]); iv2[t] = pk2(inv[t], inv[t]); }
#pragma unroll
                for (int dz = 0; dz < 3; dz++) {
                    const unsigned long long* wp =
                        reinterpret_cast<const unsigned long long*>(ws + (((tap0+dz)*8 + icg) << 4));
                    unsigned long long w0 = wp[0], w1 = wp[1], w2 = wp[2], w3 = wp[3];
                    unsigned long long w4 = wp[4], w5 = wp[5], w6 = wp[6], w7 = wp[7];
#pragma unroll
                    for (int pp = 0; pp < 3; pp++) {
                        unsigned long long vp = ip2[pp+dz];
                        unsigned long long vv = iv2[pp+dz];
                        fma2(acc2[pp][0], vp, w0); fma2(acc2[pp][1], vp, w1);
                        fma2(acc2[pp][2], vp, w2); fma2(acc2[pp][3], vp, w3);
                        fma2(acc2[pp][4], vv, w4); fma2(acc2[pp][5], vv, w5);
                        fma2(acc2[pp][6], vv, w6); fma2(acc2[pp][7], vv, w7);
                    }
                }
            }
        }
    }
    int ob = (x*S + y)*S + z0;
#pragma unroll
    for (int j = 0; j < 8; j++) {
#pragma unroll
        for (int pp = 0; pp < 3; pp++) {
            float lo, hi;
            upk2(acc2[pp][j], lo, hi);
            g_c2[(n*16 + 2*j    )*S3 + ob + pp] = lo;
            g_c2[(n*16 + 2*j + 1)*S3 + ob + pp] = hi;
        }
    }
}

// ---------------- BN2 + relu + 1x1 heads -> helmholtz (into d_out) ----------------
__global__ void helm_kernel(const float* __restrict__ g2p, const float* __restrict__ b2p,
                            const float* __restrict__ g2v, const float* __restrict__ b2v,
                            const float* __restrict__ pow_, const float* __restrict__ pob,
                            const float* __restrict__ vow,  const float* __restrict__ vob,
                            const float* __restrict__ phiw, const float* __restrict__ vortw,
                            float* __restrict__ out) {
    int idx = blockIdx.x * blockDim.x + threadIdx.x;
    if (idx >= NB*S3) return;
    int p = idx % S3; int n = idx / S3;

    float y[16];
#pragma unroll
    for (int c = 0; c < 16; c++) {
        float mean = g_stat[32 + c], istd = g_stat[48 + c];
        float gg = (c < 8) ? g2p[c] : g2v[c-8];
        float bb = (c < 8) ? b2p[c] : b2v[c-8];
        float v = (g_c2[(n*16 + c)*S3 + p] - mean) * istd * gg + bb;
        y[c] = fmaxf(v, 0.f);
    }
    float ph = pob[0];
#pragma unroll
    for (int c = 0; c < 8; c++) ph += y[c] * pow_[c];
    ph *= phiw[0];
    out[OFF_HELM + (n*4)*S3 + p] = ph;
    float vscale = vortw[0] * 66.f;
#pragma unroll
    for (int r = 0; r < 3; r++) {
        float v = vob[r];
#pragma unroll
        for (int c = 0; c < 8; c++) v += y[8+c] * vow[r*8 + c];
        out[OFF_HELM + (n*4 + 1 + r)*S3 + p] = v * vscale;
    }
}

// ---------------- velocity stencils (into d_out) ----------------
__device__ __forceinline__ float HV(const float* hm, int ch, int x, int y, int z) {
    return hm[ch*S3 + (x*S + y)*S + z];
}

__global__ void vel_kernel(float* __restrict__ out) {
    int idx = blockIdx.x * blockDim.x + threadIdx.x;
    if (idx >= NB*D3) return;
    int p = idx % D3; int n = idx / D3;
    int k = p & 63, j = (p >> 6) & 63, i = p >> 12;
    const float* hm = out + OFF_HELM + n*4*S3;

    float vp0 = 0.5f * (HV(hm,0, 1+i, 1+j, k+2) - HV(hm,0, 1+i, 1+j, k));
    float vp1 = 0.5f * (HV(hm,0, 1+i, j+2, 1+k) - HV(hm,0, 1+i, j,   1+k));
    float vp2 = 0.5f * (HV(hm,0, i+2, 1+j, 1+k) - HV(hm,0, i,   1+j, 1+k));

    float ua = (HV(hm,2, 2+i,1+j,k+1) - HV(hm,2, 1+i,1+j,k+1)) - (HV(hm,1, 1+i,2+j,k+1) - HV(hm,1, 1+i,1+j,k+1));
    float ub = (HV(hm,2, 2+i,1+j,k  ) - HV(hm,2, 1+i,1+j,k  )) - (HV(hm,1, 1+i,2+j,k  ) - HV(hm,1, 1+i,1+j,k  ));
    float vv0 = 0.5f * (ua + ub);
    float va = (HV(hm,1, 1+i,j+1,k+2) - HV(hm,1, 1+i,j+1,k+1)) - (HV(hm,3, i+2,j+1,k+1) - HV(hm,3, i+1,j+1,k+1));
    float vb = (HV(hm,1, 1+i,j,  k+2) - HV(hm,1, 1+i,j,  k+1)) - (HV(hm,3, i+2,j,  k+1) - HV(hm,3, i+1,j,  k+1));
    float vv1 = 0.5f * (va + vb);
    float wa = (HV(hm,3, i+1,j+2,k+1) - HV(hm,3, i+1,j+1,k+1)) - (HV(hm,2, i+1,j+1,k+2) - HV(hm,2, i+1,j+1,k+1));
    float wb = (HV(hm,3, i,  j+2,k+1) - HV(hm,3, i,  j+1,k+1)) - (HV(hm,2, i,  j+1,k+2) - HV(hm,2, i,  j+1,k+1));
    float vv2 = 0.5f * (wa + wb);

    int b = n*3*D3 + p;
    out[OFF_VPHI  + b        ] = vp0;
    out[OFF_VPHI  + b + D3   ] = vp1;
    out[OFF_VPHI  + b + 2*D3 ] = vp2;
    out[OFF_VVORT + b        ] = vv0;
    out[OFF_VVORT + b + D3   ] = vv1;
    out[OFF_VVORT + b + 2*D3 ] = vv2;
    out[OFF_VEL   + b        ] = vp0 + vv0;
    out[OFF_VEL   + b + D3   ] = vp1 + vv1;
    out[OFF_VEL   + b + 2*D3 ] = vp2 + vv2;
}

// ---------------- BFECC advect passes ----------------
__global__ void advect_kernel(const float* __restrict__ ext_src, const float* __restrict__ tex,
                              const float* __restrict__ vel, float sgn, int mode) {
    int idx = blockIdx.x * blockDim.x + threadIdx.x;
    if (idx >= NB*D3) return;
    int p = idx % D3; int n = idx / D3;
    int k = p & 63, j = (p >> 6) & 63, i = p >> 12;

    float v0 = vel[(n*3    )*D3 + p];
    float v1 = vel[(n*3 + 1)*D3 + p];
    float v2 = vel[(n*3 + 2)*D3 + p];
    float px = (float)i - sgn*v2;
    float py = (float)j - sgn*v1;
    float pz = (float)k - sgn*v0;
    px = fminf(fmaxf(px, 0.f), 63.f);
    py = fminf(fmaxf(py, 0.f), 63.f);
    pz = fminf(fmaxf(pz, 0.f), 63.f);
    int x0 = (int)px; float fx = px - x0; int x1 = min(x0+1, 63);
    int y0 = (int)py; float fy = py - y0; int y1 = min(y0+1, 63);
    int z0 = (int)pz; float fz = pz - z0; int z1 = min(z0+1, 63);

    float w000 = (1-fx)*(1-fy)*(1-fz), w001 = (1-fx)*(1-fy)*fz;
    float w010 = (1-fx)*fy*(1-fz),     w011 = (1-fx)*fy*fz;
    float w100 = fx*(1-fy)*(1-fz),     w101 = fx*(1-fy)*fz;
    float w110 = fx*fy*(1-fz),         w111 = fx*fy*fz;

    int b00 = (x0*64 + y0)*64, b01 = (x0*64 + y1)*64;
    int b10 = (x1*64 + y0)*64, b11 = (x1*64 + y1)*64;

    const float* src = (mode == 0) ? ext_src : ((mode == 1) ? g_phi1 : g_comb);
    float* dst = (mode == 0) ? g_phi1 : ((mode == 1) ? g_comb : g_pred);

#pragma unroll
    for (int c = 0; c < 8; c++) {
        const float* s = src + (n*8 + c)*D3;
        float v = w000*s[b00+z0] + w001*s[b00+z1] + w010*s[b01+z0] + w011*s[b01+z1]
                + w100*s[b10+z0] + w101*s[b10+z1] + w110*s[b11+z0] + w111*s[b11+z1];
        if (mode == 1) v = 1.5f * tex[(n*8 + c)*D3 + p] - 0.5f * v;
        dst[(n*8 + c)*D3 + p] = v;
    }
}

// ---------------- LN + FF stage 1 (LN, @W1+b1, exact GELU), ii-pair f32x2 ----------------
__global__ void f1_kernel(const float* __restrict__ lng, const float* __restrict__ lnb,
                          const float* __restrict__ w1, const float* __restrict__ b1) {
    __shared__ unsigned long long Wp[2048];   // Wp[jj*32+q] = (W[2q][jj], W[2q+1][jj])
    __shared__ float Bv[64], G[64], Bt[64];
    float* fW = reinterpret_cast<float*>(Wp);
    for (int i = threadIdx.x; i < 4096; i += blockDim.x) {
        int ii = i >> 6, jj = i & 63;
        fW[(jj*32 + (ii >> 1))*2 + (ii & 1)] = w1[i];
    }
    if (threadIdx.x < 64) { Bv[threadIdx.x] = b1[threadIdx.x]; G[threadIdx.x] = lng[threadIdx.x]; Bt[threadIdx.x] = lnb[threadIdx.x]; }
    __syncthreads();

    int p = blockIdx.x * blockDim.x + threadIdx.x;
    if (p >= D3) return;
    float h[64]; float s = 0.f, s2 = 0.f;
#pragma unroll
    for (int c = 0; c < 64; c++) { float v = g_pred[c*D3 + p]; h[c] = v; s += v; s2 += v*v; }
    float mean = s * (1.f/64.f);
    float var  = s2 * (1.f/64.f) - mean*mean;
    float is = rsqrtf(var + 1e-5f);
    unsigned long long hp[32];
#pragma unroll
    for (int c = 0; c < 32; c++) {
        float e = (h[2*c]   - mean) * is * G[2*c]   + Bt[2*c];
        float o = (h[2*c+1] - mean) * is * G[2*c+1] + Bt[2*c+1];
        hp[c] = pk2(e, o);
    }

    for (int jj = 0; jj < 64; jj++) {
        const unsigned long long* wr = Wp + jj*32;
        unsigned long long a0 = 0ULL, a1 = 0ULL;
#pragma unroll
        for (int q = 0; q < 32; q += 2) {
            fma2(a0, hp[q],   wr[q]);
            fma2(a1, hp[q+1], wr[q+1]);
        }
        float l0, h0, l1, h1;
        upk2(a0, l0, h0); upk2(a1, l1, h1);
        float a = Bv[jj] + ((l0 + h0) + (l1 + h1));
        g_gbuf[jj*D3 + p] = 0.5f * a * (1.f + erff(a * 0.70710678118f));
    }
}

// ---------------- FF stage 2 (@W2+b2, residual -> d_out x), ii-pair f32x2 ----------------
__global__ void f2_kernel(const float* __restrict__ w2, const float* __restrict__ b2,
                          float* __restrict__ out) {
    __shared__ unsigned long long Wp[2048];
    __shared__ float Bv[64];
    float* fW = reinterpret_cast<float*>(Wp);
    for (int i = threadIdx.x; i < 4096; i += blockDim.x) {
        int ii = i >> 6, jj = i & 63;
        fW[(jj*32 + (ii >> 1))*2 + (ii & 1)] = w2[i];
    }
    if (threadIdx.x < 64) Bv[threadIdx.x] = b2[threadIdx.x];
    __syncthreads();

    int p = blockIdx.x * blockDim.x + threadIdx.x;
    if (p >= D3) return;
    unsigned long long gp[32];
#pragma unroll
    for (int c = 0; c < 32; c++)
        gp[c] = pk2(g_gbuf[(2*c)*D3 + p], g_gbuf[(2*c+1)*D3 + p]);

    for (int jj = 0; jj < 64; jj++) {
        const unsigned long long* wr = Wp + jj*32;
        unsigned long long a0 = 0ULL, a1 = 0ULL;
#pragma unroll
        for (int q = 0; q < 32; q += 2) {
            fma2(a0, gp[q],   wr[q]);
            fma2(a1, gp[q+1], wr[q+1]);
        }
        float l0, h0, l1, h1;
        upk2(a0, l0, h0); upk2(a1, l1, h1);
        float a = Bv[jj] + ((l0 + h0) + (l1 + h1));
        out[OFF_X + jj*D3 + p] = g_pred[jj*D3 + p] + a;
    }
}

// ---------------- host launch ----------------
extern "C" void kernel_launch(void* const* d_in, const int* in_sizes, int n_in,
                              void* d_out, int out_size) {
    const float* prev      = (const float*)d_in[0];
    const float* nxt       = (const float*)d_in[1];
    const float* texture   = (const float*)d_in[2];
    const float* mask      = (const float*)d_in[3];
    const float* boundary  = (const float*)d_in[4];
    const float* enc_w     = (const float*)d_in[5];
    const float* enc_b     = (const float*)d_in[6];
    const float* phi_c1_w  = (const float*)d_in[7];
    const float* phi_bn1_g = (const float*)d_in[8];
    const float* phi_bn1_b = (const float*)d_in[9];
    const float* phi_c2_w  = (const float*)d_in[10];
    const float* phi_bn2_g = (const float*)d_in[11];
    const float* phi_bn2_b = (const float*)d_in[12];
    const float* phi_out_w = (const float*)d_in[13];
    const float* phi_out_b = (const float*)d_in[14];
    const float* vort_c1_w = (const float*)d_in[15];
    const float* vort_bn1_g= (const float*)d_in[16];
    const float* vort_bn1_b= (const float*)d_in[17];
    const float* vort_c2_w = (const float*)d_in[18];
    const float* vort_bn2_g= (const float*)d_in[19];
    const float* vort_bn2_b= (const float*)d_in[20];
    const float* vort_out_w= (const float*)d_in[21];
    const float* vort_out_b= (const float*)d_in[22];
    const float* phi_weight= (const float*)d_in[23];
    const float* vort_weight=(const float*)d_in[24];
    const float* ln_g      = (const float*)d_in[25];
    const float* ln_b      = (const float*)d_in[26];
    const float* ff_w1     = (const float*)d_in[27];
    const float* ff_b1     = (const float*)d_in[28];
    const float* ff_w2     = (const float*)d_in[29];
    const float* ff_b2     = (const float*)d_in[30];
    float* out = (float*)d_out;

    pack_kernel<<<(3*WC1_PACK + 255)/256, 256>>>(phi_c1_w, vort_c1_w, phi_c2_w, vort_c2_w);

    int encBlocks = (NB*H3 + 255)/256;
    enc_kernel<<<encBlocks, 256>>>(prev, mask,     enc_w, enc_b, 0);
    enc_kernel<<<encBlocks, 256>>>(prev, boundary, enc_w, enc_b, 1);
    enc_kernel<<<encBlocks, 256>>>(nxt,  mask,     enc_w, enc_b, 2);

    corr_kernel<<<(NB*H3 + 255)/256, 256>>>();

    cudaFuncSetAttribute(conv1_kernel, cudaFuncAttributeMaxDynamicSharedMemorySize, 3*WC1_PACK*4);
    conv1_kernel<<<(NB*H3 + 255)/256, 256, 3*WC1_PACK*4>>>();

    bn_stats_partial<<<dim3(16, 32), 512>>>(0);
    bn_stats_final<<<16, 32>>>(0);

    int upN = NB*16*S3;
    upsample_kernel<<<(upN + 255)/256, 256>>>(phi_bn1_g, phi_bn1_b, vort_bn1_g, vort_bn1_b);

    conv2_kernel<<<(NB*S*S*22 + 255)/256, 256>>>();

    bn_stats_partial<<<dim3(16, 32), 512>>>(1);
    bn_stats_final<<<16, 32>>>(1);

    helm_kernel<<<(NB*S3 + 255)/256, 256>>>(phi_bn2_g, phi_bn2_b, vort_bn2_g, vort_bn2_b,
                                            phi_out_w, phi_out_b, vort_out_w, vort_out_b,
                                            phi_weight, vort_weight, out);

    vel_kernel<<<(NB*D3 + 255)/256, 256>>>(out);

    const float* vel = out + OFF_VEL;
    advect_kernel<<<(NB*D3 + 255)/256, 256>>>(texture, texture, vel,  1.f, 0);
    advect_kernel<<<(NB*D3 + 255)/256, 256>>>(texture, texture, vel, -1.f, 1);
    advect_kernel<<<(NB*D3 + 255)/256, 256>>>(texture, texture, vel,  1.f, 2);

    f1_kernel<<<(D3 + 127)/128, 128>>>(ln_g, ln_b, ff_w1, ff_b1);
    f2_kernel<<<(D3 + 127)/128, 128>>>(ff_w2, ff_b2, out);
}

// round 11
// speedup vs baseline: 1.1163x; 1.0186x over previous
#include <cuda_runtime.h>
#include <math.h>

// ---------------- dimensions ----------------
#define NB 8          // batch*groups
#define S  66
#define S2 4356       // 66*66
#define S3 287496     // 66^3
#define HH 33
#define H2 1089       // 33*33
#define H3 35937      // 33^3
#define D3 262144     // 64^3

// output packing offsets (x, helmholtz, vel, vel_phi, vel_vort)
#define OFF_X     0
#define OFF_HELM  16777216
#define OFF_VEL   25977088
#define OFF_VPHI  32268544
#define OFF_VVORT 38560000

#define WC1_PACK 7776          // 18*27*16
// ---------------- scratch (static device memory; no allocation APIs) ----------------
__device__ float g_f[3][NB*64*H3];     // encoder outputs: pm, pb, nm
__device__ float g_corr[NB*18*H3];     // correlation output (18 distinct channels)
__device__ float g_c1[NB*16*H3];       // conv1 raw out (phi 0-7, vort 8-15)
__device__ float g_u1[NB*16*S3];       // upsampled (post BN1+relu)
__device__ float g_c2[NB*16*S3];       // conv2 raw out
__device__ float g_phi1[64*D3];        // advect pass 1
__device__ float g_comb[64*D3];        // 1.5*tex - 0.5*phi2
__device__ float g_pred[64*D3];        // final advect result
__device__ float g_wc1[3*WC1_PACK];    // conv1 summed packs: [pack][(tap*18+ic)*16+oc]
__device__ float g_wp2[27*8*16];       // packed conv2 weights [(tap*8+icg)*16+oc]
__device__ float g_stat[64];           // mean1[16], istd1[16], mean2[16], istd2[16]
__device__ double g_part[16*32*2];     // partial reduction sums

// ---------------- packed f32x2 helpers (sm_103a FFMA2 via PTX) ----------------
__device__ __forceinline__ unsigned long long pk2(float a, float b) {
    unsigned long long r;
    asm("mov.b64 %0, {%1, %2};" : "=l"(r) : "f"(a), "f"(b));
    return r;
}
__device__ __forceinline__ void fma2(unsigned long long& d, unsigned long long a, unsigned long long b) {
    asm("fma.rn.f32x2 %0, %1, %2, %0;" : "+l"(d) : "l"(a), "l"(b));
}
__device__ __forceinline__ void upk2(unsigned long long v, float& lo, float& hi) {
    asm("mov.b64 {%0, %1}, %2;" : "=f"(lo), "=f"(hi) : "l"(v));
}

// ---------------- weight packing ----------------
__global__ void pack_kernel(const float* __restrict__ pw1, const float* __restrict__ vw1,
                            const float* __restrict__ pw2, const float* __restrict__ vw2) {
    int i = blockIdx.x * blockDim.x + threadIdx.x;
    if (i < 3*WC1_PACK) {
        int pack = i / WC1_PACK; int r = i % WC1_PACK;
        int oc = r & 15; int t18 = r >> 4; int ic = t18 % 18; int tap = t18 / 18;
        int w = ic / 9, s = ic % 9;
        int c0 = w*27 + s, c1 = c0 + 9, c2 = c0 + 18;
        const float* src = (oc < 8) ? pw1 : vw1;
        int o = (oc < 8) ? oc : oc - 8;
        float W0 = src[(o*54 + c0)*27 + tap];
        float W1 = src[(o*54 + c1)*27 + tap];
        float W2 = src[(o*54 + c2)*27 + tap];
        float v = (pack == 0) ? (W0 + W1 + W2) : ((pack == 1) ? (W0 + W1) : (W1 + W2));
        g_wc1[i] = v;
    }
    if (i < 27*8*16) {
        int oc = i & 15; int icg = (i >> 4) % 8; int t = (i >> 4) / 8;
        g_wp2[i] = (oc < 8) ? pw2[(oc*8 + icg)*27 + t] : vw2[((oc-8)*8 + icg)*27 + t];
    }
}

// ---------------- encoder: conv3d stride 2, kernel 2, input = src*mul, ic-pair f32x2, LDS.128 ----------------
__global__ void enc_kernel(const float* __restrict__ src, const float* __restrict__ mul,
                           const float* __restrict__ w, const float* __restrict__ b, int variant) {
    __shared__ __align__(16) float ws[4096];
    __shared__ float bs[64];
    for (int i = threadIdx.x; i < 4096; i += blockDim.x) ws[i] = w[i];
    if (threadIdx.x < 64) bs[threadIdx.x] = b[threadIdx.x];
    __syncthreads();

    int idx = blockIdx.x * blockDim.x + threadIdx.x;
    if (idx >= NB*H3) return;
    int p = idx % H3;
    int n = idx / H3;
    int z = p % HH, y = (p / HH) % HH, x = p / H2;
    int X = 2*x, Y = 2*y, Z = 2*z;

    float m[8];
#pragma unroll
    for (int t = 0; t < 8; t++) {
        int dx = t >> 2, dy = (t >> 1) & 1, dz = t & 1;
        m[t] = mul[((X+dx)*S + (Y+dy))*S + (Z+dz)];
    }

    unsigned long long xp[32];
#pragma unroll
    for (int ic = 0; ic < 8; ic++) {
        int base = (n*8 + ic)*S3 + (X*S + Y)*S + Z;
#pragma unroll
        for (int th = 0; th < 4; th++) {
            int t0 = 2*th, t1 = 2*th + 1;
            int dx0 = t0 >> 2, dy0 = (t0 >> 1) & 1, dz0 = t0 & 1;
            int dx1 = t1 >> 2, dy1 = (t1 >> 1) & 1, dz1 = t1 & 1;
            float v0 = src[base + (dx0*S + dy0)*S + dz0] * m[t0];
            float v1 = src[base + (dx1*S + dy1)*S + dz1] * m[t1];
            xp[ic*4 + th] = pk2(v0, v1);
        }
    }

    float* outp = &g_f[variant][(n*64)*H3 + p];
    for (int oc = 0; oc < 64; oc++) {
        const ulonglong2* wu = reinterpret_cast<const ulonglong2*>(ws + (oc << 6));
        unsigned long long a0 = 0ULL, a1 = 0ULL;
#pragma unroll
        for (int q = 0; q < 16; q++) {
            ulonglong2 w2v = wu[q];
            fma2(a0, xp[2*q],   w2v.x);
            fma2(a1, xp[2*q+1], w2v.y);
        }
        float l0, h0, l1, h1;
        upk2(a0, l0, h0); upk2(a1, l1, h1);
        outp[oc*H3] = bs[oc] + ((l0 + h0) + (l1 + h1));
    }
}

// ---------------- correlation: 18 distinct channels, s-pair f32x2 ----------------
__global__ void corr_kernel() {
    int idx = blockIdx.x * blockDim.x + threadIdx.x;
    if (idx >= NB*H3) return;
    int p = idx % H3; int n = idx / H3;
    int y = (p / HH) % HH, x = p / H2;

    const float* A0 = &g_f[0][n*64*H3 + p];
    const float* A1 = &g_f[1][n*64*H3 + p];
    const float* B  = &g_f[2][n*64*H3 + p];

    int off[9]; bool ok[9];
    {
        int s = 0;
        for (int di = -1; di <= 1; di++)
            for (int dj = -1; dj <= 1; dj++) {
                ok[s] = (x+di >= 0 && x+di < HH && y+dj >= 0 && y+dj < HH);
                off[s] = (di*HH + dj)*HH;
                s++;
            }
    }
    unsigned long long acc2[9];
#pragma unroll
    for (int s = 0; s < 9; s++) acc2[s] = 0ULL;

    for (int c = 0; c < 64; c++) {
        unsigned long long a2 = pk2(A0[c*H3], A1[c*H3]);
        const float* Bc = B + c*H3;
#pragma unroll
        for (int s = 0; s < 9; s++) {
            float bv = ok[s] ? Bc[off[s]] : 0.f;
            fma2(acc2[s], pk2(bv, bv), a2);
        }
    }
#pragma unroll
    for (int s = 0; s < 9; s++) {
        float a, bqq;
        upk2(acc2[s], a, bqq);
        g_corr[(n*18 + s    )*H3 + p] = a   * (1.f/64.f);
        g_corr[(n*18 + 9 + s)*H3 + p] = bqq * (1.f/64.f);
    }
}

// ---------------- conv1: effective 18 -> 16, 3^3, pad 1, on 33^3, f32x2 + LDS.128 ----------------
__global__ void conv1_kernel() {
    extern __shared__ float ws[];
    for (int i = threadIdx.x; i < 3*WC1_PACK; i += blockDim.x) ws[i] = g_wc1[i];
    __syncthreads();

    int idx = blockIdx.x * blockDim.x + threadIdx.x;
    if (idx >= NB*H3) return;
    int p = idx % H3; int n = idx / H3;
    int z = p % HH, y = (p / HH) % HH, x = p / H2;

    unsigned long long acc2[8];
#pragma unroll
    for (int i = 0; i < 8; i++) acc2[i] = 0ULL;

    const float* cbase = g_corr + n*18*H3;
    for (int tap = 0; tap < 27; tap++) {
        int dx = tap/9 - 1, dy = (tap/3)%3 - 1, dz = tap%3 - 1;
        int xx = x+dx, yy = y+dy, zz = z+dz;
        if ((unsigned)xx >= (unsigned)HH || (unsigned)yy >= (unsigned)HH || (unsigned)zz >= (unsigned)HH) continue;
        int q = (xx*HH + yy)*HH + zz;
        int sel = (zz == 0) ? 1 : ((zz == HH-1) ? 2 : 0);
        const float* wt = ws + sel*WC1_PACK + tap*288;
#pragma unroll
        for (int ic = 0; ic < 18; ic++) {
            float v = cbase[ic*H3 + q];
            unsigned long long v2 = pk2(v, v);
            const ulonglong2* wp = reinterpret_cast<const ulonglong2*>(wt + (ic << 4));
            ulonglong2 w01 = wp[0], w23 = wp[1], w45 = wp[2], w67 = wp[3];
            fma2(acc2[0], v2, w01.x); fma2(acc2[1], v2, w01.y);
            fma2(acc2[2], v2, w23.x); fma2(acc2[3], v2, w23.y);
            fma2(acc2[4], v2, w45.x); fma2(acc2[5], v2, w45.y);
            fma2(acc2[6], v2, w67.x); fma2(acc2[7], v2, w67.y);
        }
    }
#pragma unroll
    for (int j = 0; j < 8; j++) {
        float lo, hi;
        upk2(acc2[j], lo, hi);
        g_c1[(n*16 + 2*j    )*H3 + p] = lo;
        g_c1[(n*16 + 2*j + 1)*H3 + p] = hi;
    }
}

// ---------------- BN stats (two-stage deterministic) ----------------
__global__ void bn_stats_partial(int phase) {
    const float* src = phase ? g_c2 : g_c1;
    int spatial = phase ? S3 : H3;
    int total = NB * spatial;
    int ch = blockIdx.x, sl = blockIdx.y;
    double s = 0.0, s2 = 0.0;
    for (int i = sl*blockDim.x + threadIdx.x; i < total; i += 32*blockDim.x) {
        int n = i / spatial, p = i % spatial;
        float v = src[(n*16 + ch)*spatial + p];
        s += v; s2 += (double)v * v;
    }
    __shared__ double sh[512], sh2[512];
    sh[threadIdx.x] = s; sh2[threadIdx.x] = s2;
    __syncthreads();
    for (int st = 256; st > 0; st >>= 1) {
        if (threadIdx.x < st) { sh[threadIdx.x] += sh[threadIdx.x+st]; sh2[threadIdx.x] += sh2[threadIdx.x+st]; }
        __syncthreads();
    }
    if (threadIdx.x == 0) {
        g_part[(ch*32 + sl)*2 + 0] = sh[0];
        g_part[(ch*32 + sl)*2 + 1] = sh2[0];
    }
}

__global__ void bn_stats_final(int phase) {
    int ch = blockIdx.x;
    if (threadIdx.x != 0) return;
    int spatial = phase ? S3 : H3;
    double total = (double)NB * spatial;
    double s = 0.0, s2 = 0.0;
    for (int i = 0; i < 32; i++) { s += g_part[(ch*32+i)*2]; s2 += g_part[(ch*32+i)*2+1]; }
    double mean = s / total;
    double var = s2 / total - mean*mean;
    g_stat[phase*32 + ch]      = (float)mean;
    g_stat[phase*32 + 16 + ch] = (float)(1.0 / sqrt(var + 1e-5));
}

// ---------------- BN1 + relu + trilinear upsample x2 (align_corners) ----------------
__device__ __forceinline__ float bnrelu(float v, float sc, float sh) { return fmaxf(v*sc + sh, 0.f); }

__global__ void upsample_kernel(const float* __restrict__ g1p, const float* __restrict__ b1p,
                                const float* __restrict__ g1v, const float* __restrict__ b1v) {
    int idx = blockIdx.x * blockDim.x + threadIdx.x;
    if (idx >= NB*16*S3) return;
    int p = idx % S3; int ch = (idx / S3) % 16; int n = idx / (16*S3);
    int Z = p % S, Y = (p / S) % S, X = p / S2;

    float mean = g_stat[ch], istd = g_stat[16 + ch];
    float gg = (ch < 8) ? g1p[ch] : g1v[ch-8];
    float bb = (ch < 8) ? b1p[ch] : b1v[ch-8];
    float sc = istd * gg, sh = bb - mean * sc;

    const float SC = 32.f / 65.f;
    float sx = X * SC; int x0 = (int)sx; float fx = sx - x0; int x1 = min(x0+1, 32);
    float sy = Y * SC; int y0 = (int)sy; float fy = sy - y0; int y1 = min(y0+1, 32);
    float sz = Z * SC; int z0 = (int)sz; float fz = sz - z0; int z1 = min(z0+1, 32);

    const float* base = g_c1 + (n*16 + ch)*H3;
#define RD(xi,yi,zi) bnrelu(base[((xi)*HH+(yi))*HH+(zi)], sc, sh)
    float v =
      ((RD(x0,y0,z0)*(1-fx) + RD(x1,y0,z0)*fx)*(1-fy) + (RD(x0,y1,z0)*(1-fx) + RD(x1,y1,z0)*fx)*fy)*(1-fz)
    + ((RD(x0,y0,z1)*(1-fx) + RD(x1,y0,z1)*fx)*(1-fy) + (RD(x0,y1,z1)*(1-fx) + RD(x1,y1,z1)*fx)*fy)*fz;
#undef RD
    g_u1[idx] = v;
}

// ---------------- conv2: grouped 2x(8->8), 3^3, pad 1, on 66^3, z-vec x3, f32x2 + LDS.128 ----------------
__global__ void conv2_kernel() {
    __shared__ __align__(16) float ws[27*8*16];
    for (int i = threadIdx.x; i < 27*8*16; i += blockDim.x) ws[i] = g_wp2[i];
    __syncthreads();

    int idx = blockIdx.x * blockDim.x + threadIdx.x;
    if (idx >= NB*S*S*22) return;
    int zt = idx % 22;
    int y  = (idx / 22) % S;
    int x  = (idx / (22*S)) % S;
    int n  = idx / (22*S*S);
    int z0 = 3*zt;

    unsigned long long acc2[3][8];
#pragma unroll
    for (int pp = 0; pp < 3; pp++)
#pragma unroll
        for (int i = 0; i < 8; i++) acc2[pp][i] = 0ULL;

    const float* ubase = g_u1 + n*16*S3;
    bool zlo = (zt == 0);
    bool zhi = (zt == 21);

#pragma unroll
    for (int dx = -1; dx <= 1; dx++) {
        int xx = x + dx;
        if ((unsigned)xx >= (unsigned)S) continue;
#pragma unroll
        for (int dy = -1; dy <= 1; dy++) {
            int yy = y + dy;
            if ((unsigned)yy >= (unsigned)S) continue;
            int tap0 = ((dx+1)*3 + (dy+1))*3;
            const float* col = ubase + (xx*S + yy)*S + z0;
#pragma unroll
            for (int icg = 0; icg < 8; icg++) {
                const float* cp = col + icg*S3;
                const float* cv = col + (8+icg)*S3;
                float inp[5], inv[5];
                inp[0] = zlo ? 0.f : cp[-1];  inv[0] = zlo ? 0.f : cv[-1];
                inp[1] = cp[0];               inv[1] = cv[0];
                inp[2] = cp[1];               inv[2] = cv[1];
                inp[3] = cp[2];               inv[3] = cv[2];
                inp[4] = zhi ? 0.f : cp[3];   inv[4] = zhi ? 0.f : cv[3];
                unsigned long long ip2[5], iv2[5];
#pragma unroll
                for (int t = 0; t < 5; t++) { ip2[t] = pk2(inp[t], inp[t]); iv2[t] = pk2(inv[t], inv[t]); }
#pragma unroll
                for (int dz = 0; dz < 3; dz++) {
                    const ulonglong2* wp =
                        reinterpret_cast<const ulonglong2*>(ws + (((tap0+dz)*8 + icg) << 4));
                    ulonglong2 w01 = wp[0], w23 = wp[1], w45 = wp[2], w67 = wp[3];
#pragma unroll
                    for (int pp = 0; pp < 3; pp++) {
                        unsigned long long vp = ip2[pp+dz];
                        unsigned long long vv = iv2[pp+dz];
                        fma2(acc2[pp][0], vp, w01.x); fma2(acc2[pp][1], vp, w01.y);
                        fma2(acc2[pp][2], vp, w23.x); fma2(acc2[pp][3], vp, w23.y);
                        fma2(acc2[pp][4], vv, w45.x); fma2(acc2[pp][5], vv, w45.y);
                        fma2(acc2[pp][6], vv, w67.x); fma2(acc2[pp][7], vv, w67.y);
                    }
                }
            }
        }
    }
    int ob = (x*S + y)*S + z0;
#pragma unroll
    for (int j = 0; j < 8; j++) {
#pragma unroll
        for (int pp = 0; pp < 3; pp++) {
            float lo, hi;
            upk2(acc2[pp][j], lo, hi);
            g_c2[(n*16 + 2*j    )*S3 + ob + pp] = lo;
            g_c2[(n*16 + 2*j + 1)*S3 + ob + pp] = hi;
        }
    }
}

// ---------------- BN2 + relu + 1x1 heads -> helmholtz (into d_out) ----------------
__global__ void helm_kernel(const float* __restrict__ g2p, const float* __restrict__ b2p,
                            const float* __restrict__ g2v, const float* __restrict__ b2v,
                            const float* __restrict__ pow_, const float* __restrict__ pob,
                            const float* __restrict__ vow,  const float* __restrict__ vob,
                            const float* __restrict__ phiw, const float* __restrict__ vortw,
                            float* __restrict__ out) {
    int idx = blockIdx.x * blockDim.x + threadIdx.x;
    if (idx >= NB*S3) return;
    int p = idx % S3; int n = idx / S3;

    float y[16];
#pragma unroll
    for (int c = 0; c < 16; c++) {
        float mean = g_stat[32 + c], istd = g_stat[48 + c];
        float gg = (c < 8) ? g2p[c] : g2v[c-8];
        float bb = (c < 8) ? b2p[c] : b2v[c-8];
        float v = (g_c2[(n*16 + c)*S3 + p] - mean) * istd * gg + bb;
        y[c] = fmaxf(v, 0.f);
    }
    float ph = pob[0];
#pragma unroll
    for (int c = 0; c < 8; c++) ph += y[c] * pow_[c];
    ph *= phiw[0];
    out[OFF_HELM + (n*4)*S3 + p] = ph;
    float vscale = vortw[0] * 66.f;
#pragma unroll
    for (int r = 0; r < 3; r++) {
        float v = vob[r];
#pragma unroll
        for (int c = 0; c < 8; c++) v += y[8+c] * vow[r*8 + c];
        out[OFF_HELM + (n*4 + 1 + r)*S3 + p] = v * vscale;
    }
}

// ---------------- velocity stencils (into d_out) ----------------
__device__ __forceinline__ float HV(const float* hm, int ch, int x, int y, int z) {
    return hm[ch*S3 + (x*S + y)*S + z];
}

__global__ void vel_kernel(float* __restrict__ out) {
    int idx = blockIdx.x * blockDim.x + threadIdx.x;
    if (idx >= NB*D3) return;
    int p = idx % D3; int n = idx / D3;
    int k = p & 63, j = (p >> 6) & 63, i = p >> 12;
    const float* hm = out + OFF_HELM + n*4*S3;

    float vp0 = 0.5f * (HV(hm,0, 1+i, 1+j, k+2) - HV(hm,0, 1+i, 1+j, k));
    float vp1 = 0.5f * (HV(hm,0, 1+i, j+2, 1+k) - HV(hm,0, 1+i, j,   1+k));
    float vp2 = 0.5f * (HV(hm,0, i+2, 1+j, 1+k) - HV(hm,0, i,   1+j, 1+k));

    float ua = (HV(hm,2, 2+i,1+j,k+1) - HV(hm,2, 1+i,1+j,k+1)) - (HV(hm,1, 1+i,2+j,k+1) - HV(hm,1, 1+i,1+j,k+1));
    float ub = (HV(hm,2, 2+i,1+j,k  ) - HV(hm,2, 1+i,1+j,k  )) - (HV(hm,1, 1+i,2+j,k  ) - HV(hm,1, 1+i,1+j,k  ));
    float vv0 = 0.5f * (ua + ub);
    float va = (HV(hm,1, 1+i,j+1,k+2) - HV(hm,1, 1+i,j+1,k+1)) - (HV(hm,3, i+2,j+1,k+1) - HV(hm,3, i+1,j+1,k+1));
    float vb = (HV(hm,1, 1+i,j,  k+2) - HV(hm,1, 1+i,j,  k+1)) - (HV(hm,3, i+2,j,  k+1) - HV(hm,3, i+1,j,  k+1));
    float vv1 = 0.5f * (va + vb);
    float wa = (HV(hm,3, i+1,j+2,k+1) - HV(hm,3, i+1,j+1,k+1)) - (HV(hm,2, i+1,j+1,k+2) - HV(hm,2, i+1,j+1,k+1));
    float wb = (HV(hm,3, i,  j+2,k+1) - HV(hm,3, i,  j+1,k+1)) - (HV(hm,2, i,  j+1,k+2) - HV(hm,2, i,  j+1,k+1));
    float vv2 = 0.5f * (wa + wb);

    int b = n*3*D3 + p;
    out[OFF_VPHI  + b        ] = vp0;
    out[OFF_VPHI  + b + D3   ] = vp1;
    out[OFF_VPHI  + b + 2*D3 ] = vp2;
    out[OFF_VVORT + b        ] = vv0;
    out[OFF_VVORT + b + D3   ] = vv1;
    out[OFF_VVORT + b + 2*D3 ] = vv2;
    out[OFF_VEL   + b        ] = vp0 + vv0;
    out[OFF_VEL   + b + D3   ] = vp1 + vv1;
    out[OFF_VEL   + b + 2*D3 ] = vp2 + vv2;
}

// ---------------- BFECC advect passes ----------------
__global__ void advect_kernel(const float* __restrict__ ext_src, const float* __restrict__ tex,
                              const float* __restrict__ vel, float sgn, int mode) {
    int idx = blockIdx.x * blockDim.x + threadIdx.x;
    if (idx >= NB*D3) return;
    int p = idx % D3; int n = idx / D3;
    int k = p & 63, j = (p >> 6) & 63, i = p >> 12;

    float v0 = vel[(n*3    )*D3 + p];
    float v1 = vel[(n*3 + 1)*D3 + p];
    float v2 = vel[(n*3 + 2)*D3 + p];
    float px = (float)i - sgn*v2;
    float py = (float)j - sgn*v1;
    float pz = (float)k - sgn*v0;
    px = fminf(fmaxf(px, 0.f), 63.f);
    py = fminf(fmaxf(py, 0.f), 63.f);
    pz = fminf(fmaxf(pz, 0.f), 63.f);
    int x0 = (int)px; float fx = px - x0; int x1 = min(x0+1, 63);
    int y0 = (int)py; float fy = py - y0; int y1 = min(y0+1, 63);
    int z0 = (int)pz; float fz = pz - z0; int z1 = min(z0+1, 63);

    float w000 = (1-fx)*(1-fy)*(1-fz), w001 = (1-fx)*(1-fy)*fz;
    float w010 = (1-fx)*fy*(1-fz),     w011 = (1-fx)*fy*fz;
    float w100 = fx*(1-fy)*(1-fz),     w101 = fx*(1-fy)*fz;
    float w110 = fx*fy*(1-fz),         w111 = fx*fy*fz;

    int b00 = (x0*64 + y0)*64, b01 = (x0*64 + y1)*64;
    int b10 = (x1*64 + y0)*64, b11 = (x1*64 + y1)*64;

    const float* src = (mode == 0) ? ext_src : ((mode == 1) ? g_phi1 : g_comb);
    float* dst = (mode == 0) ? g_phi1 : ((mode == 1) ? g_comb : g_pred);

#pragma unroll
    for (int c = 0; c < 8; c++) {
        const float* s = src + (n*8 + c)*D3;
        float v = w000*s[b00+z0] + w001*s[b00+z1] + w010*s[b01+z0] + w011*s[b01+z1]
                + w100*s[b10+z0] + w101*s[b10+z1] + w110*s[b11+z0] + w111*s[b11+z1];
        if (mode == 1) v = 1.5f * tex[(n*8 + c)*D3 + p] - 0.5f * v;
        dst[(n*8 + c)*D3 + p] = v;
    }
}

// ---------------- fused LN + FF (LN, @W1+b1, GELU, @W2+b2, residual -> d_out) ----------------
__global__ void ff_kernel(const float* __restrict__ lng, const float* __restrict__ lnb,
                          const float* __restrict__ w1, const float* __restrict__ b1,
                          const float* __restrict__ w2, const float* __restrict__ b2,
                          float* __restrict__ out) {
    __shared__ __align__(16) unsigned long long Wp1[2048];  // Wp1[jj*32+q] = (W1[2q][jj], W1[2q+1][jj])
    __shared__ __align__(16) unsigned long long Wp2[2048];
    __shared__ float Bv1[64], Bv2[64], G[64], Bt[64];
    float* fW1 = reinterpret_cast<float*>(Wp1);
    float* fW2 = reinterpret_cast<float*>(Wp2);
    for (int i = threadIdx.x; i < 4096; i += blockDim.x) {
        int ii = i >> 6, jj = i & 63;
        int d = (jj*32 + (ii >> 1))*2 + (ii & 1);
        fW1[d] = w1[i];
        fW2[d] = w2[i];
    }
    if (threadIdx.x < 64) {
        Bv1[threadIdx.x] = b1[threadIdx.x]; Bv2[threadIdx.x] = b2[threadIdx.x];
        G[threadIdx.x] = lng[threadIdx.x];  Bt[threadIdx.x] = lnb[threadIdx.x];
    }
    __syncthreads();

    int p = blockIdx.x * blockDim.x + threadIdx.x;
    if (p >= D3) return;

    float h[64]; float s = 0.f, s2 = 0.f;
#pragma unroll
    for (int c = 0; c < 64; c++) { float v = g_pred[c*D3 + p]; h[c] = v; s += v; s2 += v*v; }
    float mean = s * (1.f/64.f);
    float var  = s2 * (1.f/64.f) - mean*mean;
    float is = rsqrtf(var + 1e-5f);
    unsigned long long hp[32];
#pragma unroll
    for (int c = 0; c < 32; c++) {
        float e = (h[2*c]   - mean) * is * G[2*c]   + Bt[2*c];
        float o = (h[2*c+1] - mean) * is * G[2*c+1] + Bt[2*c+1];
        hp[c] = pk2(e, o);
    }

    // GEMM1 + GELU, packed result pairs
    unsigned long long gp[32];
    for (int jj = 0; jj < 64; jj += 2) {
        const ulonglong2* wrA = reinterpret_cast<const ulonglong2*>(Wp1 + jj*32);
        const ulonglong2* wrB = reinterpret_cast<const ulonglong2*>(Wp1 + (jj+1)*32);
        unsigned long long a0 = 0ULL, a1 = 0ULL, c0 = 0ULL, c1 = 0ULL;
#pragma unroll
        for (int q = 0; q < 16; q++) {
            ulonglong2 wa = wrA[q];
            ulonglong2 wb = wrB[q];
            fma2(a0, hp[2*q],   wa.x);
            fma2(a1, hp[2*q+1], wa.y);
            fma2(c0, hp[2*q],   wb.x);
            fma2(c1, hp[2*q+1], wb.y);
        }
        float l0, h0, l1, h1;
        upk2(a0, l0, h0); upk2(a1, l1, h1);
        float aA = Bv1[jj] + ((l0 + h0) + (l1 + h1));
        upk2(c0, l0, h0); upk2(c1, l1, h1);
        float aB = Bv1[jj+1] + ((l0 + h0) + (l1 + h1));
        float gA = 0.5f * aA * (1.f + erff(aA * 0.70710678118f));
        float gB = 0.5f * aB * (1.f + erff(aB * 0.70710678118f));
        gp[jj >> 1] = pk2(gA, gB);
    }

    // GEMM2 + residual
    for (int jj = 0; jj < 64; jj++) {
        const ulonglong2* wr = reinterpret_cast<const ulonglong2*>(Wp2 + jj*32);
        unsigned long long a0 = 0ULL, a1 = 0ULL;
#pragma unroll
        for (int q = 0; q < 16; q++) {
            ulonglong2 w2v = wr[q];
            fma2(a0, gp[2*q],   w2v.x);
            fma2(a1, gp[2*q+1], w2v.y);
        }
        float l0, h0, l1, h1;
        upk2(a0, l0, h0); upk2(a1, l1, h1);
        float a = Bv2[jj] + ((l0 + h0) + (l1 + h1));
        out[OFF_X + jj*D3 + p] = g_pred[jj*D3 + p] + a;
    }
}

// ---------------- host launch ----------------
extern "C" void kernel_launch(void* const* d_in, const int* in_sizes, int n_in,
                              void* d_out, int out_size) {
    const float* prev      = (const float*)d_in[0];
    const float* nxt       = (const float*)d_in[1];
    const float* texture   = (const float*)d_in[2];
    const float* mask      = (const float*)d_in[3];
    const float* boundary  = (const float*)d_in[4];
    const float* enc_w     = (const float*)d_in[5];
    const float* enc_b     = (const float*)d_in[6];
    const float* phi_c1_w  = (const float*)d_in[7];
    const float* phi_bn1_g = (const float*)d_in[8];
    const float* phi_bn1_b = (const float*)d_in[9];
    const float* phi_c2_w  = (const float*)d_in[10];
    const float* phi_bn2_g = (const float*)d_in[11];
    const float* phi_bn2_b = (const float*)d_in[12];
    const float* phi_out_w = (const float*)d_in[13];
    const float* phi_out_b = (const float*)d_in[14];
    const float* vort_c1_w = (const float*)d_in[15];
    const float* vort_bn1_g= (const float*)d_in[16];
    const float* vort_bn1_b= (const float*)d_in[17];
    const float* vort_c2_w = (const float*)d_in[18];
    const float* vort_bn2_g= (const float*)d_in[19];
    const float* vort_bn2_b= (const float*)d_in[20];
    const float* vort_out_w= (const float*)d_in[21];
    const float* vort_out_b= (const float*)d_in[22];
    const float* phi_weight= (const float*)d_in[23];
    const float* vort_weight=(const float*)d_in[24];
    const float* ln_g      = (const float*)d_in[25];
    const float* ln_b      = (const float*)d_in[26];
    const float* ff_w1     = (const float*)d_in[27];
    const float* ff_b1     = (const float*)d_in[28];
    const float* ff_w2     = (const float*)d_in[29];
    const float* ff_b2     = (const float*)d_in[30];
    float* out = (float*)d_out;

    pack_kernel<<<(3*WC1_PACK + 255)/256, 256>>>(phi_c1_w, vort_c1_w, phi_c2_w, vort_c2_w);

    int encBlocks = (NB*H3 + 255)/256;
    enc_kernel<<<encBlocks, 256>>>(prev, mask,     enc_w, enc_b, 0);
    enc_kernel<<<encBlocks, 256>>>(prev, boundary, enc_w, enc_b, 1);
    enc_kernel<<<encBlocks, 256>>>(nxt,  mask,     enc_w, enc_b, 2);

    corr_kernel<<<(NB*H3 + 255)/256, 256>>>();

    cudaFuncSetAttribute(conv1_kernel, cudaFuncAttributeMaxDynamicSharedMemorySize, 3*WC1_PACK*4);
    conv1_kernel<<<(NB*H3 + 255)/256, 256, 3*WC1_PACK*4>>>();

    bn_stats_partial<<<dim3(16, 32), 512>>>(0);
    bn_stats_final<<<16, 32>>>(0);

    int upN = NB*16*S3;
    upsample_kernel<<<(upN + 255)/256, 256>>>(phi_bn1_g, phi_bn1_b, vort_bn1_g, vort_bn1_b);

    conv2_kernel<<<(NB*S*S*22 + 255)/256, 256>>>();

    bn_stats_partial<<<dim3(16, 32), 512>>>(1);
    bn_stats_final<<<16, 32>>>(1);

    helm_kernel<<<(NB*S3 + 255)/256, 256>>>(phi_bn2_g, phi_bn2_b, vort_bn2_g, vort_bn2_b,
                                            phi_out_w, phi_out_b, vort_out_w, vort_out_b,
                                            phi_weight, vort_weight, out);

    vel_kernel<<<(NB*D3 + 255)/256, 256>>>(out);

    const float* vel = out + OFF_VEL;
    advect_kernel<<<(NB*D3 + 255)/256, 256>>>(texture, texture, vel,  1.f, 0);
    advect_kernel<<<(NB*D3 + 255)/256, 256>>>(texture, texture, vel, -1.f, 1);
    advect_kernel<<<(NB*D3 + 255)/256, 256>>>(texture, texture, vel,  1.f, 2);

    ff_kernel<<<(D3 + 127)/128, 128>>>(ln_g, ln_b, ff_w1, ff_b1, ff_w2, ff_b2, out);
}

// round 12
// speedup vs baseline: 1.2551x; 1.1244x over previous
#include <cuda_runtime.h>
#include <math.h>

// ---------------- dimensions ----------------
#define NB 8          // batch*groups
#define S  66
#define S2 4356       // 66*66
#define S3 287496     // 66^3
#define HH 33
#define H2 1089       // 33*33
#define H3 35937      // 33^3
#define D3 262144     // 64^3

// output packing offsets (x, helmholtz, vel, vel_phi, vel_vort)
#define OFF_X     0
#define OFF_HELM  16777216
#define OFF_VEL   25977088
#define OFF_VPHI  32268544
#define OFF_VVORT 38560000

#define WC1_PACK 7776          // 18*27*16
#define NBLK1 1124             // conv1 blocks: ceil(NB*H3/256)
#define NBLK2 2995             // conv2 blocks: ceil(NB*66*66*22/256)

// ---------------- scratch (static device memory; no allocation APIs) ----------------
__device__ float g_f[3][NB*64*H3];     // encoder outputs: pm, pb, nm
__device__ float g_corr[NB*18*H3];     // correlation output (18 distinct channels)
__device__ float g_c1[NB*16*H3];       // conv1 raw out (phi 0-7, vort 8-15)
__device__ float g_u1[NB*16*S3];       // upsampled (post BN1+relu)
__device__ float g_c2[NB*16*S3];       // conv2 raw out
__device__ float g_phi1[64*D3];        // advect pass 1
__device__ float g_comb[64*D3];        // 1.5*tex - 0.5*phi2
__device__ float g_pred[64*D3];        // final advect result
__device__ float g_wc1[3*WC1_PACK];    // conv1 summed packs
__device__ float g_wp2[27*8*16];       // packed conv2 weights
__device__ float g_stat[64];           // mean1[16], istd1[16], mean2[16], istd2[16]
__device__ double g_pc1[16*NBLK1*2];   // conv1 per-block stat partials
__device__ double g_pc2[16*NBLK2*2];   // conv2 per-block stat partials

// ---------------- packed f32x2 helpers (sm_103a FFMA2 via PTX) ----------------
__device__ __forceinline__ unsigned long long pk2(float a, float b) {
    unsigned long long r;
    asm("mov.b64 %0, {%1, %2};" : "=l"(r) : "f"(a), "f"(b));
    return r;
}
__device__ __forceinline__ void fma2(unsigned long long& d, unsigned long long a, unsigned long long b) {
    asm("fma.rn.f32x2 %0, %1, %2, %0;" : "+l"(d) : "l"(a), "l"(b));
}
__device__ __forceinline__ void upk2(unsigned long long v, float& lo, float& hi) {
    asm("mov.b64 {%0, %1}, %2;" : "=f"(lo), "=f"(hi) : "l"(v));
}
__device__ __forceinline__ float wred(float v) {
#pragma unroll
    for (int o = 16; o > 0; o >>= 1) v += __shfl_down_sync(0xffffffffu, v, o);
    return v;
}

// ---------------- weight packing ----------------
__global__ void pack_kernel(const float* __restrict__ pw1, const float* __restrict__ vw1,
                            const float* __restrict__ pw2, const float* __restrict__ vw2) {
    int i = blockIdx.x * blockDim.x + threadIdx.x;
    if (i < 3*WC1_PACK) {
        int pack = i / WC1_PACK; int r = i % WC1_PACK;
        int oc = r & 15; int t18 = r >> 4; int ic = t18 % 18; int tap = t18 / 18;
        int w = ic / 9, s = ic % 9;
        int c0 = w*27 + s, c1 = c0 + 9, c2 = c0 + 18;
        const float* src = (oc < 8) ? pw1 : vw1;
        int o = (oc < 8) ? oc : oc - 8;
        float W0 = src[(o*54 + c0)*27 + tap];
        float W1 = src[(o*54 + c1)*27 + tap];
        float W2 = src[(o*54 + c2)*27 + tap];
        float v = (pack == 0) ? (W0 + W1 + W2) : ((pack == 1) ? (W0 + W1) : (W1 + W2));
        g_wc1[i] = v;
    }
    if (i < 27*8*16) {
        int oc = i & 15; int icg = (i >> 4) % 8; int t = (i >> 4) / 8;
        g_wp2[i] = (oc < 8) ? pw2[(oc*8 + icg)*27 + t] : vw2[((oc-8)*8 + icg)*27 + t];
    }
}

// ---------------- encoder: conv3d stride 2, kernel 2, input = src*mul, oc-pair ILP ----------------
__global__ void enc_kernel(const float* __restrict__ src, const float* __restrict__ mul,
                           const float* __restrict__ w, const float* __restrict__ b, int variant) {
    __shared__ __align__(16) float ws[4096];
    __shared__ float bs[64];
    for (int i = threadIdx.x; i < 4096; i += blockDim.x) ws[i] = w[i];
    if (threadIdx.x < 64) bs[threadIdx.x] = b[threadIdx.x];
    __syncthreads();

    int idx = blockIdx.x * blockDim.x + threadIdx.x;
    if (idx >= NB*H3) return;
    int p = idx % H3;
    int n = idx / H3;
    int z = p % HH, y = (p / HH) % HH, x = p / H2;
    int X = 2*x, Y = 2*y, Z = 2*z;

    float m[8];
#pragma unroll
    for (int t = 0; t < 8; t++) {
        int dx = t >> 2, dy = (t >> 1) & 1, dz = t & 1;
        m[t] = mul[((X+dx)*S + (Y+dy))*S + (Z+dz)];
    }

    unsigned long long xp[32];
#pragma unroll
    for (int ic = 0; ic < 8; ic++) {
        int base = (n*8 + ic)*S3 + (X*S + Y)*S + Z;
#pragma unroll
        for (int th = 0; th < 4; th++) {
            int t0 = 2*th, t1 = 2*th + 1;
            int dx0 = t0 >> 2, dy0 = (t0 >> 1) & 1, dz0 = t0 & 1;
            int dx1 = t1 >> 2, dy1 = (t1 >> 1) & 1, dz1 = t1 & 1;
            float v0 = src[base + (dx0*S + dy0)*S + dz0] * m[t0];
            float v1 = src[base + (dx1*S + dy1)*S + dz1] * m[t1];
            xp[ic*4 + th] = pk2(v0, v1);
        }
    }

    float* outp = &g_f[variant][(n*64)*H3 + p];
    for (int oc = 0; oc < 64; oc += 2) {
        const ulonglong2* wA = reinterpret_cast<const ulonglong2*>(ws + (oc << 6));
        const ulonglong2* wB = reinterpret_cast<const ulonglong2*>(ws + ((oc+1) << 6));
        unsigned long long a0 = 0ULL, a1 = 0ULL, b0 = 0ULL, b1 = 0ULL;
#pragma unroll
        for (int q = 0; q < 16; q++) {
            ulonglong2 wa = wA[q];
            ulonglong2 wb = wB[q];
            fma2(a0, xp[2*q],   wa.x);
            fma2(a1, xp[2*q+1], wa.y);
            fma2(b0, xp[2*q],   wb.x);
            fma2(b1, xp[2*q+1], wb.y);
        }
        float l0, h0, l1, h1;
        upk2(a0, l0, h0); upk2(a1, l1, h1);
        outp[oc*H3] = bs[oc] + ((l0 + h0) + (l1 + h1));
        upk2(b0, l0, h0); upk2(b1, l1, h1);
        outp[(oc+1)*H3] = bs[oc+1] + ((l0 + h0) + (l1 + h1));
    }
}

// ---------------- correlation: 18 distinct channels, s-pair f32x2 ----------------
__global__ void corr_kernel() {
    int idx = blockIdx.x * blockDim.x + threadIdx.x;
    if (idx >= NB*H3) return;
    int p = idx % H3; int n = idx / H3;
    int y = (p / HH) % HH, x = p / H2;

    const float* A0 = &g_f[0][n*64*H3 + p];
    const float* A1 = &g_f[1][n*64*H3 + p];
    const float* B  = &g_f[2][n*64*H3 + p];

    int off[9]; bool ok[9];
    {
        int s = 0;
        for (int di = -1; di <= 1; di++)
            for (int dj = -1; dj <= 1; dj++) {
                ok[s] = (x+di >= 0 && x+di < HH && y+dj >= 0 && y+dj < HH);
                off[s] = (di*HH + dj)*HH;
                s++;
            }
    }
    unsigned long long acc2[9];
#pragma unroll
    for (int s = 0; s < 9; s++) acc2[s] = 0ULL;

    for (int c = 0; c < 64; c++) {
        unsigned long long a2 = pk2(A0[c*H3], A1[c*H3]);
        const float* Bc = B + c*H3;
#pragma unroll
        for (int s = 0; s < 9; s++) {
            float bv = ok[s] ? Bc[off[s]] : 0.f;
            fma2(acc2[s], pk2(bv, bv), a2);
        }
    }
#pragma unroll
    for (int s = 0; s < 9; s++) {
        float a, bqq;
        upk2(acc2[s], a, bqq);
        g_corr[(n*18 + s    )*H3 + p] = a   * (1.f/64.f);
        g_corr[(n*18 + 9 + s)*H3 + p] = bqq * (1.f/64.f);
    }
}

// ---------------- conv1: effective 18 -> 16, with fused BN stat partials ----------------
__global__ void conv1_kernel() {
    extern __shared__ float ws[];
    __shared__ double sW[8][16][2];
    for (int i = threadIdx.x; i < 3*WC1_PACK; i += blockDim.x) ws[i] = g_wc1[i];
    __syncthreads();

    int idx = blockIdx.x * blockDim.x + threadIdx.x;
    bool valid = (idx < NB*H3);
    int p = 0, n = 0, z = 0, y = 0, x = 0;
    if (valid) {
        p = idx % H3; n = idx / H3;
        z = p % HH; y = (p / HH) % HH; x = p / H2;
    }

    unsigned long long acc2[8];
#pragma unroll
    for (int i = 0; i < 8; i++) acc2[i] = 0ULL;

    if (valid) {
        const float* cbase = g_corr + n*18*H3;
        for (int tap = 0; tap < 27; tap++) {
            int dx = tap/9 - 1, dy = (tap/3)%3 - 1, dz = tap%3 - 1;
            int xx = x+dx, yy = y+dy, zz = z+dz;
            if ((unsigned)xx >= (unsigned)HH || (unsigned)yy >= (unsigned)HH || (unsigned)zz >= (unsigned)HH) continue;
            int q = (xx*HH + yy)*HH + zz;
            int sel = (zz == 0) ? 1 : ((zz == HH-1) ? 2 : 0);
            const float* wt = ws + sel*WC1_PACK + tap*288;
#pragma unroll
            for (int ic = 0; ic < 18; ic++) {
                float v = cbase[ic*H3 + q];
                unsigned long long v2 = pk2(v, v);
                const ulonglong2* wp = reinterpret_cast<const ulonglong2*>(wt + (ic << 4));
                ulonglong2 w01 = wp[0], w23 = wp[1], w45 = wp[2], w67 = wp[3];
                fma2(acc2[0], v2, w01.x); fma2(acc2[1], v2, w01.y);
                fma2(acc2[2], v2, w23.x); fma2(acc2[3], v2, w23.y);
                fma2(acc2[4], v2, w45.x); fma2(acc2[5], v2, w45.y);
                fma2(acc2[6], v2, w67.x); fma2(acc2[7], v2, w67.y);
            }
        }
    }

    int warp = threadIdx.x >> 5;
#pragma unroll
    for (int j = 0; j < 8; j++) {
        float lo = 0.f, hi = 0.f;
        upk2(acc2[j], lo, hi);
        if (!valid) { lo = 0.f; hi = 0.f; }
        if (valid) {
            g_c1[(n*16 + 2*j    )*H3 + p] = lo;
            g_c1[(n*16 + 2*j + 1)*H3 + p] = hi;
        }
        float sl = wred(lo), s2l = wred(lo*lo);
        float sh = wred(hi), s2h = wred(hi*hi);
        if ((threadIdx.x & 31) == 0) {
            sW[warp][2*j  ][0] = (double)sl; sW[warp][2*j  ][1] = (double)s2l;
            sW[warp][2*j+1][0] = (double)sh; sW[warp][2*j+1][1] = (double)s2h;
        }
        __syncwarp();
    }
    __syncthreads();
    if (threadIdx.x < 16) {
        double s = 0.0, s2 = 0.0;
        for (int wi = 0; wi < 8; wi++) { s += sW[wi][threadIdx.x][0]; s2 += sW[wi][threadIdx.x][1]; }
        g_pc1[(threadIdx.x*NBLK1 + blockIdx.x)*2 + 0] = s;
        g_pc1[(threadIdx.x*NBLK1 + blockIdx.x)*2 + 1] = s2;
    }
}

// ---------------- stats reduce: per-channel partial sums -> mean/istd ----------------
__global__ void stats_reduce(int phase) {
    int ch = blockIdx.x;
    int NP = phase ? NBLK2 : NBLK1;
    const double* src = phase ? g_pc2 : g_pc1;
    __shared__ double sh[256], sh2[256];
    double s = 0.0, s2 = 0.0;
    for (int i = threadIdx.x; i < NP; i += 256) {
        s  += src[(ch*NP + i)*2 + 0];
        s2 += src[(ch*NP + i)*2 + 1];
    }
    sh[threadIdx.x] = s; sh2[threadIdx.x] = s2;
    __syncthreads();
    for (int st = 128; st > 0; st >>= 1) {
        if (threadIdx.x < st) { sh[threadIdx.x] += sh[threadIdx.x+st]; sh2[threadIdx.x] += sh2[threadIdx.x+st]; }
        __syncthreads();
    }
    if (threadIdx.x == 0) {
        double total = (double)NB * (phase ? S3 : H3);
        double mean = sh[0] / total;
        double var  = sh2[0] / total - mean*mean;
        g_stat[phase*32 + ch]      = (float)mean;
        g_stat[phase*32 + 16 + ch] = (float)(1.0 / sqrt(var + 1e-5));
    }
}

// ---------------- BN1 + relu + trilinear upsample x2 (align_corners) ----------------
__device__ __forceinline__ float bnrelu(float v, float sc, float sh) { return fmaxf(v*sc + sh, 0.f); }

__global__ void upsample_kernel(const float* __restrict__ g1p, const float* __restrict__ b1p,
                                const float* __restrict__ g1v, const float* __restrict__ b1v) {
    int idx = blockIdx.x * blockDim.x + threadIdx.x;
    if (idx >= NB*16*S3) return;
    int p = idx % S3; int ch = (idx / S3) % 16; int n = idx / (16*S3);
    int Z = p % S, Y = (p / S) % S, X = p / S2;

    float mean = g_stat[ch], istd = g_stat[16 + ch];
    float gg = (ch < 8) ? g1p[ch] : g1v[ch-8];
    float bb = (ch < 8) ? b1p[ch] : b1v[ch-8];
    float sc = istd * gg, sh = bb - mean * sc;

    const float SC = 32.f / 65.f;
    float sx = X * SC; int x0 = (int)sx; float fx = sx - x0; int x1 = min(x0+1, 32);
    float sy = Y * SC; int y0 = (int)sy; float fy = sy - y0; int y1 = min(y0+1, 32);
    float sz = Z * SC; int z0 = (int)sz; float fz = sz - z0; int z1 = min(z0+1, 32);

    const float* base = g_c1 + (n*16 + ch)*H3;
#define RD(xi,yi,zi) bnrelu(base[((xi)*HH+(yi))*HH+(zi)], sc, sh)
    float v =
      ((RD(x0,y0,z0)*(1-fx) + RD(x1,y0,z0)*fx)*(1-fy) + (RD(x0,y1,z0)*(1-fx) + RD(x1,y1,z0)*fx)*fy)*(1-fz)
    + ((RD(x0,y0,z1)*(1-fx) + RD(x1,y0,z1)*fx)*(1-fy) + (RD(x0,y1,z1)*(1-fx) + RD(x1,y1,z1)*fx)*fy)*fz;
#undef RD
    g_u1[idx] = v;
}

// ---------------- conv2: grouped 2x(8->8), z-vec x3, f32x2, fused BN stat partials ----------------
__global__ void conv2_kernel() {
    __shared__ __align__(16) float ws[27*8*16];
    __shared__ double sW[8][16][2];
    for (int i = threadIdx.x; i < 27*8*16; i += blockDim.x) ws[i] = g_wp2[i];
    __syncthreads();

    int idx = blockIdx.x * blockDim.x + threadIdx.x;
    bool valid = (idx < NB*S*S*22);
    int zt = 0, y = 0, x = 0, n = 0;
    if (valid) {
        zt = idx % 22;
        y  = (idx / 22) % S;
        x  = (idx / (22*S)) % S;
        n  = idx / (22*S*S);
    }
    int z0 = 3*zt;

    unsigned long long acc2[3][8];
#pragma unroll
    for (int pp = 0; pp < 3; pp++)
#pragma unroll
        for (int i = 0; i < 8; i++) acc2[pp][i] = 0ULL;

    if (valid) {
        const float* ubase = g_u1 + n*16*S3;
        bool zlo = (zt == 0);
        bool zhi = (zt == 21);

#pragma unroll
        for (int dx = -1; dx <= 1; dx++) {
            int xx = x + dx;
            if ((unsigned)xx >= (unsigned)S) continue;
#pragma unroll
            for (int dy = -1; dy <= 1; dy++) {
                int yy = y + dy;
                if ((unsigned)yy >= (unsigned)S) continue;
                int tap0 = ((dx+1)*3 + (dy+1))*3;
                const float* col = ubase + (xx*S + yy)*S + z0;
#pragma unroll
                for (int icg = 0; icg < 8; icg++) {
                    const float* cp = col + icg*S3;
                    const float* cv = col + (8+icg)*S3;
                    float inp[5], inv[5];
                    inp[0] = zlo ? 0.f : cp[-1];  inv[0] = zlo ? 0.f : cv[-1];
                    inp[1] = cp[0];               inv[1] = cv[0];
                    inp[2] = cp[1];               inv[2] = cv[1];
                    inp[3] = cp[2];               inv[3] = cv[2];
                    inp[4] = zhi ? 0.f : cp[3];   inv[4] = zhi ? 0.f : cv[3];
                    unsigned long long ip2[5], iv2[5];
#pragma unroll
                    for (int t = 0; t < 5; t++) { ip2[t] = pk2(inp[t], inp[t]); iv2[t] = pk2(inv[t], inv[t]); }
#pragma unroll
                    for (int dz = 0; dz < 3; dz++) {
                        const ulonglong2* wp =
                            reinterpret_cast<const ulonglong2*>(ws + (((tap0+dz)*8 + icg) << 4));
                        ulonglong2 w01 = wp[0], w23 = wp[1], w45 = wp[2], w67 = wp[3];
#pragma unroll
                        for (int pp = 0; pp < 3; pp++) {
                            unsigned long long vp = ip2[pp+dz];
                            unsigned long long vv = iv2[pp+dz];
                            fma2(acc2[pp][0], vp, w01.x); fma2(acc2[pp][1], vp, w01.y);
                            fma2(acc2[pp][2], vp, w23.x); fma2(acc2[pp][3], vp, w23.y);
                            fma2(acc2[pp][4], vv, w45.x); fma2(acc2[pp][5], vv, w45.y);
                            fma2(acc2[pp][6], vv, w67.x); fma2(acc2[pp][7], vv, w67.y);
                        }
                    }
                }
            }
        }
    }

    int ob = (x*S + y)*S + z0;
    int warp = threadIdx.x >> 5;
#pragma unroll
    for (int j = 0; j < 8; j++) {
        float sLo = 0.f, s2Lo = 0.f, sHi = 0.f, s2Hi = 0.f;
#pragma unroll
        for (int pp = 0; pp < 3; pp++) {
            float lo, hi;
            upk2(acc2[pp][j], lo, hi);
            if (valid) {
                g_c2[(n*16 + 2*j    )*S3 + ob + pp] = lo;
                g_c2[(n*16 + 2*j + 1)*S3 + ob + pp] = hi;
                sLo += lo; s2Lo += lo*lo;
                sHi += hi; s2Hi += hi*hi;
            }
        }
        float a = wred(sLo), b = wred(s2Lo);
        float c = wred(sHi), d = wred(s2Hi);
        if ((threadIdx.x & 31) == 0) {
            sW[warp][2*j  ][0] = (double)a; sW[warp][2*j  ][1] = (double)b;
            sW[warp][2*j+1][0] = (double)c; sW[warp][2*j+1][1] = (double)d;
        }
        __syncwarp();
    }
    __syncthreads();
    if (threadIdx.x < 16) {
        double s = 0.0, s2 = 0.0;
        for (int wi = 0; wi < 8; wi++) { s += sW[wi][threadIdx.x][0]; s2 += sW[wi][threadIdx.x][1]; }
        g_pc2[(threadIdx.x*NBLK2 + blockIdx.x)*2 + 0] = s;
        g_pc2[(threadIdx.x*NBLK2 + blockIdx.x)*2 + 1] = s2;
    }
}

// ---------------- BN2 + relu + 1x1 heads -> helmholtz (into d_out) ----------------
__global__ void helm_kernel(const float* __restrict__ g2p, const float* __restrict__ b2p,
                            const float* __restrict__ g2v, const float* __restrict__ b2v,
                            const float* __restrict__ pow_, const float* __restrict__ pob,
                            const float* __restrict__ vow,  const float* __restrict__ vob,
                            const float* __restrict__ phiw, const float* __restrict__ vortw,
                            float* __restrict__ out) {
    int idx = blockIdx.x * blockDim.x + threadIdx.x;
    if (idx >= NB*S3) return;
    int p = idx % S3; int n = idx / S3;

    float y[16];
#pragma unroll
    for (int c = 0; c < 16; c++) {
        float mean = g_stat[32 + c], istd = g_stat[48 + c];
        float gg = (c < 8) ? g2p[c] : g2v[c-8];
        float bb = (c < 8) ? b2p[c] : b2v[c-8];
        float v = (g_c2[(n*16 + c)*S3 + p] - mean) * istd * gg + bb;
        y[c] = fmaxf(v, 0.f);
    }
    float ph = pob[0];
#pragma unroll
    for (int c = 0; c < 8; c++) ph += y[c] * pow_[c];
    ph *= phiw[0];
    out[OFF_HELM + (n*4)*S3 + p] = ph;
    float vscale = vortw[0] * 66.f;
#pragma unroll
    for (int r = 0; r < 3; r++) {
        float v = vob[r];
#pragma unroll
        for (int c = 0; c < 8; c++) v += y[8+c] * vow[r*8 + c];
        out[OFF_HELM + (n*4 + 1 + r)*S3 + p] = v * vscale;
    }
}

// ---------------- velocity stencils (into d_out) ----------------
__device__ __forceinline__ float HV(const float* hm, int ch, int x, int y, int z) {
    return hm[ch*S3 + (x*S + y)*S + z];
}

__global__ void vel_kernel(float* __restrict__ out) {
    int idx = blockIdx.x * blockDim.x + threadIdx.x;
    if (idx >= NB*D3) return;
    int p = idx % D3; int n = idx / D3;
    int k = p & 63, j = (p >> 6) & 63, i = p >> 12;
    const float* hm = out + OFF_HELM + n*4*S3;

    float vp0 = 0.5f * (HV(hm,0, 1+i, 1+j, k+2) - HV(hm,0, 1+i, 1+j, k));
    float vp1 = 0.5f * (HV(hm,0, 1+i, j+2, 1+k) - HV(hm,0, 1+i, j,   1+k));
    float vp2 = 0.5f * (HV(hm,0, i+2, 1+j, 1+k) - HV(hm,0, i,   1+j, 1+k));

    float ua = (HV(hm,2, 2+i,1+j,k+1) - HV(hm,2, 1+i,1+j,k+1)) - (HV(hm,1, 1+i,2+j,k+1) - HV(hm,1, 1+i,1+j,k+1));
    float ub = (HV(hm,2, 2+i,1+j,k  ) - HV(hm,2, 1+i,1+j,k  )) - (HV(hm,1, 1+i,2+j,k  ) - HV(hm,1, 1+i,1+j,k  ));
    float vv0 = 0.5f * (ua + ub);
    float va = (HV(hm,1, 1+i,j+1,k+2) - HV(hm,1, 1+i,j+1,k+1)) - (HV(hm,3, i+2,j+1,k+1) - HV(hm,3, i+1,j+1,k+1));
    float vb = (HV(hm,1, 1+i,j,  k+2) - HV(hm,1, 1+i,j,  k+1)) - (HV(hm,3, i+2,j,  k+1) - HV(hm,3, i+1,j,  k+1));
    float vv1 = 0.5f * (va + vb);
    float wa = (HV(hm,3, i+1,j+2,k+1) - HV(hm,3, i+1,j+1,k+1)) - (HV(hm,2, i+1,j+1,k+2) - HV(hm,2, i+1,j+1,k+1));
    float wb = (HV(hm,3, i,  j+2,k+1) - HV(hm,3, i,  j+1,k+1)) - (HV(hm,2, i,  j+1,k+2) - HV(hm,2, i,  j+1,k+1));
    float vv2 = 0.5f * (wa + wb);

    int b = n*3*D3 + p;
    out[OFF_VPHI  + b        ] = vp0;
    out[OFF_VPHI  + b + D3   ] = vp1;
    out[OFF_VPHI  + b + 2*D3 ] = vp2;
    out[OFF_VVORT + b        ] = vv0;
    out[OFF_VVORT + b + D3   ] = vv1;
    out[OFF_VVORT + b + 2*D3 ] = vv2;
    out[OFF_VEL   + b        ] = vp0 + vv0;
    out[OFF_VEL   + b + D3   ] = vp1 + vv1;
    out[OFF_VEL   + b + 2*D3 ] = vp2 + vv2;
}

// ---------------- BFECC advect passes ----------------
__global__ void advect_kernel(const float* __restrict__ ext_src, const float* __restrict__ tex,
                              const float* __restrict__ vel, float sgn, int mode) {
    int idx = blockIdx.x * blockDim.x + threadIdx.x;
    if (idx >= NB*D3) return;
    int p = idx % D3; int n = idx / D3;
    int k = p & 63, j = (p >> 6) & 63, i = p >> 12;

    float v0 = vel[(n*3    )*D3 + p];
    float v1 = vel[(n*3 + 1)*D3 + p];
    float v2 = vel[(n*3 + 2)*D3 + p];
    float px = (float)i - sgn*v2;
    float py = (float)j - sgn*v1;
    float pz = (float)k - sgn*v0;
    px = fminf(fmaxf(px, 0.f), 63.f);
    py = fminf(fmaxf(py, 0.f), 63.f);
    pz = fminf(fmaxf(pz, 0.f), 63.f);
    int x0 = (int)px; float fx = px - x0; int x1 = min(x0+1, 63);
    int y0 = (int)py; float fy = py - y0; int y1 = min(y0+1, 63);
    int z0 = (int)pz; float fz = pz - z0; int z1 = min(z0+1, 63);

    float w000 = (1-fx)*(1-fy)*(1-fz), w001 = (1-fx)*(1-fy)*fz;
    float w010 = (1-fx)*fy*(1-fz),     w011 = (1-fx)*fy*fz;
    float w100 = fx*(1-fy)*(1-fz),     w101 = fx*(1-fy)*fz;
    float w110 = fx*fy*(1-fz),         w111 = fx*fy*fz;

    int b00 = (x0*64 + y0)*64, b01 = (x0*64 + y1)*64;
    int b10 = (x1*64 + y0)*64, b11 = (x1*64 + y1)*64;

    const float* src = (mode == 0) ? ext_src : ((mode == 1) ? g_phi1 : g_comb);
    float* dst = (mode == 0) ? g_phi1 : ((mode == 1) ? g_comb : g_pred);

#pragma unroll
    for (int c = 0; c < 8; c++) {
        const float* s = src + (n*8 + c)*D3;
        float v = w000*s[b00+z0] + w001*s[b00+z1] + w010*s[b01+z0] + w011*s[b01+z1]
                + w100*s[b10+z0] + w101*s[b10+z1] + w110*s[b11+z0] + w111*s[b11+z1];
        if (mode == 1) v = 1.5f * tex[(n*8 + c)*D3 + p] - 0.5f * v;
        dst[(n*8 + c)*D3 + p] = v;
    }
}

// ---------------- fused LN + FF (LN, @W1+b1, GELU, @W2+b2, residual -> d_out) ----------------
__global__ void ff_kernel(const float* __restrict__ lng, const float* __restrict__ lnb,
                          const float* __restrict__ w1, const float* __restrict__ b1,
                          const float* __restrict__ w2, const float* __restrict__ b2,
                          float* __restrict__ out) {
    __shared__ __align__(16) unsigned long long Wp1[2048];
    __shared__ __align__(16) unsigned long long Wp2[2048];
    __shared__ float Bv1[64], Bv2[64], G[64], Bt[64];
    float* fW1 = reinterpret_cast<float*>(Wp1);
    float* fW2 = reinterpret_cast<float*>(Wp2);
    for (int i = threadIdx.x; i < 4096; i += blockDim.x) {
        int ii = i >> 6, jj = i & 63;
        int d = (jj*32 + (ii >> 1))*2 + (ii & 1);
        fW1[d] = w1[i];
        fW2[d] = w2[i];
    }
    if (threadIdx.x < 64) {
        Bv1[threadIdx.x] = b1[threadIdx.x]; Bv2[threadIdx.x] = b2[threadIdx.x];
        G[threadIdx.x] = lng[threadIdx.x];  Bt[threadIdx.x] = lnb[threadIdx.x];
    }
    __syncthreads();

    int p = blockIdx.x * blockDim.x + threadIdx.x;
    if (p >= D3) return;

    float h[64]; float s = 0.f, s2 = 0.f;
#pragma unroll
    for (int c = 0; c < 64; c++) { float v = g_pred[c*D3 + p]; h[c] = v; s += v; s2 += v*v; }
    float mean = s * (1.f/64.f);
    float var  = s2 * (1.f/64.f) - mean*mean;
    float is = rsqrtf(var + 1e-5f);
    unsigned long long hp[32];
#pragma unroll
    for (int c = 0; c < 32; c++) {
        float e = (h[2*c]   - mean) * is * G[2*c]   + Bt[2*c];
        float o = (h[2*c+1] - mean) * is * G[2*c+1] + Bt[2*c+1];
        hp[c] = pk2(e, o);
    }

    unsigned long long gp[32];
    for (int jj = 0; jj < 64; jj += 2) {
        const ulonglong2* wrA = reinterpret_cast<const ulonglong2*>(Wp1 + jj*32);
        const ulonglong2* wrB = reinterpret_cast<const ulonglong2*>(Wp1 + (jj+1)*32);
        unsigned long long a0 = 0ULL, a1 = 0ULL, c0 = 0ULL, c1 = 0ULL;
#pragma unroll
        for (int q = 0; q < 16; q++) {
            ulonglong2 wa = wrA[q];
            ulonglong2 wb = wrB[q];
            fma2(a0, hp[2*q],   wa.x);
            fma2(a1, hp[2*q+1], wa.y);
            fma2(c0, hp[2*q],   wb.x);
            fma2(c1, hp[2*q+1], wb.y);
        }
        float l0, h0, l1, h1;
        upk2(a0, l0, h0); upk2(a1, l1, h1);
        float aA = Bv1[jj] + ((l0 + h0) + (l1 + h1));
        upk2(c0, l0, h0); upk2(c1, l1, h1);
        float aB = Bv1[jj+1] + ((l0 + h0) + (l1 + h1));
        float gA = 0.5f * aA * (1.f + erff(aA * 0.70710678118f));
        float gB = 0.5f * aB * (1.f + erff(aB * 0.70710678118f));
        gp[jj >> 1] = pk2(gA, gB);
    }

    for (int jj = 0; jj < 64; jj++) {
        const ulonglong2* wr = reinterpret_cast<const ulonglong2*>(Wp2 + jj*32);
        unsigned long long a0 = 0ULL, a1 = 0ULL;
#pragma unroll
        for (int q = 0; q < 16; q++) {
            ulonglong2 w2v = wr[q];
            fma2(a0, gp[2*q],   w2v.x);
            fma2(a1, gp[2*q+1], w2v.y);
        }
        float l0, h0, l1, h1;
        upk2(a0, l0, h0); upk2(a1, l1, h1);
        float a = Bv2[jj] + ((l0 + h0) + (l1 + h1));
        out[OFF_X + jj*D3 + p] = g_pred[jj*D3 + p] + a;
    }
}

// ---------------- host launch ----------------
extern "C" void kernel_launch(void* const* d_in, const int* in_sizes, int n_in,
                              void* d_out, int out_size) {
    const float* prev      = (const float*)d_in[0];
    const float* nxt       = (const float*)d_in[1];
    const float* texture   = (const float*)d_in[2];
    const float* mask      = (const float*)d_in[3];
    const float* boundary  = (const float*)d_in[4];
    const float* enc_w     = (const float*)d_in[5];
    const float* enc_b     = (const float*)d_in[6];
    const float* phi_c1_w  = (const float*)d_in[7];
    const float* phi_bn1_g = (const float*)d_in[8];
    const float* phi_bn1_b = (const float*)d_in[9];
    const float* phi_c2_w  = (const float*)d_in[10];
    const float* phi_bn2_g = (const float*)d_in[11];
    const float* phi_bn2_b = (const float*)d_in[12];
    const float* phi_out_w = (const float*)d_in[13];
    const float* phi_out_b = (const float*)d_in[14];
    const float* vort_c1_w = (const float*)d_in[15];
    const float* vort_bn1_g= (const float*)d_in[16];
    const float* vort_bn1_b= (const float*)d_in[17];
    const float* vort_c2_w = (const float*)d_in[18];
    const float* vort_bn2_g= (const float*)d_in[19];
    const float* vort_bn2_b= (const float*)d_in[20];
    const float* vort_out_w= (const float*)d_in[21];
    const float* vort_out_b= (const float*)d_in[22];
    const float* phi_weight= (const float*)d_in[23];
    const float* vort_weight=(const float*)d_in[24];
    const float* ln_g      = (const float*)d_in[25];
    const float* ln_b      = (const float*)d_in[26];
    const float* ff_w1     = (const float*)d_in[27];
    const float* ff_b1     = (const float*)d_in[28];
    const float* ff_w2     = (const float*)d_in[29];
    const float* ff_b2     = (const float*)d_in[30];
    float* out = (float*)d_out;

    pack_kernel<<<(3*WC1_PACK + 255)/256, 256>>>(phi_c1_w, vort_c1_w, phi_c2_w, vort_c2_w);

    int encBlocks = (NB*H3 + 255)/256;
    enc_kernel<<<encBlocks, 256>>>(prev, mask,     enc_w, enc_b, 0);
    enc_kernel<<<encBlocks, 256>>>(prev, boundary, enc_w, enc_b, 1);
    enc_kernel<<<encBlocks, 256>>>(nxt,  mask,     enc_w, enc_b, 2);

    corr_kernel<<<(NB*H3 + 255)/256, 256>>>();

    cudaFuncSetAttribute(conv1_kernel, cudaFuncAttributeMaxDynamicSharedMemorySize, 3*WC1_PACK*4);
    conv1_kernel<<<NBLK1, 256, 3*WC1_PACK*4>>>();
    stats_reduce<<<16, 256>>>(0);

    int upN = NB*16*S3;
    upsample_kernel<<<(upN + 255)/256, 256>>>(phi_bn1_g, phi_bn1_b, vort_bn1_g, vort_bn1_b);

    conv2_kernel<<<NBLK2, 256>>>();
    stats_reduce<<<16, 256>>>(1);

    helm_kernel<<<(NB*S3 + 255)/256, 256>>>(phi_bn2_g, phi_bn2_b, vort_bn2_g, vort_bn2_b,
                                            phi_out_w, phi_out_b, vort_out_w, vort_out_b,
                                            phi_weight, vort_weight, out);

    vel_kernel<<<(NB*D3 + 255)/256, 256>>>(out);

    const float* vel = out + OFF_VEL;
    advect_kernel<<<(NB*D3 + 255)/256, 256>>>(texture, texture, vel,  1.f, 0);
    advect_kernel<<<(NB*D3 + 255)/256, 256>>>(texture, texture, vel, -1.f, 1);
    advect_kernel<<<(NB*D3 + 255)/256, 256>>>(texture, texture, vel,  1.f, 2);

    ff_kernel<<<(D3 + 127)/128, 128>>>(ln_g, ln_b, ff_w1, ff_b1, ff_w2, ff_b2, out);
}

// round 15
// speedup vs baseline: 1.2729x; 1.0142x over previous
#include <cuda_runtime.h>
#include <math.h>

// ---------------- dimensions ----------------
#define NB 8          // batch*groups
#define S  66
#define S2 4356       // 66*66
#define S3 287496     // 66^3
#define HH 33
#define H2 1089       // 33*33
#define H3 35937      // 33^3
#define D3 262144     // 64^3

// output packing offsets (x, helmholtz, vel, vel_phi, vel_vort)
#define OFF_X     0
#define OFF_HELM  16777216
#define OFF_VEL   25977088
#define OFF_VPHI  32268544
#define OFF_VVORT 38560000

#define WC1_PACK 7776          // 18*27*16
#define NBLK1 1124             // conv1 blocks: ceil(NB*H3/256)
#define NBLK2 2995             // conv2 blocks: ceil(NB*66*66*22/256)
#define ENC_BPN 562            // ceil(H3/64)

// ---------------- scratch (static device memory; no allocation APIs) ----------------
__device__ float g_f[3][NB*64*H3];     // encoder outputs: pm, pb, nm
__device__ float g_corr[NB*18*H3];     // correlation output (18 distinct channels)
__device__ float g_c1[NB*16*H3];       // conv1 raw out (phi 0-7, vort 8-15)
__device__ float g_u1[NB*16*S3];       // upsampled (post BN1+relu)
__device__ float g_c2[NB*16*S3];       // conv2 raw out
__device__ float g_phi1[64*D3];        // advect pass 1
__device__ float g_comb[64*D3];        // 1.5*tex - 0.5*phi2
__device__ float g_pred[64*D3];        // final advect result
__device__ float g_wc1[3*WC1_PACK];    // conv1 summed packs
__device__ float g_wp2[27*8*16];       // packed conv2 weights
__device__ float g_stat[64];           // mean1[16], istd1[16], mean2[16], istd2[16]
__device__ double g_pc1[16*NBLK1*2];   // conv1 per-block stat partials
__device__ double g_pc2[16*NBLK2*2];   // conv2 per-block stat partials

// ---------------- packed f32x2 helpers (sm_103a FFMA2 via PTX) ----------------
__device__ __forceinline__ unsigned long long pk2(float a, float b) {
    unsigned long long r;
    asm("mov.b64 %0, {%1, %2};" : "=l"(r) : "f"(a), "f"(b));
    return r;
}
__device__ __forceinline__ void fma2(unsigned long long& d, unsigned long long a, unsigned long long b) {
    asm("fma.rn.f32x2 %0, %1, %2, %0;" : "+l"(d) : "l"(a), "l"(b));
}
__device__ __forceinline__ void upk2(unsigned long long v, float& lo, float& hi) {
    asm("mov.b64 {%0, %1}, %2;" : "=f"(lo), "=f"(hi) : "l"(v));
}
__device__ __forceinline__ float wred(float v) {
#pragma unroll
    for (int o = 16; o > 0; o >>= 1) v += __shfl_down_sync(0xffffffffu, v, o);
    return v;
}

// ---------------- weight packing ----------------
__global__ void pack_kernel(const float* __restrict__ pw1, const float* __restrict__ vw1,
                            const float* __restrict__ pw2, const float* __restrict__ vw2) {
    int i = blockIdx.x * blockDim.x + threadIdx.x;
    if (i < 3*WC1_PACK) {
        int pack = i / WC1_PACK; int r = i % WC1_PACK;
        int oc = r & 15; int t18 = r >> 4; int ic = t18 % 18; int tap = t18 / 18;
        int w = ic / 9, s = ic % 9;
        int c0 = w*27 + s, c1 = c0 + 9, c2 = c0 + 18;
        const float* src = (oc < 8) ? pw1 : vw1;
        int o = (oc < 8) ? oc : oc - 8;
        float W0 = src[(o*54 + c0)*27 + tap];
        float W1 = src[(o*54 + c1)*27 + tap];
        float W2 = src[(o*54 + c2)*27 + tap];
        float v = (pack == 0) ? (W0 + W1 + W2) : ((pack == 1) ? (W0 + W1) : (W1 + W2));
        g_wc1[i] = v;
    }
    if (i < 27*8*16) {
        int oc = i & 15; int icg = (i >> 4) % 8; int t = (i >> 4) / 8;
        g_wp2[i] = (oc < 8) ? pw2[(oc*8 + icg)*27 + t] : vw2[((oc-8)*8 + icg)*27 + t];
    }
}

// ---------------- encoder as smem-tiled GEMM: 64-pos x 64-oc tile, 4x4 register blocks ----------------
__global__ __launch_bounds__(256) void enc_kernel(const float* __restrict__ src, const float* __restrict__ mul,
                                                  const float* __restrict__ w, const float* __restrict__ b, int variant) {
    __shared__ __align__(16) float ws[64*68];
    __shared__ __align__(16) float xs[64*68];
    __shared__ float bs[64];
    int tid = threadIdx.x;
    for (int i = tid; i < 4096; i += 256) ws[(i >> 6)*68 + (i & 63)] = w[i];
    if (tid < 64) bs[tid] = b[tid];

    int n  = blockIdx.x / ENC_BPN;
    int p0 = (blockIdx.x % ENC_BPN) * 64;

    // staging: 4 threads per position, 16 k-values each (2 ic x 8 taps)
    {
        int pl = tid >> 2;
        int p = p0 + pl;
        int kc = (tid & 3) << 4;
        float vals[16];
        if (p < H3) {
            int z = p % HH, y = (p / HH) % HH, x = p / H2;
            int base0 = ((2*x)*S + (2*y))*S + (2*z);
            float m[8];
#pragma unroll
            for (int t = 0; t < 8; t++) {
                int dx = t >> 2, dy = (t >> 1) & 1, dz = t & 1;
                m[t] = mul[base0 + (dx*S + dy)*S + dz];
            }
#pragma unroll
            for (int q = 0; q < 16; q++) {
                int k = kc + q; int ic = k >> 3; int t = k & 7;
                int dx = t >> 2, dy = (t >> 1) & 1, dz = t & 1;
                vals[q] = src[(n*8 + ic)*S3 + base0 + (dx*S + dy)*S + dz] * m[t];
            }
        } else {
#pragma unroll
            for (int q = 0; q < 16; q++) vals[q] = 0.f;
        }
#pragma unroll
        for (int q = 0; q < 16; q++) xs[pl*68 + kc + q] = vals[q];
    }
    __syncthreads();

    // compute: thread (pg, og) -> positions pg+16r, output channels og*4+c
    int pg = tid & 15, og = tid >> 4;
    int ocb = og * 4;
    unsigned long long acc[4][4];
#pragma unroll
    for (int r = 0; r < 4; r++)
#pragma unroll
        for (int c = 0; c < 4; c++) acc[r][c] = 0ULL;

    for (int kk = 0; kk < 64; kk += 4) {
        ulonglong2 xv[4], wv[4];
#pragma unroll
        for (int r = 0; r < 4; r++)
            xv[r] = *reinterpret_cast<const ulonglong2*>(&xs[(pg + 16*r)*68 + kk]);
#pragma unroll
        for (int c = 0; c < 4; c++)
            wv[c] = *reinterpret_cast<const ulonglong2*>(&ws[(ocb + c)*68 + kk]);
#pragma unroll
        for (int r = 0; r < 4; r++)
#pragma unroll
            for (int c = 0; c < 4; c++) {
                fma2(acc[r][c], xv[r].x, wv[c].x);
                fma2(acc[r][c], xv[r].y, wv[c].y);
            }
    }

    float* outp = &g_f[variant][(n*64)*H3];
#pragma unroll
    for (int r = 0; r < 4; r++) {
        int p = p0 + pg + 16*r;
        if (p >= H3) continue;
#pragma unroll
        for (int c = 0; c < 4; c++) {
            float lo, hi;
            upk2(acc[r][c], lo, hi);
            outp[(ocb + c)*H3 + p] = bs[ocb + c] + lo + hi;
        }
    }
}

// ---------------- correlation: 18 distinct channels, s-pair f32x2 ----------------
__global__ void corr_kernel() {
    int idx = blockIdx.x * blockDim.x + threadIdx.x;
    if (idx >= NB*H3) return;
    int p = idx % H3; int n = idx / H3;
    int y = (p / HH) % HH, x = p / H2;

    const float* A0 = &g_f[0][n*64*H3 + p];
    const float* A1 = &g_f[1][n*64*H3 + p];
    const float* B  = &g_f[2][n*64*H3 + p];

    int off[9]; bool ok[9];
    {
        int s = 0;
        for (int di = -1; di <= 1; di++)
            for (int dj = -1; dj <= 1; dj++) {
                ok[s] = (x+di >= 0 && x+di < HH && y+dj >= 0 && y+dj < HH);
                off[s] = (di*HH + dj)*HH;
                s++;
            }
    }
    unsigned long long acc2[9];
#pragma unroll
    for (int s = 0; s < 9; s++) acc2[s] = 0ULL;

    for (int c = 0; c < 64; c++) {
        unsigned long long a2 = pk2(A0[c*H3], A1[c*H3]);
        const float* Bc = B + c*H3;
#pragma unroll
        for (int s = 0; s < 9; s++) {
            float bv = ok[s] ? Bc[off[s]] : 0.f;
            fma2(acc2[s], pk2(bv, bv), a2);
        }
    }
#pragma unroll
    for (int s = 0; s < 9; s++) {
        float a, bqq;
        upk2(acc2[s], a, bqq);
        g_corr[(n*18 + s    )*H3 + p] = a   * (1.f/64.f);
        g_corr[(n*18 + 9 + s)*H3 + p] = bqq * (1.f/64.f);
    }
}

// ---------------- conv1: effective 18 -> 16, with fused BN stat partials ----------------
__global__ void conv1_kernel() {
    extern __shared__ float ws[];
    __shared__ double sW[8][16][2];
    for (int i = threadIdx.x; i < 3*WC1_PACK; i += blockDim.x) ws[i] = g_wc1[i];
    __syncthreads();

    int idx = blockIdx.x * blockDim.x + threadIdx.x;
    bool valid = (idx < NB*H3);
    int p = 0, n = 0, z = 0, y = 0, x = 0;
    if (valid) {
        p = idx % H3; n = idx / H3;
        z = p % HH; y = (p / HH) % HH; x = p / H2;
    }

    unsigned long long acc2[8];
#pragma unroll
    for (int i = 0; i < 8; i++) acc2[i] = 0ULL;

    if (valid) {
        const float* cbase = g_corr + n*18*H3;
        for (int tap = 0; tap < 27; tap++) {
            int dx = tap/9 - 1, dy = (tap/3)%3 - 1, dz = tap%3 - 1;
            int xx = x+dx, yy = y+dy, zz = z+dz;
            if ((unsigned)xx >= (unsigned)HH || (unsigned)yy >= (unsigned)HH || (unsigned)zz >= (unsigned)HH) continue;
            int q = (xx*HH + yy)*HH + zz;
            int sel = (zz == 0) ? 1 : ((zz == HH-1) ? 2 : 0);
            const float* wt = ws + sel*WC1_PACK + tap*288;
#pragma unroll
            for (int ic = 0; ic < 18; ic++) {
                float v = cbase[ic*H3 + q];
                unsigned long long v2 = pk2(v, v);
                const ulonglong2* wp = reinterpret_cast<const ulonglong2*>(wt + (ic << 4));
                ulonglong2 w01 = wp[0], w23 = wp[1], w45 = wp[2], w67 = wp[3];
                fma2(acc2[0], v2, w01.x); fma2(acc2[1], v2, w01.y);
                fma2(acc2[2], v2, w23.x); fma2(acc2[3], v2, w23.y);
                fma2(acc2[4], v2, w45.x); fma2(acc2[5], v2, w45.y);
                fma2(acc2[6], v2, w67.x); fma2(acc2[7], v2, w67.y);
            }
        }
    }

    int warp = threadIdx.x >> 5;
#pragma unroll
    for (int j = 0; j < 8; j++) {
        float lo = 0.f, hi = 0.f;
        upk2(acc2[j], lo, hi);
        if (!valid) { lo = 0.f; hi = 0.f; }
        if (valid) {
            g_c1[(n*16 + 2*j    )*H3 + p] = lo;
            g_c1[(n*16 + 2*j + 1)*H3 + p] = hi;
        }
        float sl = wred(lo), s2l = wred(lo*lo);
        float sh = wred(hi), s2h = wred(hi*hi);
        if ((threadIdx.x & 31) == 0) {
            sW[warp][2*j  ][0] = (double)sl; sW[warp][2*j  ][1] = (double)s2l;
            sW[warp][2*j+1][0] = (double)sh; sW[warp][2*j+1][1] = (double)s2h;
        }
        __syncwarp();
    }
    __syncthreads();
    if (threadIdx.x < 16) {
        double s = 0.0, s2 = 0.0;
        for (int wi = 0; wi < 8; wi++) { s += sW[wi][threadIdx.x][0]; s2 += sW[wi][threadIdx.x][1]; }
        g_pc1[(threadIdx.x*NBLK1 + blockIdx.x)*2 + 0] = s;
        g_pc1[(threadIdx.x*NBLK1 + blockIdx.x)*2 + 1] = s2;
    }
}

// ---------------- stats reduce: per-channel partial sums -> mean/istd ----------------
__global__ void stats_reduce(int phase) {
    int ch = blockIdx.x;
    int NP = phase ? NBLK2 : NBLK1;
    const double* src = phase ? g_pc2 : g_pc1;
    __shared__ double sh[256], sh2[256];
    double s = 0.0, s2 = 0.0;
    for (int i = threadIdx.x; i < NP; i += 256) {
        s  += src[(ch*NP + i)*2 + 0];
        s2 += src[(ch*NP + i)*2 + 1];
    }
    sh[threadIdx.x] = s; sh2[threadIdx.x] = s2;
    __syncthreads();
    for (int st = 128; st > 0; st >>= 1) {
        if (threadIdx.x < st) { sh[threadIdx.x] += sh[threadIdx.x+st]; sh2[threadIdx.x] += sh2[threadIdx.x+st]; }
        __syncthreads();
    }
    if (threadIdx.x == 0) {
        double total = (double)NB * (phase ? S3 : H3);
        double mean = sh[0] / total;
        double var  = sh2[0] / total - mean*mean;
        g_stat[phase*32 + ch]      = (float)mean;
        g_stat[phase*32 + 16 + ch] = (float)(1.0 / sqrt(var + 1e-5));
    }
}

// ---------------- BN1 + relu + trilinear upsample x2 (align_corners) ----------------
__device__ __forceinline__ float bnrelu(float v, float sc, float sh) { return fmaxf(v*sc + sh, 0.f); }

__global__ void upsample_kernel(const float* __restrict__ g1p, const float* __restrict__ b1p,
                                const float* __restrict__ g1v, const float* __restrict__ b1v) {
    int idx = blockIdx.x * blockDim.x + threadIdx.x;
    if (idx >= NB*16*S3) return;
    int p = idx % S3; int ch = (idx / S3) % 16; int n = idx / (16*S3);
    int Z = p % S, Y = (p / S) % S, X = p / S2;

    float mean = g_stat[ch], istd = g_stat[16 + ch];
    float gg = (ch < 8) ? g1p[ch] : g1v[ch-8];
    float bb = (ch < 8) ? b1p[ch] : b1v[ch-8];
    float sc = istd * gg, sh = bb - mean * sc;

    const float SC = 32.f / 65.f;
    float sx = X * SC; int x0 = (int)sx; float fx = sx - x0; int x1 = min(x0+1, 32);
    float sy = Y * SC; int y0 = (int)sy; float fy = sy - y0; int y1 = min(y0+1, 32);
    float sz = Z * SC; int z0 = (int)sz; float fz = sz - z0; int z1 = min(z0+1, 32);

    const float* base = g_c1 + (n*16 + ch)*H3;
#define RD(xi,yi,zi) bnrelu(base[((xi)*HH+(yi))*HH+(zi)], sc, sh)
    float v =
      ((RD(x0,y0,z0)*(1-fx) + RD(x1,y0,z0)*fx)*(1-fy) + (RD(x0,y1,z0)*(1-fx) + RD(x1,y1,z0)*fx)*fy)*(1-fz)
    + ((RD(x0,y0,z1)*(1-fx) + RD(x1,y0,z1)*fx)*(1-fy) + (RD(x0,y1,z1)*(1-fx) + RD(x1,y1,z1)*fx)*fy)*fz;
#undef RD
    g_u1[idx] = v;
}

// ---------------- conv2: grouped 2x(8->8), z-vec x3, f32x2, fused BN stat partials ----------------
__global__ void conv2_kernel() {
    __shared__ __align__(16) float ws[27*8*16];
    __shared__ double sW[8][16][2];
    for (int i = threadIdx.x; i < 27*8*16; i += blockDim.x) ws[i] = g_wp2[i];
    __syncthreads();

    int idx = blockIdx.x * blockDim.x + threadIdx.x;
    bool valid = (idx < NB*S*S*22);
    int zt = 0, y = 0, x = 0, n = 0;
    if (valid) {
        zt = idx % 22;
        y  = (idx / 22) % S;
        x  = (idx / (22*S)) % S;
        n  = idx / (22*S*S);
    }
    int z0 = 3*zt;

    unsigned long long acc2[3][8];
#pragma unroll
    for (int pp = 0; pp < 3; pp++)
#pragma unroll
        for (int i = 0; i < 8; i++) acc2[pp][i] = 0ULL;

    if (valid) {
        const float* ubase = g_u1 + n*16*S3;
        bool zlo = (zt == 0);
        bool zhi = (zt == 21);

#pragma unroll
        for (int dx = -1; dx <= 1; dx++) {
            int xx = x + dx;
            if ((unsigned)xx >= (unsigned)S) continue;
#pragma unroll
            for (int dy = -1; dy <= 1; dy++) {
                int yy = y + dy;
                if ((unsigned)yy >= (unsigned)S) continue;
                int tap0 = ((dx+1)*3 + (dy+1))*3;
                const float* col = ubase + (xx*S + yy)*S + z0;
#pragma unroll
                for (int icg = 0; icg < 8; icg++) {
                    const float* cp = col + icg*S3;
                    const float* cv = col + (8+icg)*S3;
                    float inp[5], inv[5];
                    inp[0] = zlo ? 0.f : cp[-1];  inv[0] = zlo ? 0.f : cv[-1];
                    inp[1] = cp[0];               inv[1] = cv[0];
                    inp[2] = cp[1];               inv[2] = cv[1];
                    inp[3] = cp[2];               inv[3] = cv[2];
                    inp[4] = zhi ? 0.f : cp[3];   inv[4] = zhi ? 0.f : cv[3];
                    unsigned long long ip2[5], iv2[5];
#pragma unroll
                    for (int t = 0; t < 5; t++) { ip2[t] = pk2(inp[t], inp[t]); iv2[t] = pk2(inv[t], inv[t]); }
#pragma unroll
                    for (int dz = 0; dz < 3; dz++) {
                        const ulonglong2* wp =
                            reinterpret_cast<const ulonglong2*>(ws + (((tap0+dz)*8 + icg) << 4));
                        ulonglong2 w01 = wp[0], w23 = wp[1], w45 = wp[2], w67 = wp[3];
#pragma unroll
                        for (int pp = 0; pp < 3; pp++) {
                            unsigned long long vp = ip2[pp+dz];
                            unsigned long long vv = iv2[pp+dz];
                            fma2(acc2[pp][0], vp, w01.x); fma2(acc2[pp][1], vp, w01.y);
                            fma2(acc2[pp][2], vp, w23.x); fma2(acc2[pp][3], vp, w23.y);
                            fma2(acc2[pp][4], vv, w45.x); fma2(acc2[pp][5], vv, w45.y);
                            fma2(acc2[pp][6], vv, w67.x); fma2(acc2[pp][7], vv, w67.y);
                        }
                    }
                }
            }
        }
    }

    int ob = (x*S + y)*S + z0;
    int warp = threadIdx.x >> 5;
#pragma unroll
    for (int j = 0; j < 8; j++) {
        float sLo = 0.f, s2Lo = 0.f, sHi = 0.f, s2Hi = 0.f;
#pragma unroll
        for (int pp = 0; pp < 3; pp++) {
            float lo, hi;
            upk2(acc2[pp][j], lo, hi);
            if (valid) {
                g_c2[(n*16 + 2*j    )*S3 + ob + pp] = lo;
                g_c2[(n*16 + 2*j + 1)*S3 + ob + pp] = hi;
                sLo += lo; s2Lo += lo*lo;
                sHi += hi; s2Hi += hi*hi;
            }
        }
        float a = wred(sLo), b = wred(s2Lo);
        float c = wred(sHi), d = wred(s2Hi);
        if ((threadIdx.x & 31) == 0) {
            sW[warp][2*j  ][0] = (double)a; sW[warp][2*j  ][1] = (double)b;
            sW[warp][2*j+1][0] = (double)c; sW[warp][2*j+1][1] = (double)d;
        }
        __syncwarp();
    }
    __syncthreads();
    if (threadIdx.x < 16) {
        double s = 0.0, s2 = 0.0;
        for (int wi = 0; wi < 8; wi++) { s += sW[wi][threadIdx.x][0]; s2 += sW[wi][threadIdx.x][1]; }
        g_pc2[(threadIdx.x*NBLK2 + blockIdx.x)*2 + 0] = s;
        g_pc2[(threadIdx.x*NBLK2 + blockIdx.x)*2 + 1] = s2;
    }
}

// ---------------- BN2 + relu + 1x1 heads -> helmholtz (into d_out) ----------------
__global__ void helm_kernel(const float* __restrict__ g2p, const float* __restrict__ b2p,
                            const float* __restrict__ g2v, const float* __restrict__ b2v,
                            const float* __restrict__ pow_, const float* __restrict__ pob,
                            const float* __restrict__ vow,  const float* __restrict__ vob,
                            const float* __restrict__ phiw, const float* __restrict__ vortw,
                            float* __restrict__ out) {
    int idx = blockIdx.x * blockDim.x + threadIdx.x;
    if (idx >= NB*S3) return;
    int p = idx % S3; int n = idx / S3;

    float y[16];
#pragma unroll
    for (int c = 0; c < 16; c++) {
        float mean = g_stat[32 + c], istd = g_stat[48 + c];
        float gg = (c < 8) ? g2p[c] : g2v[c-8];
        float bb = (c < 8) ? b2p[c] : b2v[c-8];
        float v = (g_c2[(n*16 + c)*S3 + p] - mean) * istd * gg + bb;
        y[c] = fmaxf(v, 0.f);
    }
    float ph = pob[0];
#pragma unroll
    for (int c = 0; c < 8; c++) ph += y[c] * pow_[c];
    ph *= phiw[0];
    out[OFF_HELM + (n*4)*S3 + p] = ph;
    float vscale = vortw[0] * 66.f;
#pragma unroll
    for (int r = 0; r < 3; r++) {
        float v = vob[r];
#pragma unroll
        for (int c = 0; c < 8; c++) v += y[8+c] * vow[r*8 + c];
        out[OFF_HELM + (n*4 + 1 + r)*S3 + p] = v * vscale;
    }
}

// ---------------- velocity stencils (into d_out) ----------------
__device__ __forceinline__ float HV(const float* hm, int ch, int x, int y, int z) {
    return hm[ch*S3 + (x*S + y)*S + z];
}

__global__ void vel_kernel(float* __restrict__ out) {
    int idx = blockIdx.x * blockDim.x + threadIdx.x;
    if (idx >= NB*D3) return;
    int p = idx % D3; int n = idx / D3;
    int k = p & 63, j = (p >> 6) & 63, i = p >> 12;
    const float* hm = out + OFF_HELM + n*4*S3;

    float vp0 = 0.5f * (HV(hm,0, 1+i, 1+j, k+2) - HV(hm,0, 1+i, 1+j, k));
    float vp1 = 0.5f * (HV(hm,0, 1+i, j+2, 1+k) - HV(hm,0, 1+i, j,   1+k));
    float vp2 = 0.5f * (HV(hm,0, i+2, 1+j, 1+k) - HV(hm,0, i,   1+j, 1+k));

    float ua = (HV(hm,2, 2+i,1+j,k+1) - HV(hm,2, 1+i,1+j,k+1)) - (HV(hm,1, 1+i,2+j,k+1) - HV(hm,1, 1+i,1+j,k+1));
    float ub = (HV(hm,2, 2+i,1+j,k  ) - HV(hm,2, 1+i,1+j,k  )) - (HV(hm,1, 1+i,2+j,k  ) - HV(hm,1, 1+i,1+j,k  ));
    float vv0 = 0.5f * (ua + ub);
    float va = (HV(hm,1, 1+i,j+1,k+2) - HV(hm,1, 1+i,j+1,k+1)) - (HV(hm,3, i+2,j+1,k+1) - HV(hm,3, i+1,j+1,k+1));
    float vb = (HV(hm,1, 1+i,j,  k+2) - HV(hm,1, 1+i,j,  k+1)) - (HV(hm,3, i+2,j,  k+1) - HV(hm,3, i+1,j,  k+1));
    float vv1 = 0.5f * (va + vb);
    float wa = (HV(hm,3, i+1,j+2,k+1) - HV(hm,3, i+1,j+1,k+1)) - (HV(hm,2, i+1,j+1,k+2) - HV(hm,2, i+1,j+1,k+1));
    float wb = (HV(hm,3, i,  j+2,k+1) - HV(hm,3, i,  j+1,k+1)) - (HV(hm,2, i,  j+1,k+2) - HV(hm,2, i,  j+1,k+1));
    float vv2 = 0.5f * (wa + wb);

    int b = n*3*D3 + p;
    out[OFF_VPHI  + b        ] = vp0;
    out[OFF_VPHI  + b + D3   ] = vp1;
    out[OFF_VPHI  + b + 2*D3 ] = vp2;
    out[OFF_VVORT + b        ] = vv0;
    out[OFF_VVORT + b + D3   ] = vv1;
    out[OFF_VVORT + b + 2*D3 ] = vv2;
    out[OFF_VEL   + b        ] = vp0 + vv0;
    out[OFF_VEL   + b + D3   ] = vp1 + vv1;
    out[OFF_VEL   + b + 2*D3 ] = vp2 + vv2;
}

// ---------------- BFECC advect passes ----------------
__global__ void advect_kernel(const float* __restrict__ ext_src, const float* __restrict__ tex,
                              const float* __restrict__ vel, float sgn, int mode) {
    int idx = blockIdx.x * blockDim.x + threadIdx.x;
    if (idx >= NB*D3) return;
    int p = idx % D3; int n = idx / D3;
    int k = p & 63, j = (p >> 6) & 63, i = p >> 12;

    float v0 = vel[(n*3    )*D3 + p];
    float v1 = vel[(n*3 + 1)*D3 + p];
    float v2 = vel[(n*3 + 2)*D3 + p];
    float px = (float)i - sgn*v2;
    float py = (float)j - sgn*v1;
    float pz = (float)k - sgn*v0;
    px = fminf(fmaxf(px, 0.f), 63.f);
    py = fminf(fmaxf(py, 0.f), 63.f);
    pz = fminf(fmaxf(pz, 0.f), 63.f);
    int x0 = (int)px; float fx = px - x0; int x1 = min(x0+1, 63);
    int y0 = (int)py; float fy = py - y0; int y1 = min(y0+1, 63);
    int z0 = (int)pz; float fz = pz - z0; int z1 = min(z0+1, 63);

    float w000 = (1-fx)*(1-fy)*(1-fz), w001 = (1-fx)*(1-fy)*fz;
    float w010 = (1-fx)*fy*(1-fz),     w011 = (1-fx)*fy*fz;
    float w100 = fx*(1-fy)*(1-fz),     w101 = fx*(1-fy)*fz;
    float w110 = fx*fy*(1-fz),         w111 = fx*fy*fz;

    int b00 = (x0*64 + y0)*64, b01 = (x0*64 + y1)*64;
    int b10 = (x1*64 + y0)*64, b11 = (x1*64 + y1)*64;

    const float* src = (mode == 0) ? ext_src : ((mode == 1) ? g_phi1 : g_comb);
    float* dst = (mode == 0) ? g_phi1 : ((mode == 1) ? g_comb : g_pred);

#pragma unroll
    for (int c = 0; c < 8; c++) {
        const float* s = src + (n*8 + c)*D3;
        float v = w000*s[b00+z0] + w001*s[b00+z1] + w010*s[b01+z0] + w011*s[b01+z1]
                + w100*s[b10+z0] + w101*s[b10+z1] + w110*s[b11+z0] + w111*s[b11+z1];
        if (mode == 1) v = 1.5f * tex[(n*8 + c)*D3 + p] - 0.5f * v;
        dst[(n*8 + c)*D3 + p] = v;
    }
}

// ---------------- fused LN + FF (LN, @W1+b1, GELU, @W2+b2, residual -> d_out) ----------------
__global__ void ff_kernel(const float* __restrict__ lng, const float* __restrict__ lnb,
                          const float* __restrict__ w1, const float* __restrict__ b1,
                          const float* __restrict__ w2, const float* __restrict__ b2,
                          float* __restrict__ out) {
    __shared__ __align__(16) unsigned long long Wp1[2048];
    __shared__ __align__(16) unsigned long long Wp2[2048];
    __shared__ float Bv1[64], Bv2[64], G[64], Bt[64];
    float* fW1 = reinterpret_cast<float*>(Wp1);
    float* fW2 = reinterpret_cast<float*>(Wp2);
    for (int i = threadIdx.x; i < 4096; i += blockDim.x) {
        int ii = i >> 6, jj = i & 63;
        int d = (jj*32 + (ii >> 1))*2 + (ii & 1);
        fW1[d] = w1[i];
        fW2[d] = w2[i];
    }
    if (threadIdx.x < 64) {
        Bv1[threadIdx.x] = b1[threadIdx.x]; Bv2[threadIdx.x] = b2[threadIdx.x];
        G[threadIdx.x] = lng[threadIdx.x];  Bt[threadIdx.x] = lnb[threadIdx.x];
    }
    __syncthreads();

    int p = blockIdx.x * blockDim.x + threadIdx.x;
    if (p >= D3) return;

    float h[64]; float s = 0.f, s2 = 0.f;
#pragma unroll
    for (int c = 0; c < 64; c++) { float v = g_pred[c*D3 + p]; h[c] = v; s += v; s2 += v*v; }
    float mean = s * (1.f/64.f);
    float var  = s2 * (1.f/64.f) - mean*mean;
    float is = rsqrtf(var + 1e-5f);
    unsigned long long hp[32];
#pragma unroll
    for (int c = 0; c < 32; c++) {
        float e = (h[2*c]   - mean) * is * G[2*c]   + Bt[2*c];
        float o = (h[2*c+1] - mean) * is * G[2*c+1] + Bt[2*c+1];
        hp[c] = pk2(e, o);
    }

    unsigned long long gp[32];
    for (int jj = 0; jj < 64; jj += 2) {
        const ulonglong2* wrA = reinterpret_cast<const ulonglong2*>(Wp1 + jj*32);
        const ulonglong2* wrB = reinterpret_cast<const ulonglong2*>(Wp1 + (jj+1)*32);
        unsigned long long a0 = 0ULL, a1 = 0ULL, c0 = 0ULL, c1 = 0ULL;
#pragma unroll
        for (int q = 0; q < 16; q++) {
            ulonglong2 wa = wrA[q];
            ulonglong2 wb = wrB[q];
            fma2(a0, hp[2*q],   wa.x);
            fma2(a1, hp[2*q+1], wa.y);
            fma2(c0, hp[2*q],   wb.x);
            fma2(c1, hp[2*q+1], wb.y);
        }
        float l0, h0, l1, h1;
        upk2(a0, l0, h0); upk2(a1, l1, h1);
        float aA = Bv1[jj] + ((l0 + h0) + (l1 + h1));
        upk2(c0, l0, h0); upk2(c1, l1, h1);
        float aB = Bv1[jj+1] + ((l0 + h0) + (l1 + h1));
        float gA = 0.5f * aA * (1.f + erff(aA * 0.70710678118f));
        float gB = 0.5f * aB * (1.f + erff(aB * 0.70710678118f));
        gp[jj >> 1] = pk2(gA, gB);
    }

    for (int jj = 0; jj < 64; jj++) {
        const ulonglong2* wr = reinterpret_cast<const ulonglong2*>(Wp2 + jj*32);
        unsigned long long a0 = 0ULL, a1 = 0ULL;
#pragma unroll
        for (int q = 0; q < 16; q++) {
            ulonglong2 w2v = wr[q];
            fma2(a0, gp[2*q],   w2v.x);
            fma2(a1, gp[2*q+1], w2v.y);
        }
        float l0, h0, l1, h1;
        upk2(a0, l0, h0); upk2(a1, l1, h1);
        float a = Bv2[jj] + ((l0 + h0) + (l1 + h1));
        out[OFF_X + jj*D3 + p] = g_pred[jj*D3 + p] + a;
    }
}

// ---------------- host launch ----------------
extern "C" void kernel_launch(void* const* d_in, const int* in_sizes, int n_in,
                              void* d_out, int out_size) {
    const float* prev      = (const float*)d_in[0];
    const float* nxt       = (const float*)d_in[1];
    const float* texture   = (const float*)d_in[2];
    const float* mask      = (const float*)d_in[3];
    const float* boundary  = (const float*)d_in[4];
    const float* enc_w     = (const float*)d_in[5];
    const float* enc_b     = (const float*)d_in[6];
    const float* phi_c1_w  = (const float*)d_in[7];
    const float* phi_bn1_g = (const float*)d_in[8];
    const float* phi_bn1_b = (const float*)d_in[9];
    const float* phi_c2_w  = (const float*)d_in[10];
    const float* phi_bn2_g = (const float*)d_in[11];
    const float* phi_bn2_b = (const float*)d_in[12];
    const float* phi_out_w = (const float*)d_in[13];
    const float* phi_out_b = (const float*)d_in[14];
    const float* vort_c1_w = (const float*)d_in[15];
    const float* vort_bn1_g= (const float*)d_in[16];
    const float* vort_bn1_b= (const float*)d_in[17];
    const float* vort_c2_w = (const float*)d_in[18];
    const float* vort_bn2_g= (const float*)d_in[19];
    const float* vort_bn2_b= (const float*)d_in[20];
    const float* vort_out_w= (const float*)d_in[21];
    const float* vort_out_b= (const float*)d_in[22];
    const float* phi_weight= (const float*)d_in[23];
    const float* vort_weight=(const float*)d_in[24];
    const float* ln_g      = (const float*)d_in[25];
    const float* ln_b      = (const float*)d_in[26];
    const float* ff_w1     = (const float*)d_in[27];
    const float* ff_b1     = (const float*)d_in[28];
    const float* ff_w2     = (const float*)d_in[29];
    const float* ff_b2     = (const float*)d_in[30];
    float* out = (float*)d_out;

    pack_kernel<<<(3*WC1_PACK + 255)/256, 256>>>(phi_c1_w, vort_c1_w, phi_c2_w, vort_c2_w);

    int encBlocks = NB * ENC_BPN;
    enc_kernel<<<encBlocks, 256>>>(prev, mask,     enc_w, enc_b, 0);
    enc_kernel<<<encBlocks, 256>>>(prev, boundary, enc_w, enc_b, 1);
    enc_kernel<<<encBlocks, 256>>>(nxt,  mask,     enc_w, enc_b, 2);

    corr_kernel<<<(NB*H3 + 255)/256, 256>>>();

    cudaFuncSetAttribute(conv1_kernel, cudaFuncAttributeMaxDynamicSharedMemorySize, 3*WC1_PACK*4);
    conv1_kernel<<<NBLK1, 256, 3*WC1_PACK*4>>>();
    stats_reduce<<<16, 256>>>(0);

    int upN = NB*16*S3;
    upsample_kernel<<<(upN + 255)/256, 256>>>(phi_bn1_g, phi_bn1_b, vort_bn1_g, vort_bn1_b);

    conv2_kernel<<<NBLK2, 256>>>();
    stats_reduce<<<16, 256>>>(1);

    helm_kernel<<<(NB*S3 + 255)/256, 256>>>(phi_bn2_g, phi_bn2_b, vort_bn2_g, vort_bn2_b,
                                            phi_out_w, phi_out_b, vort_out_w, vort_out_b,
                                            phi_weight, vort_weight, out);

    vel_kernel<<<(NB*D3 + 255)/256, 256>>>(out);

    const float* vel = out + OFF_VEL;
    advect_kernel<<<(NB*D3 + 255)/256, 256>>>(texture, texture, vel,  1.f, 0);
    advect_kernel<<<(NB*D3 + 255)/256, 256>>>(texture, texture, vel, -1.f, 1);
    advect_kernel<<<(NB*D3 + 255)/256, 256>>>(texture, texture, vel,  1.f, 2);

    ff_kernel<<<(D3 + 127)/128, 128>>>(ln_g, ln_b, ff_w1, ff_b1, ff_w2, ff_b2, out);
}